// round 2
// baseline (speedup 1.0000x reference)
#include <cuda_runtime.h>

#define B_   2
#define H_   32
#define KVH_ 8
#define G_   4
#define S_   2048
#define D_   128
#define TT   128
#define NT   256

// Output layout: concat of flattened leaves (attn_output, attn_weights, key, value)
static const size_t OUT_P = (size_t)B_ * H_ * S_ * D_;            // 16777216
static const size_t OUT_K = OUT_P + (size_t)B_ * H_ * S_ * S_;    // 285212672
static const size_t OUT_V = OUT_K + (size_t)B_ * KVH_ * S_ * D_;  // 289406976

// softmax stats scratch
__device__ float g_m[B_ * H_ * S_];
__device__ float g_linv[B_ * H_ * S_];

// ---------------------------------------------------------------------------
// Kernel 1: raw scores S = Q K^T / scale  (lower triangle), online row stats,
//           zero-fill of upper triangle. Writes raw scores into the
//           attn_weights region of d_out (kernel 2 overwrites with softmax).
// ---------------------------------------------------------------------------
__global__ void __launch_bounds__(NT, 1)
qk_stats_kernel(const float* __restrict__ Q, const float* __restrict__ K,
                const float* __restrict__ scale_ptr, float* __restrict__ out)
{
    extern __shared__ float sm[];
    float* Qt = sm;           // [d][r] swizzled: addr = d*128 + (r ^ (((d>>2)&7)<<2))
    float* Kt = sm + TT * TT; // [d][c] swizzled

    const int qt = blockIdx.x, h = blockIdx.y, b = blockIdx.z;
    const int kvh = h >> 2;
    const int q0 = qt * TT;
    const float inv_scale = 1.0f / scale_ptr[0];

    const float* Qbase = Q + (((size_t)(b * H_ + h)) * S_ + q0) * D_;
    const float* Kbase = K + (((size_t)(b * KVH_ + kvh)) * S_) * D_;
    float* Pbase = out + OUT_P + (((size_t)(b * H_ + h)) * S_ + q0) * S_;

    const int tid = threadIdx.x;
    const int tx = tid & 15, ty = tid >> 4;
    const int ra = ty * 8, cb = tx * 8;

    // Load Q tile, transposed + swizzled (once per CTA)
#pragma unroll
    for (int it = 0; it < (TT * 32) / NT; it++) {
        int idx = it * NT + tid;
        int r = idx >> 5;
        int d4 = (idx & 31) << 2;
        float4 v = *(const float4*)(Qbase + r * D_ + d4);
        int vv = ((d4 >> 2) & 7) << 2;
        Qt[(d4 + 0) * TT + (r ^ vv)] = v.x;
        Qt[(d4 + 1) * TT + (r ^ vv)] = v.y;
        Qt[(d4 + 2) * TT + (r ^ vv)] = v.z;
        Qt[(d4 + 3) * TT + (r ^ vv)] = v.w;
    }

    float m_run[8], l_run[8];
#pragma unroll
    for (int i = 0; i < 8; i++) { m_run[i] = -3.0e38f; l_run[i] = 0.0f; }

    for (int kt = 0; kt <= qt; kt++) {
        const int k0 = kt * TT;
        __syncthreads();
#pragma unroll
        for (int it = 0; it < (TT * 32) / NT; it++) {
            int idx = it * NT + tid;
            int c = idx >> 5;
            int d4 = (idx & 31) << 2;
            float4 v = *(const float4*)(Kbase + (size_t)(k0 + c) * D_ + d4);
            int vv = ((d4 >> 2) & 7) << 2;
            Kt[(d4 + 0) * TT + (c ^ vv)] = v.x;
            Kt[(d4 + 1) * TT + (c ^ vv)] = v.y;
            Kt[(d4 + 2) * TT + (c ^ vv)] = v.z;
            Kt[(d4 + 3) * TT + (c ^ vv)] = v.w;
        }
        __syncthreads();

        float acc[8][8];
#pragma unroll
        for (int i = 0; i < 8; i++)
#pragma unroll
            for (int j = 0; j < 8; j++) acc[i][j] = 0.0f;

#pragma unroll 4
        for (int dd = 0; dd < D_; dd++) {
            const int vv = ((dd >> 2) & 7) << 2;
            float4 a0 = *(const float4*)&Qt[dd * TT + (ra ^ vv)];
            float4 a1 = *(const float4*)&Qt[dd * TT + ((ra + 4) ^ vv)];
            float4 b0 = *(const float4*)&Kt[dd * TT + (cb ^ vv)];
            float4 b1 = *(const float4*)&Kt[dd * TT + ((cb + 4) ^ vv)];
            float av[8] = {a0.x, a0.y, a0.z, a0.w, a1.x, a1.y, a1.z, a1.w};
            float bv[8] = {b0.x, b0.y, b0.z, b0.w, b1.x, b1.y, b1.z, b1.w};
#pragma unroll
            for (int i = 0; i < 8; i++)
#pragma unroll
                for (int j = 0; j < 8; j++)
                    acc[i][j] = fmaf(av[i], bv[j], acc[i][j]);
        }

        const bool diag = (kt == qt);
#pragma unroll
        for (int i = 0; i < 8; i++) {
            const int gq = q0 + ra + i;
            float s[8];
            float rmax = -3.0e38f;
#pragma unroll
            for (int j = 0; j < 8; j++) {
                float v = acc[i][j] * inv_scale;
                if (diag && (k0 + cb + j > gq)) v = -3.0e38f;
                s[j] = v;
                rmax = fmaxf(rmax, v);
            }
            float* prow = Pbase + (size_t)(ra + i) * S_ + k0 + cb;
            *(float4*)prow       = make_float4(s[0], s[1], s[2], s[3]);
            *(float4*)(prow + 4) = make_float4(s[4], s[5], s[6], s[7]);
#pragma unroll
            for (int off = 8; off >= 1; off >>= 1)
                rmax = fmaxf(rmax, __shfl_xor_sync(0xffffffffu, rmax, off));
            const float newm = fmaxf(m_run[i], rmax);
            const float corr = __expf(m_run[i] - newm);
            float se = 0.0f;
#pragma unroll
            for (int j = 0; j < 8; j++) se += __expf(s[j] - newm);
#pragma unroll
            for (int off = 8; off >= 1; off >>= 1)
                se += __shfl_xor_sync(0xffffffffu, se, off);
            l_run[i] = l_run[i] * corr + se;
            m_run[i] = newm;
        }
    }

    if (tx == 0) {
#pragma unroll
        for (int i = 0; i < 8; i++) {
            const int gidx = (b * H_ + h) * S_ + q0 + ra + i;
            g_m[gidx] = m_run[i];
            g_linv[gidx] = 1.0f / l_run[i];
        }
    }

    // Zero-fill upper triangle columns (final attn_weights values there are 0.0)
    const int zbase = (qt + 1) * TT;
    const int zc4 = (S_ - zbase) >> 2;
    if (zc4 > 0) {
        const float4 z4 = make_float4(0.f, 0.f, 0.f, 0.f);
        for (int r = 0; r < TT; r++) {
            float* prow = Pbase + (size_t)r * S_ + zbase;
            for (int c4 = tid; c4 < zc4; c4 += NT)
                *(float4*)(prow + (c4 << 2)) = z4;
        }
    }
}

// ---------------------------------------------------------------------------
// Kernel 2: P = softmax(S) (reads raw scores, writes final weights) and
//           O = P @ V, fused per q-tile.
// ---------------------------------------------------------------------------
__global__ void __launch_bounds__(NT, 1)
softmax_pv_kernel(const float* __restrict__ V, float* __restrict__ out)
{
    extern __shared__ float sm[];
    float* Pt  = sm;                 // [k][r] swizzled (64 KB)
    float* Vs  = sm + TT * TT;       // [k][132] natural, padded
    float* msm = Vs + TT * 132;      // [128]
    float* lsm = msm + TT;           // [128]

    const int qt = blockIdx.x, h = blockIdx.y, b = blockIdx.z;
    const int kvh = h >> 2;
    const int q0 = qt * TT;

    float* Pbase = out + OUT_P + (((size_t)(b * H_ + h)) * S_ + q0) * S_;
    float* Obase = out + (((size_t)(b * H_ + h)) * S_ + q0) * D_;
    const float* Vbase = V + (size_t)b * S_ * KVH_ * D_ + kvh * D_;

    const int tid = threadIdx.x;
    const int tx = tid & 15, ty = tid >> 4;
    const int ra = ty * 8, cb = tx * 8;

    if (tid < TT) {
        const int gidx = (b * H_ + h) * S_ + q0 + tid;
        msm[tid] = g_m[gidx];
        lsm[tid] = g_linv[gidx];
    }

    float acc[8][8];
#pragma unroll
    for (int i = 0; i < 8; i++)
#pragma unroll
        for (int j = 0; j < 8; j++) acc[i][j] = 0.0f;

    for (int kt = 0; kt <= qt; kt++) {
        const int k0 = kt * TT;
        __syncthreads();
        // Load raw scores, apply softmax, write final weights, stash into smem
#pragma unroll
        for (int it = 0; it < (TT * 32) / NT; it++) {
            int idx = it * NT + tid;
            int r = idx >> 5;
            int c4 = (idx & 31) << 2;
            float* pp = Pbase + (size_t)r * S_ + k0 + c4;
            float4 s4 = *(const float4*)pp;
            const float mm = msm[r], li = lsm[r];
            float4 p4;
            p4.x = __expf(s4.x - mm) * li;
            p4.y = __expf(s4.y - mm) * li;
            p4.z = __expf(s4.z - mm) * li;
            p4.w = __expf(s4.w - mm) * li;
            *(float4*)pp = p4;
            int vv = ((c4 >> 2) & 7) << 2;
            Pt[(c4 + 0) * TT + (r ^ vv)] = p4.x;
            Pt[(c4 + 1) * TT + (r ^ vv)] = p4.y;
            Pt[(c4 + 2) * TT + (r ^ vv)] = p4.z;
            Pt[(c4 + 3) * TT + (r ^ vv)] = p4.w;
        }
        // Load V tile
#pragma unroll
        for (int it = 0; it < (TT * 32) / NT; it++) {
            int idx = it * NT + tid;
            int k = idx >> 5;
            int d4 = (idx & 31) << 2;
            float4 v = *(const float4*)(Vbase + (size_t)(k0 + k) * (KVH_ * D_) + d4);
            *(float4*)&Vs[k * 132 + d4] = v;
        }
        __syncthreads();

#pragma unroll 4
        for (int kk = 0; kk < TT; kk++) {
            const int vv = ((kk >> 2) & 7) << 2;
            float4 a0 = *(const float4*)&Pt[kk * TT + (ra ^ vv)];
            float4 a1 = *(const float4*)&Pt[kk * TT + ((ra + 4) ^ vv)];
            float4 b0 = *(const float4*)&Vs[kk * 132 + cb];
            float4 b1 = *(const float4*)&Vs[kk * 132 + cb + 4];
            float av[8] = {a0.x, a0.y, a0.z, a0.w, a1.x, a1.y, a1.z, a1.w};
            float bv[8] = {b0.x, b0.y, b0.z, b0.w, b1.x, b1.y, b1.z, b1.w};
#pragma unroll
            for (int i = 0; i < 8; i++)
#pragma unroll
                for (int j = 0; j < 8; j++)
                    acc[i][j] = fmaf(av[i], bv[j], acc[i][j]);
        }
    }

#pragma unroll
    for (int i = 0; i < 8; i++) {
        float* orow = Obase + (size_t)(ra + i) * D_ + cb;
        *(float4*)orow       = make_float4(acc[i][0], acc[i][1], acc[i][2], acc[i][3]);
        *(float4*)(orow + 4) = make_float4(acc[i][4], acc[i][5], acc[i][6], acc[i][7]);
    }
}

// ---------------------------------------------------------------------------
// Kernel 3: present = (key copy, value permuted [B,S,KVH,D] -> [B,KVH,S,D])
// ---------------------------------------------------------------------------
__global__ void copy_kv_kernel(const float* __restrict__ K, const float* __restrict__ Vv,
                               float* __restrict__ out)
{
    const int i = blockIdx.x * NT + threadIdx.x;  // 0 .. 2097151 (float4 units)
    if (i < 1048576) {
        ((float4*)(out + OUT_K))[i] = ((const float4*)K)[i];
    } else {
        const int j = i - 1048576;
        const int row = j >> 5;          // packed (b, kvh, s), 32768 rows
        const int d4 = (j & 31) << 2;
        const int b = row >> 14;         // / (KVH_*S_)
        const int kvh = (row >> 11) & 7; // / S_ % KVH_
        const int s = row & 2047;
        const float4 v = *(const float4*)(Vv + ((((size_t)b * S_ + s) * KVH_ + kvh) << 7) + d4);
        *(float4*)(out + OUT_V + ((size_t)row << 7) + d4) = v;
    }
}

extern "C" void kernel_launch(void* const* d_in, const int* in_sizes, int n_in,
                              void* d_out, int out_size)
{
    (void)in_sizes; (void)n_in; (void)out_size;
    const float* Q     = (const float*)d_in[0];
    const float* K     = (const float*)d_in[1];
    const float* V     = (const float*)d_in[2];
    const float* scale = (const float*)d_in[4];
    float* out = (float*)d_out;

    cudaFuncSetAttribute(qk_stats_kernel, cudaFuncAttributeMaxDynamicSharedMemorySize, 131072);
    cudaFuncSetAttribute(softmax_pv_kernel, cudaFuncAttributeMaxDynamicSharedMemorySize, 134144);

    copy_kv_kernel<<<8192, NT>>>(K, V, out);

    dim3 grid(S_ / TT, H_, B_);
    qk_stats_kernel<<<grid, NT, 131072>>>(Q, K, scale, out);
    softmax_pv_kernel<<<grid, NT, 134144>>>(V, out);
}

// round 5
// speedup vs baseline: 1.9103x; 1.9103x over previous
#include <cuda_runtime.h>
#include <cuda_bf16.h>
#include <cstdint>

#define B_   2
#define H_   32
#define KVH_ 8
#define S_   2048
#define D_   128
#define TT   128

static const size_t OUT_P = (size_t)B_ * H_ * S_ * D_;            // attn_output end
static const size_t OUT_K = OUT_P + (size_t)B_ * H_ * S_ * S_;    // attn_weights end
static const size_t OUT_V = OUT_K + (size_t)B_ * KVH_ * S_ * D_;

// -------- scratch (__device__ BSS, no allocation) --------
__device__ __nv_bfloat16 gQhi[(size_t)B_ * H_ * S_ * D_];
__device__ __nv_bfloat16 gQlo[(size_t)B_ * H_ * S_ * D_];
__device__ __nv_bfloat16 gKhi[(size_t)B_ * KVH_ * S_ * D_];
__device__ __nv_bfloat16 gKlo[(size_t)B_ * KVH_ * S_ * D_];
__device__ __nv_bfloat16 gVthi[(size_t)B_ * KVH_ * D_ * S_];   // [b][kvh][d][s]
__device__ __nv_bfloat16 gVtlo[(size_t)B_ * KVH_ * D_ * S_];
__device__ float g_m[B_ * H_ * S_];
__device__ float g_linv[B_ * H_ * S_];

__device__ __forceinline__ uint32_t smem_to_u32(const void* p) {
    uint32_t a;
    asm("{ .reg .u64 t; cvta.to.shared.u64 t, %1; cvt.u32.u64 %0, t; }" : "=r"(a) : "l"(p));
    return a;
}
__device__ __forceinline__ uint32_t b2u(__nv_bfloat162 x) { return *reinterpret_cast<uint32_t*>(&x); }

// byte offset inside a [128 x 128 bf16] tile, 256B rows, 16B-granule XOR swizzle
__device__ __forceinline__ uint32_t toff(int r, int c) {
    return (uint32_t)(r * 256 + ((((c >> 3) ^ (r & 7)) & 15) << 4) + (c & 7) * 2);
}

#define LDSM_X4(d0, d1, d2, d3, a) \
    asm volatile("ldmatrix.sync.aligned.m8n8.x4.shared.b16 {%0,%1,%2,%3}, [%4];" \
                 : "=r"(d0), "=r"(d1), "=r"(d2), "=r"(d3) : "r"(a))

__device__ __forceinline__ void mma16816(float* c, const uint32_t* a, const uint32_t* b) {
    asm volatile(
        "mma.sync.aligned.m16n8k16.row.col.f32.bf16.bf16.f32 "
        "{%0,%1,%2,%3}, {%4,%5,%6,%7}, {%8,%9}, {%0,%1,%2,%3};"
        : "+f"(c[0]), "+f"(c[1]), "+f"(c[2]), "+f"(c[3])
        : "r"(a[0]), "r"(a[1]), "r"(a[2]), "r"(a[3]), "r"(b[0]), "r"(b[1]));
}

// smem tile byte offsets (dynamic smem)
#define T0_OFF 0
#define T1_OFF 32768
#define T2_OFF 65536
#define T3_OFF 98304
#define STAT_OFF 131072
#define SMEM1 (131072 + 2048)
#define SMEM2 (131072 + 1024)

// ---------------------------------------------------------------------------
// conversion kernels
// ---------------------------------------------------------------------------
__global__ void cvtQ_kernel(const float* __restrict__ Q) {
    size_t i = (size_t)blockIdx.x * 256 + threadIdx.x;  // float4 index
    float4 v = ((const float4*)Q)[i];
    __nv_bfloat162 h01 = __floats2bfloat162_rn(v.x, v.y);
    __nv_bfloat162 h23 = __floats2bfloat162_rn(v.z, v.w);
    __nv_bfloat162 l01 = __floats2bfloat162_rn(v.x - __bfloat162float(h01.x),
                                               v.y - __bfloat162float(h01.y));
    __nv_bfloat162 l23 = __floats2bfloat162_rn(v.z - __bfloat162float(h23.x),
                                               v.w - __bfloat162float(h23.y));
    ((uint2*)gQhi)[i] = make_uint2(b2u(h01), b2u(h23));
    ((uint2*)gQlo)[i] = make_uint2(b2u(l01), b2u(l23));
}
__global__ void cvtK_kernel(const float* __restrict__ K) {
    size_t i = (size_t)blockIdx.x * 256 + threadIdx.x;
    float4 v = ((const float4*)K)[i];
    __nv_bfloat162 h01 = __floats2bfloat162_rn(v.x, v.y);
    __nv_bfloat162 h23 = __floats2bfloat162_rn(v.z, v.w);
    __nv_bfloat162 l01 = __floats2bfloat162_rn(v.x - __bfloat162float(h01.x),
                                               v.y - __bfloat162float(h01.y));
    __nv_bfloat162 l23 = __floats2bfloat162_rn(v.z - __bfloat162float(h23.x),
                                               v.w - __bfloat162float(h23.y));
    ((uint2*)gKhi)[i] = make_uint2(b2u(h01), b2u(h23));
    ((uint2*)gKlo)[i] = make_uint2(b2u(l01), b2u(l23));
}
// V [b,s,kvh,d] fp32 -> Vt [b,kvh,d,s] bf16 hi/lo (smem tile transpose)
__global__ void cvtV_kernel(const float* __restrict__ V) {
    __shared__ float sm[32][129];
    const int bk = blockIdx.z, b = bk >> 3, kvh = bk & 7;
    const int s0 = blockIdx.x * 128, d0 = blockIdx.y * 32;
    const int tid = threadIdx.x;
#pragma unroll
    for (int it = 0; it < 4; it++) {
        int idx = it * 256 + tid;
        int s = idx >> 3, d4 = (idx & 7) * 4;
        float4 v = *(const float4*)(V + ((((size_t)b * S_ + s0 + s) * KVH_ + kvh) * D_) + d0 + d4);
        sm[d4 + 0][s] = v.x; sm[d4 + 1][s] = v.y; sm[d4 + 2][s] = v.z; sm[d4 + 3][s] = v.w;
    }
    __syncthreads();
    const size_t obase = ((size_t)(b * KVH_ + kvh) * D_ + d0) * S_ + s0;
#pragma unroll
    for (int it = 0; it < 8; it++) {
        int idx = it * 256 + tid;
        int d = idx >> 6, j = idx & 63, s = 2 * j;
        float a = sm[d][s], c = sm[d][s + 1];
        __nv_bfloat162 h = __floats2bfloat162_rn(a, c);
        __nv_bfloat162 l = __floats2bfloat162_rn(a - __bfloat162float(h.x), c - __bfloat162float(h.y));
        *(uint32_t*)(&gVthi[obase + (size_t)d * S_ + s]) = b2u(h);
        *(uint32_t*)(&gVtlo[obase + (size_t)d * S_ + s]) = b2u(l);
    }
}

// ---------------------------------------------------------------------------
// kernel 1: raw scores via HMMA (hi/lo split), per-warp-half online stats,
//           cross-warp merge, zero-fill
// ---------------------------------------------------------------------------
__global__ void __launch_bounds__(256, 1)
qk_kernel(const float* __restrict__ scale_ptr, float* __restrict__ out)
{
    extern __shared__ char smc[];
    const uint32_t sb = smem_to_u32(smc);
    float* pm = (float*)(smc + STAT_OFF);   // [2][128] partial max per column-half
    float* pl = pm + 256;                   // [2][128] partial sum per column-half

    const int tid = threadIdx.x, lane = tid & 31, wid = tid >> 5;
    const int warp_m = wid & 3, warp_n = wid >> 2;   // 4 x 2 warp grid
    const int qt = blockIdx.x, h = blockIdx.y, b = blockIdx.z;
    const int kvh = h >> 2, q0 = qt * TT;
    const float inv_scale = 1.0f / scale_ptr[0];

    const size_t qbase = (((size_t)(b * H_ + h)) * S_ + q0) * D_;
    const size_t kbase = ((size_t)(b * KVH_ + kvh)) * S_ * D_;
    float* Pbase = out + OUT_P + (((size_t)(b * H_ + h)) * S_ + q0) * S_;

    // stage Q hi/lo tiles (once)
#pragma unroll
    for (int it = 0; it < 16; it++) {
        int idx = it * 256 + tid;
        int arr = idx >> 11, rem = idx & 2047;
        int r = rem >> 4, c = (rem & 15) * 8;
        const __nv_bfloat16* src = (arr ? gQlo : gQhi) + qbase + (size_t)r * D_ + c;
        *(uint4*)(smc + (arr ? T1_OFF : T0_OFF) + toff(r, c)) = *(const uint4*)src;
    }

    // per-warp running stats over this warp's 64-column half
    float m_run[4], l_run[4];
#pragma unroll
    for (int i = 0; i < 4; i++) { m_run[i] = -3.0e38f; l_run[i] = 0.0f; }

    for (int kt = 0; kt <= qt; kt++) {
        const int k0 = kt * TT;
        __syncthreads();
#pragma unroll
        for (int it = 0; it < 16; it++) {
            int idx = it * 256 + tid;
            int arr = idx >> 11, rem = idx & 2047;
            int r = rem >> 4, c = (rem & 15) * 8;
            const __nv_bfloat16* src = (arr ? gKlo : gKhi) + kbase + (size_t)(k0 + r) * D_ + c;
            *(uint4*)(smc + (arr ? T3_OFF : T2_OFF) + toff(r, c)) = *(const uint4*)src;
        }
        __syncthreads();

        float acc[2][8][4];
#pragma unroll
        for (int mt = 0; mt < 2; mt++)
#pragma unroll
            for (int nt = 0; nt < 8; nt++)
#pragma unroll
                for (int k = 0; k < 4; k++) acc[mt][nt][k] = 0.0f;

#pragma unroll
        for (int ks = 0; ks < 8; ks++) {
            uint32_t ah[2][4], al[2][4], bh[8][2], bl[8][2];
#pragma unroll
            for (int mt = 0; mt < 2; mt++) {
                int r = warp_m * 32 + mt * 16 + (lane & 15);
                int cc = ks * 16 + (lane >> 4) * 8;
                uint32_t o = toff(r, cc);
                LDSM_X4(ah[mt][0], ah[mt][1], ah[mt][2], ah[mt][3], sb + T0_OFF + o);
                LDSM_X4(al[mt][0], al[mt][1], al[mt][2], al[mt][3], sb + T1_OFF + o);
            }
#pragma unroll
            for (int np = 0; np < 4; np++) {
                int r = warp_n * 64 + np * 16 + ((lane >> 4) << 3) + (lane & 7);
                int cc = ks * 16 + ((lane >> 3) & 1) * 8;
                uint32_t o = toff(r, cc);
                LDSM_X4(bh[2 * np][0], bh[2 * np][1], bh[2 * np + 1][0], bh[2 * np + 1][1],
                        sb + T2_OFF + o);
                LDSM_X4(bl[2 * np][0], bl[2 * np][1], bl[2 * np + 1][0], bl[2 * np + 1][1],
                        sb + T3_OFF + o);
            }
#pragma unroll
            for (int mt = 0; mt < 2; mt++)
#pragma unroll
                for (int nt = 0; nt < 8; nt++) {
                    mma16816(acc[mt][nt], ah[mt], bh[nt]);
                    mma16816(acc[mt][nt], al[mt], bh[nt]);
                    mma16816(acc[mt][nt], ah[mt], bl[nt]);
                }
        }

        // fragment epilogue (stats cover only this warp's 64 columns)
        const bool diag = (kt == qt);
#pragma unroll
        for (int mt = 0; mt < 2; mt++) {
#pragma unroll
            for (int hh = 0; hh < 2; hh++) {
                const int row_l = warp_m * 32 + mt * 16 + (lane >> 2) + hh * 8;
                float vv[8][2];
                float rmax = -3.0e38f;
#pragma unroll
                for (int nt = 0; nt < 8; nt++) {
                    float v0 = acc[mt][nt][hh * 2]     * inv_scale;
                    float v1 = acc[mt][nt][hh * 2 + 1] * inv_scale;
                    if (diag) {
                        int colb = warp_n * 64 + nt * 8 + (lane & 3) * 2;
                        if (colb > row_l)     v0 = -3.0e38f;
                        if (colb + 1 > row_l) v1 = -3.0e38f;
                    }
                    vv[nt][0] = v0; vv[nt][1] = v1;
                    rmax = fmaxf(rmax, fmaxf(v0, v1));
                }
                rmax = fmaxf(rmax, __shfl_xor_sync(0xffffffffu, rmax, 1));
                rmax = fmaxf(rmax, __shfl_xor_sync(0xffffffffu, rmax, 2));
                const int si = mt * 2 + hh;
                const float newm = fmaxf(m_run[si], rmax);
                const float corr = __expf(m_run[si] - newm);
                float se = 0.0f;
#pragma unroll
                for (int nt = 0; nt < 8; nt++)
                    se += __expf(vv[nt][0] - newm) + __expf(vv[nt][1] - newm);
                se += __shfl_xor_sync(0xffffffffu, se, 1);
                se += __shfl_xor_sync(0xffffffffu, se, 2);
                l_run[si] = l_run[si] * corr + se;
                m_run[si] = newm;

                float* prow = Pbase + (size_t)row_l * S_ + k0 + warp_n * 64 + (lane & 3) * 2;
#pragma unroll
                for (int nt = 0; nt < 8; nt++)
                    *(float2*)(prow + nt * 8) = make_float2(vv[nt][0], vv[nt][1]);
            }
        }
    }

    // cross-warp merge of the two column-half stats
    if ((lane & 3) == 0) {
#pragma unroll
        for (int mt = 0; mt < 2; mt++)
#pragma unroll
            for (int hh = 0; hh < 2; hh++) {
                const int row_l = warp_m * 32 + mt * 16 + (lane >> 2) + hh * 8;
                pm[warp_n * 128 + row_l] = m_run[mt * 2 + hh];
                pl[warp_n * 128 + row_l] = l_run[mt * 2 + hh];
            }
    }
    __syncthreads();
    if (tid < 128) {
        const float m0 = pm[tid], m1 = pm[128 + tid];
        const float l0 = pl[tid], l1 = pl[128 + tid];
        const float m = fmaxf(m0, m1);
        const float l = l0 * __expf(m0 - m) + l1 * __expf(m1 - m);
        const int gidx = (b * H_ + h) * S_ + q0 + tid;
        g_m[gidx] = m;
        g_linv[gidx] = 1.0f / l;
    }

    // zero-fill causal upper triangle
    const int zbase = (qt + 1) * TT;
    const int zc4 = (S_ - zbase) >> 2;
    if (zc4 > 0) {
        const float4 z4 = make_float4(0.f, 0.f, 0.f, 0.f);
        for (int r = 0; r < TT; r++) {
            float* prow = Pbase + (size_t)r * S_ + zbase;
            for (int c4 = tid; c4 < zc4; c4 += 256)
                *(float4*)(prow + (c4 << 2)) = z4;
        }
    }
}

// ---------------------------------------------------------------------------
// kernel 2: softmax finalize + O = P V via HMMA (hi/lo split)
// ---------------------------------------------------------------------------
__global__ void __launch_bounds__(256, 1)
pv_kernel(float* __restrict__ out)
{
    extern __shared__ char smc[];
    const uint32_t sb = smem_to_u32(smc);
    float* msm = (float*)(smc + STAT_OFF);
    float* lsm = msm + 128;

    const int tid = threadIdx.x, lane = tid & 31, wid = tid >> 5;
    const int warp_m = wid & 3, warp_n = wid >> 2;
    const int qt = blockIdx.x, h = blockIdx.y, b = blockIdx.z;
    const int kvh = h >> 2, q0 = qt * TT;

    float* Pbase = out + OUT_P + (((size_t)(b * H_ + h)) * S_ + q0) * S_;
    float* Obase = out + (((size_t)(b * H_ + h)) * S_ + q0) * D_;
    const size_t vbase = ((size_t)(b * KVH_ + kvh)) * D_ * S_;

    if (tid < 128) {
        const int gidx = (b * H_ + h) * S_ + q0 + tid;
        msm[tid] = g_m[gidx];
        lsm[tid] = g_linv[gidx];
    }

    float acc[2][8][4];
#pragma unroll
    for (int mt = 0; mt < 2; mt++)
#pragma unroll
        for (int nt = 0; nt < 8; nt++)
#pragma unroll
            for (int k = 0; k < 4; k++) acc[mt][nt][k] = 0.0f;

    for (int kt = 0; kt <= qt; kt++) {
        const int k0 = kt * TT;
        __syncthreads();
        // P: read raw scores, finalize softmax, write weights, stage hi/lo bf16
#pragma unroll 4
        for (int it = 0; it < 16; it++) {
            int idx = it * 256 + tid;
            int r = idx >> 5, c4 = (idx & 31) << 2;
            float* pp = Pbase + (size_t)r * S_ + k0 + c4;
            float4 s4 = *(const float4*)pp;
            const float mm = msm[r], li = lsm[r];
            float4 p4;
            p4.x = __expf(s4.x - mm) * li;
            p4.y = __expf(s4.y - mm) * li;
            p4.z = __expf(s4.z - mm) * li;
            p4.w = __expf(s4.w - mm) * li;
            *(float4*)pp = p4;
            __nv_bfloat162 h01 = __floats2bfloat162_rn(p4.x, p4.y);
            __nv_bfloat162 h23 = __floats2bfloat162_rn(p4.z, p4.w);
            __nv_bfloat162 l01 = __floats2bfloat162_rn(p4.x - __bfloat162float(h01.x),
                                                       p4.y - __bfloat162float(h01.y));
            __nv_bfloat162 l23 = __floats2bfloat162_rn(p4.z - __bfloat162float(h23.x),
                                                       p4.w - __bfloat162float(h23.y));
            uint32_t o = toff(r, c4);
            *(uint2*)(smc + T0_OFF + o) = make_uint2(b2u(h01), b2u(h23));
            *(uint2*)(smc + T1_OFF + o) = make_uint2(b2u(l01), b2u(l23));
        }
        // V^T tiles hi/lo (rows = d, cols = kseq)
#pragma unroll
        for (int it = 0; it < 16; it++) {
            int idx = it * 256 + tid;
            int arr = idx >> 11, rem = idx & 2047;
            int r = rem >> 4, c = (rem & 15) * 8;
            const __nv_bfloat16* src = (arr ? gVtlo : gVthi) + vbase + (size_t)r * S_ + k0 + c;
            *(uint4*)(smc + (arr ? T3_OFF : T2_OFF) + toff(r, c)) = *(const uint4*)src;
        }
        __syncthreads();

#pragma unroll
        for (int ks = 0; ks < 8; ks++) {
            uint32_t ah[2][4], al[2][4], bh[8][2], bl[8][2];
#pragma unroll
            for (int mt = 0; mt < 2; mt++) {
                int r = warp_m * 32 + mt * 16 + (lane & 15);
                int cc = ks * 16 + (lane >> 4) * 8;
                uint32_t o = toff(r, cc);
                LDSM_X4(ah[mt][0], ah[mt][1], ah[mt][2], ah[mt][3], sb + T0_OFF + o);
                LDSM_X4(al[mt][0], al[mt][1], al[mt][2], al[mt][3], sb + T1_OFF + o);
            }
#pragma unroll
            for (int np = 0; np < 4; np++) {
                int r = warp_n * 64 + np * 16 + ((lane >> 4) << 3) + (lane & 7);
                int cc = ks * 16 + ((lane >> 3) & 1) * 8;
                uint32_t o = toff(r, cc);
                LDSM_X4(bh[2 * np][0], bh[2 * np][1], bh[2 * np + 1][0], bh[2 * np + 1][1],
                        sb + T2_OFF + o);
                LDSM_X4(bl[2 * np][0], bl[2 * np][1], bl[2 * np + 1][0], bl[2 * np + 1][1],
                        sb + T3_OFF + o);
            }
#pragma unroll
            for (int mt = 0; mt < 2; mt++)
#pragma unroll
                for (int nt = 0; nt < 8; nt++) {
                    mma16816(acc[mt][nt], ah[mt], bh[nt]);
                    mma16816(acc[mt][nt], al[mt], bh[nt]);
                    mma16816(acc[mt][nt], ah[mt], bl[nt]);
                }
        }
    }

    // O epilogue
#pragma unroll
    for (int mt = 0; mt < 2; mt++)
#pragma unroll
        for (int hh = 0; hh < 2; hh++) {
            const int row_l = warp_m * 32 + mt * 16 + (lane >> 2) + hh * 8;
            float* orow = Obase + (size_t)row_l * D_ + warp_n * 64 + (lane & 3) * 2;
#pragma unroll
            for (int nt = 0; nt < 8; nt++)
                *(float2*)(orow + nt * 8) =
                    make_float2(acc[mt][nt][hh * 2], acc[mt][nt][hh * 2 + 1]);
        }
}

// ---------------------------------------------------------------------------
// kernel 3: present = (key copy, value permute)
// ---------------------------------------------------------------------------
__global__ void copy_kv_kernel(const float* __restrict__ K, const float* __restrict__ Vv,
                               float* __restrict__ out)
{
    const int i = blockIdx.x * 256 + threadIdx.x;
    if (i < 1048576) {
        ((float4*)(out + OUT_K))[i] = ((const float4*)K)[i];
    } else {
        const int j = i - 1048576;
        const int row = j >> 5;
        const int d4 = (j & 31) << 2;
        const int b = row >> 14;
        const int kvh = (row >> 11) & 7;
        const int s = row & 2047;
        const float4 v = *(const float4*)(Vv + ((((size_t)b * S_ + s) * KVH_ + kvh) << 7) + d4);
        *(float4*)(out + OUT_V + ((size_t)row << 7) + d4) = v;
    }
}

extern "C" void kernel_launch(void* const* d_in, const int* in_sizes, int n_in,
                              void* d_out, int out_size)
{
    (void)in_sizes; (void)n_in; (void)out_size;
    const float* Q     = (const float*)d_in[0];
    const float* K     = (const float*)d_in[1];
    const float* V     = (const float*)d_in[2];
    const float* scale = (const float*)d_in[4];
    float* out = (float*)d_out;

    cudaFuncSetAttribute(qk_kernel, cudaFuncAttributeMaxDynamicSharedMemorySize, SMEM1);
    cudaFuncSetAttribute(pv_kernel, cudaFuncAttributeMaxDynamicSharedMemorySize, SMEM2);

    cvtQ_kernel<<<16384, 256>>>(Q);
    cvtK_kernel<<<4096, 256>>>(K);
    cvtV_kernel<<<dim3(16, 4, 16), 256>>>(V);
    copy_kv_kernel<<<8192, 256>>>(K, V, out);

    dim3 grid(S_ / TT, H_, B_);
    qk_kernel<<<grid, 256, SMEM1>>>(scale, out);
    pv_kernel<<<grid, 256, SMEM2>>>(out);
}

// round 6
// speedup vs baseline: 2.0058x; 1.0500x over previous
#include <cuda_runtime.h>
#include <cuda_bf16.h>
#include <cstdint>

#define B_   2
#define H_   32
#define KVH_ 8
#define S_   2048
#define D_   128
#define TT   128

static const size_t OUT_P = (size_t)B_ * H_ * S_ * D_;            // attn_output end
static const size_t OUT_K = OUT_P + (size_t)B_ * H_ * S_ * S_;    // attn_weights end
static const size_t OUT_V = OUT_K + (size_t)B_ * KVH_ * S_ * D_;

// -------- scratch (__device__ BSS, no allocation) --------
__device__ __nv_bfloat16 gQhi[(size_t)B_ * H_ * S_ * D_];
__device__ __nv_bfloat16 gQlo[(size_t)B_ * H_ * S_ * D_];
__device__ __nv_bfloat16 gKhi[(size_t)B_ * KVH_ * S_ * D_];
__device__ __nv_bfloat16 gKlo[(size_t)B_ * KVH_ * S_ * D_];
__device__ __nv_bfloat16 gVthi[(size_t)B_ * KVH_ * D_ * S_];   // [b][kvh][d][s]
__device__ __nv_bfloat16 gVtlo[(size_t)B_ * KVH_ * D_ * S_];
__device__ float g_m[B_ * H_ * S_];
__device__ float g_linv[B_ * H_ * S_];
// running max after tile kt, per (bh, qt, kt, half, row)
__device__ float g_mkt[(size_t)B_ * H_ * 16 * 16 * 256];

__device__ __forceinline__ uint32_t smem_to_u32(const void* p) {
    uint32_t a;
    asm("{ .reg .u64 t; cvta.to.shared.u64 t, %1; cvt.u32.u64 %0, t; }" : "=r"(a) : "l"(p));
    return a;
}
__device__ __forceinline__ uint32_t b2u(__nv_bfloat162 x) { return *reinterpret_cast<uint32_t*>(&x); }

// byte offset inside a [128 x 128 bf16] tile, 256B rows, 16B-granule XOR swizzle
__device__ __forceinline__ uint32_t toff(int r, int c) {
    return (uint32_t)(r * 256 + ((((c >> 3) ^ (r & 7)) & 15) << 4) + (c & 7) * 2);
}

#define LDSM_X4(d0, d1, d2, d3, a) \
    asm volatile("ldmatrix.sync.aligned.m8n8.x4.shared.b16 {%0,%1,%2,%3}, [%4];" \
                 : "=r"(d0), "=r"(d1), "=r"(d2), "=r"(d3) : "r"(a))

__device__ __forceinline__ void mma16816(float* c, const uint32_t* a, const uint32_t* b) {
    asm volatile(
        "mma.sync.aligned.m16n8k16.row.col.f32.bf16.bf16.f32 "
        "{%0,%1,%2,%3}, {%4,%5,%6,%7}, {%8,%9}, {%0,%1,%2,%3};"
        : "+f"(c[0]), "+f"(c[1]), "+f"(c[2]), "+f"(c[3])
        : "r"(a[0]), "r"(a[1]), "r"(a[2]), "r"(a[3]), "r"(b[0]), "r"(b[1]));
}

#define CP_ASYNC16(dst, src) \
    asm volatile("cp.async.cg.shared.global [%0], [%1], 16;" :: "r"(dst), "l"(src))
#define CP_COMMIT() asm volatile("cp.async.commit_group;")
#define CP_WAIT0()  asm volatile("cp.async.wait_group 0;")

// smem layout (byte offsets): A tiles fixed, B tiles double-buffered
#define A_HI   0
#define A_LO   32768
#define BUF0   65536
#define BUF1   131072
#define STAT_OFF 196608
#define SMEM_SZ (196608 + 2048)

// ---------------------------------------------------------------------------
// conversion kernels
// ---------------------------------------------------------------------------
__global__ void cvtQ_kernel(const float* __restrict__ Q) {
    size_t i = (size_t)blockIdx.x * 256 + threadIdx.x;  // float4 index
    float4 v = ((const float4*)Q)[i];
    __nv_bfloat162 h01 = __floats2bfloat162_rn(v.x, v.y);
    __nv_bfloat162 h23 = __floats2bfloat162_rn(v.z, v.w);
    __nv_bfloat162 l01 = __floats2bfloat162_rn(v.x - __bfloat162float(h01.x),
                                               v.y - __bfloat162float(h01.y));
    __nv_bfloat162 l23 = __floats2bfloat162_rn(v.z - __bfloat162float(h23.x),
                                               v.w - __bfloat162float(h23.y));
    ((uint2*)gQhi)[i] = make_uint2(b2u(h01), b2u(h23));
    ((uint2*)gQlo)[i] = make_uint2(b2u(l01), b2u(l23));
}
__global__ void cvtK_kernel(const float* __restrict__ K) {
    size_t i = (size_t)blockIdx.x * 256 + threadIdx.x;
    float4 v = ((const float4*)K)[i];
    __nv_bfloat162 h01 = __floats2bfloat162_rn(v.x, v.y);
    __nv_bfloat162 h23 = __floats2bfloat162_rn(v.z, v.w);
    __nv_bfloat162 l01 = __floats2bfloat162_rn(v.x - __bfloat162float(h01.x),
                                               v.y - __bfloat162float(h01.y));
    __nv_bfloat162 l23 = __floats2bfloat162_rn(v.z - __bfloat162float(h23.x),
                                               v.w - __bfloat162float(h23.y));
    ((uint2*)gKhi)[i] = make_uint2(b2u(h01), b2u(h23));
    ((uint2*)gKlo)[i] = make_uint2(b2u(l01), b2u(l23));
}
// V [b,s,kvh,d] fp32 -> Vt [b,kvh,d,s] bf16 hi/lo (smem tile transpose)
__global__ void cvtV_kernel(const float* __restrict__ V) {
    __shared__ float sm[32][129];
    const int bk = blockIdx.z, b = bk >> 3, kvh = bk & 7;
    const int s0 = blockIdx.x * 128, d0 = blockIdx.y * 32;
    const int tid = threadIdx.x;
#pragma unroll
    for (int it = 0; it < 4; it++) {
        int idx = it * 256 + tid;
        int s = idx >> 3, d4 = (idx & 7) * 4;
        float4 v = *(const float4*)(V + ((((size_t)b * S_ + s0 + s) * KVH_ + kvh) * D_) + d0 + d4);
        sm[d4 + 0][s] = v.x; sm[d4 + 1][s] = v.y; sm[d4 + 2][s] = v.z; sm[d4 + 3][s] = v.w;
    }
    __syncthreads();
    const size_t obase = ((size_t)(b * KVH_ + kvh) * D_ + d0) * S_ + s0;
#pragma unroll
    for (int it = 0; it < 8; it++) {
        int idx = it * 256 + tid;
        int d = idx >> 6, j = idx & 63, s = 2 * j;
        float a = sm[d][s], c = sm[d][s + 1];
        __nv_bfloat162 h = __floats2bfloat162_rn(a, c);
        __nv_bfloat162 l = __floats2bfloat162_rn(a - __bfloat162float(h.x), c - __bfloat162float(h.y));
        *(uint32_t*)(&gVthi[obase + (size_t)d * S_ + s]) = b2u(h);
        *(uint32_t*)(&gVtlo[obase + (size_t)d * S_ + s]) = b2u(l);
    }
}

// ---------------------------------------------------------------------------
// kernel 1: p~ = exp(s - m_kt) via HMMA hi/lo split, double-buffered cp.async
//           K staging, per-half online stats + cross-warp merge, zero-fill
// ---------------------------------------------------------------------------
__global__ void __launch_bounds__(256, 1)
qk_kernel(const float* __restrict__ scale_ptr, float* __restrict__ out)
{
    extern __shared__ char smc[];
    const uint32_t sb = smem_to_u32(smc);
    float* pm = (float*)(smc + STAT_OFF);   // [2][128] partial max per column-half
    float* pl = pm + 256;                   // [2][128] partial sum per column-half

    const int tid = threadIdx.x, lane = tid & 31, wid = tid >> 5;
    const int warp_m = wid & 3, warp_n = wid >> 2;   // 4 x 2 warp grid
    const int qt = blockIdx.x, h = blockIdx.y, b = blockIdx.z;
    const int kvh = h >> 2, q0 = qt * TT;
    const int bh = b * H_ + h;
    const float inv_scale = 1.0f / scale_ptr[0];

    const size_t qbase = ((size_t)bh * S_ + q0) * D_;
    const size_t kbase = ((size_t)(b * KVH_ + kvh)) * S_ * D_;
    float* Pbase = out + OUT_P + ((size_t)bh * S_ + q0) * S_;
    const size_t mktbase = ((size_t)bh * 16 + qt) * 16 * 256;

    // stage Q hi/lo tiles (once, direct)
#pragma unroll
    for (int it = 0; it < 16; it++) {
        int idx = it * 256 + tid;
        int arr = idx >> 11, rem = idx & 2047;
        int r = rem >> 4, c = (rem & 15) * 8;
        const __nv_bfloat16* src = (arr ? gQlo : gQhi) + qbase + (size_t)r * D_ + c;
        *(uint4*)(smc + (arr ? A_LO : A_HI) + toff(r, c)) = *(const uint4*)src;
    }

    // prefetch K tile 0 into BUF0
    {
#pragma unroll
        for (int it = 0; it < 16; it++) {
            int idx = it * 256 + tid;
            int arr = idx >> 11, rem = idx & 2047;
            int r = rem >> 4, c = (rem & 15) * 8;
            const __nv_bfloat16* src = (arr ? gKlo : gKhi) + kbase + (size_t)r * D_ + c;
            CP_ASYNC16(sb + BUF0 + (arr ? 32768 : 0) + toff(r, c), src);
        }
        CP_COMMIT();
    }

    float m_run[4], l_run[4];
#pragma unroll
    for (int i = 0; i < 4; i++) { m_run[i] = -3.0e38f; l_run[i] = 0.0f; }

    for (int kt = 0; kt <= qt; kt++) {
        const int k0 = kt * TT;
        CP_WAIT0();
        __syncthreads();
        if (kt < qt) {   // prefetch next K tile into the other buffer
            const uint32_t nb = ((kt + 1) & 1) ? BUF1 : BUF0;
#pragma unroll
            for (int it = 0; it < 16; it++) {
                int idx = it * 256 + tid;
                int arr = idx >> 11, rem = idx & 2047;
                int r = rem >> 4, c = (rem & 15) * 8;
                const __nv_bfloat16* src =
                    (arr ? gKlo : gKhi) + kbase + (size_t)(k0 + TT + r) * D_ + c;
                CP_ASYNC16(sb + nb + (arr ? 32768 : 0) + toff(r, c), src);
            }
            CP_COMMIT();
        }
        const uint32_t Tb = (kt & 1) ? BUF1 : BUF0;

        float acc[2][8][4];
#pragma unroll
        for (int mt = 0; mt < 2; mt++)
#pragma unroll
            for (int nt = 0; nt < 8; nt++)
#pragma unroll
                for (int k = 0; k < 4; k++) acc[mt][nt][k] = 0.0f;

#pragma unroll
        for (int ks = 0; ks < 8; ks++) {
            uint32_t ah[2][4], al[2][4], bh2[8][2], bl[8][2];
#pragma unroll
            for (int mt = 0; mt < 2; mt++) {
                int r = warp_m * 32 + mt * 16 + (lane & 15);
                int cc = ks * 16 + (lane >> 4) * 8;
                uint32_t o = toff(r, cc);
                LDSM_X4(ah[mt][0], ah[mt][1], ah[mt][2], ah[mt][3], sb + A_HI + o);
                LDSM_X4(al[mt][0], al[mt][1], al[mt][2], al[mt][3], sb + A_LO + o);
            }
#pragma unroll
            for (int np = 0; np < 4; np++) {
                int r = warp_n * 64 + np * 16 + ((lane >> 4) << 3) + (lane & 7);
                int cc = ks * 16 + ((lane >> 3) & 1) * 8;
                uint32_t o = toff(r, cc);
                LDSM_X4(bh2[2 * np][0], bh2[2 * np][1], bh2[2 * np + 1][0], bh2[2 * np + 1][1],
                        sb + Tb + o);
                LDSM_X4(bl[2 * np][0], bl[2 * np][1], bl[2 * np + 1][0], bl[2 * np + 1][1],
                        sb + Tb + 32768 + o);
            }
#pragma unroll
            for (int mt = 0; mt < 2; mt++)
#pragma unroll
                for (int nt = 0; nt < 8; nt++) {
                    mma16816(acc[mt][nt], ah[mt], bh2[nt]);
                    mma16816(acc[mt][nt], al[mt], bh2[nt]);
                    mma16816(acc[mt][nt], ah[mt], bl[nt]);
                }
        }

        // fragment epilogue: stats over this warp's 64-col half; store p~ = exp(s - newm)
        const bool diag = (kt == qt);
#pragma unroll
        for (int mt = 0; mt < 2; mt++) {
#pragma unroll
            for (int hh = 0; hh < 2; hh++) {
                const int row_l = warp_m * 32 + mt * 16 + (lane >> 2) + hh * 8;
                float vv[8][2];
                float rmax = -3.0e38f;
#pragma unroll
                for (int nt = 0; nt < 8; nt++) {
                    float v0 = acc[mt][nt][hh * 2]     * inv_scale;
                    float v1 = acc[mt][nt][hh * 2 + 1] * inv_scale;
                    if (diag) {
                        int colb = warp_n * 64 + nt * 8 + (lane & 3) * 2;
                        if (colb > row_l)     v0 = -3.0e38f;
                        if (colb + 1 > row_l) v1 = -3.0e38f;
                    }
                    vv[nt][0] = v0; vv[nt][1] = v1;
                    rmax = fmaxf(rmax, fmaxf(v0, v1));
                }
                rmax = fmaxf(rmax, __shfl_xor_sync(0xffffffffu, rmax, 1));
                rmax = fmaxf(rmax, __shfl_xor_sync(0xffffffffu, rmax, 2));
                const int si = mt * 2 + hh;
                const float newm = fmaxf(m_run[si], rmax);
                const float corr = __expf(m_run[si] - newm);
                float pp[8][2];
                float se = 0.0f;
#pragma unroll
                for (int nt = 0; nt < 8; nt++) {
                    pp[nt][0] = __expf(vv[nt][0] - newm);
                    pp[nt][1] = __expf(vv[nt][1] - newm);
                    se += pp[nt][0] + pp[nt][1];
                }
                se += __shfl_xor_sync(0xffffffffu, se, 1);
                se += __shfl_xor_sync(0xffffffffu, se, 2);
                l_run[si] = l_run[si] * corr + se;
                m_run[si] = newm;

                if ((lane & 3) == 0)
                    g_mkt[mktbase + (size_t)kt * 256 + warp_n * 128 + row_l] = newm;

                float* prow = Pbase + (size_t)row_l * S_ + k0 + warp_n * 64 + (lane & 3) * 2;
#pragma unroll
                for (int nt = 0; nt < 8; nt++)
                    *(float2*)(prow + nt * 8) = make_float2(pp[nt][0], pp[nt][1]);
            }
        }
    }

    // cross-warp merge of the two column-half stats
    if ((lane & 3) == 0) {
#pragma unroll
        for (int mt = 0; mt < 2; mt++)
#pragma unroll
            for (int hh = 0; hh < 2; hh++) {
                const int row_l = warp_m * 32 + mt * 16 + (lane >> 2) + hh * 8;
                pm[warp_n * 128 + row_l] = m_run[mt * 2 + hh];
                pl[warp_n * 128 + row_l] = l_run[mt * 2 + hh];
            }
    }
    __syncthreads();
    if (tid < 128) {
        const float m0 = pm[tid], m1 = pm[128 + tid];
        const float l0 = pl[tid], l1 = pl[128 + tid];
        const float m = fmaxf(m0, m1);
        const float l = l0 * __expf(m0 - m) + l1 * __expf(m1 - m);
        const int gidx = bh * S_ + q0 + tid;
        g_m[gidx] = m;
        g_linv[gidx] = 1.0f / l;
    }

    // zero-fill causal upper triangle
    const int zbase = (qt + 1) * TT;
    const int zc4 = (S_ - zbase) >> 2;
    if (zc4 > 0) {
        const float4 z4 = make_float4(0.f, 0.f, 0.f, 0.f);
        for (int r = 0; r < TT; r++) {
            float* prow = Pbase + (size_t)r * S_ + zbase;
            for (int c4 = tid; c4 < zc4; c4 += 256)
                *(float4*)(prow + (c4 << 2)) = z4;
        }
    }
}

// ---------------------------------------------------------------------------
// kernel 2: finalize weights (multiply only, no exp) + O = P V via HMMA,
//           double-buffered cp.async V staging
// ---------------------------------------------------------------------------
__global__ void __launch_bounds__(256, 1)
pv_kernel(float* __restrict__ out)
{
    extern __shared__ char smc[];
    const uint32_t sb = smem_to_u32(smc);
    float* sc_s = (float*)(smc + STAT_OFF);  // [2][128] per-half finalize scale
    float* msm = sc_s + 256;                 // [128] final row max
    float* lsm = msm + 128;                  // [128] 1/l

    const int tid = threadIdx.x, lane = tid & 31, wid = tid >> 5;
    const int warp_m = wid & 3, warp_n = wid >> 2;
    const int qt = blockIdx.x, h = blockIdx.y, b = blockIdx.z;
    const int kvh = h >> 2, q0 = qt * TT;
    const int bh = b * H_ + h;

    float* Pbase = out + OUT_P + ((size_t)bh * S_ + q0) * S_;
    float* Obase = out + ((size_t)bh * S_ + q0) * D_;
    const size_t vbase = ((size_t)(b * KVH_ + kvh)) * D_ * S_;
    const size_t mktbase = ((size_t)bh * 16 + qt) * 16 * 256;

    if (tid < 128) {
        const int gidx = bh * S_ + q0 + tid;
        msm[tid] = g_m[gidx];
        lsm[tid] = g_linv[gidx];
    }

    // prefetch V tile 0 into BUF0
    {
#pragma unroll
        for (int it = 0; it < 16; it++) {
            int idx = it * 256 + tid;
            int arr = idx >> 11, rem = idx & 2047;
            int r = rem >> 4, c = (rem & 15) * 8;
            const __nv_bfloat16* src = (arr ? gVtlo : gVthi) + vbase + (size_t)r * S_ + c;
            CP_ASYNC16(sb + BUF0 + (arr ? 32768 : 0) + toff(r, c), src);
        }
        CP_COMMIT();
    }

    float acc[2][8][4];
#pragma unroll
    for (int mt = 0; mt < 2; mt++)
#pragma unroll
        for (int nt = 0; nt < 8; nt++)
#pragma unroll
            for (int k = 0; k < 4; k++) acc[mt][nt][k] = 0.0f;

    for (int kt = 0; kt <= qt; kt++) {
        const int k0 = kt * TT;
        CP_WAIT0();
        __syncthreads();
        if (kt < qt) {
            const uint32_t nb = ((kt + 1) & 1) ? BUF1 : BUF0;
#pragma unroll
            for (int it = 0; it < 16; it++) {
                int idx = it * 256 + tid;
                int arr = idx >> 11, rem = idx & 2047;
                int r = rem >> 4, c = (rem & 15) * 8;
                const __nv_bfloat16* src =
                    (arr ? gVtlo : gVthi) + vbase + (size_t)r * S_ + k0 + TT + c;
                CP_ASYNC16(sb + nb + (arr ? 32768 : 0) + toff(r, c), src);
            }
            CP_COMMIT();
        }
        const uint32_t Tb = (kt & 1) ? BUF1 : BUF0;

        // per-(half,row) finalize scale: exp(m_kt - m_fin) * linv   (256 exps)
        {
            const int row = tid & 127;
            const float mkt = g_mkt[mktbase + (size_t)kt * 256 + tid];
            sc_s[tid] = __expf(mkt - msm[row]) * lsm[row];
        }
        __syncthreads();

        // P: read p~, scale, write final weights, stage hi/lo bf16
#pragma unroll 4
        for (int it = 0; it < 16; it++) {
            int idx = it * 256 + tid;
            int r = idx >> 5, c4 = (idx & 31) << 2;
            float* pp = Pbase + (size_t)r * S_ + k0 + c4;
            float4 s4 = *(const float4*)pp;
            const float sc = sc_s[((c4 >> 6) << 7) + r];
            float4 p4;
            p4.x = s4.x * sc;
            p4.y = s4.y * sc;
            p4.z = s4.z * sc;
            p4.w = s4.w * sc;
            *(float4*)pp = p4;
            __nv_bfloat162 h01 = __floats2bfloat162_rn(p4.x, p4.y);
            __nv_bfloat162 h23 = __floats2bfloat162_rn(p4.z, p4.w);
            __nv_bfloat162 l01 = __floats2bfloat162_rn(p4.x - __bfloat162float(h01.x),
                                                       p4.y - __bfloat162float(h01.y));
            __nv_bfloat162 l23 = __floats2bfloat162_rn(p4.z - __bfloat162float(h23.x),
                                                       p4.w - __bfloat162float(h23.y));
            uint32_t o = toff(r, c4);
            *(uint2*)(smc + A_HI + o) = make_uint2(b2u(h01), b2u(h23));
            *(uint2*)(smc + A_LO + o) = make_uint2(b2u(l01), b2u(l23));
        }
        __syncthreads();

#pragma unroll
        for (int ks = 0; ks < 8; ks++) {
            uint32_t ah[2][4], al[2][4], bh2[8][2], bl[8][2];
#pragma unroll
            for (int mt = 0; mt < 2; mt++) {
                int r = warp_m * 32 + mt * 16 + (lane & 15);
                int cc = ks * 16 + (lane >> 4) * 8;
                uint32_t o = toff(r, cc);
                LDSM_X4(ah[mt][0], ah[mt][1], ah[mt][2], ah[mt][3], sb + A_HI + o);
                LDSM_X4(al[mt][0], al[mt][1], al[mt][2], al[mt][3], sb + A_LO + o);
            }
#pragma unroll
            for (int np = 0; np < 4; np++) {
                int r = warp_n * 64 + np * 16 + ((lane >> 4) << 3) + (lane & 7);
                int cc = ks * 16 + ((lane >> 3) & 1) * 8;
                uint32_t o = toff(r, cc);
                LDSM_X4(bh2[2 * np][0], bh2[2 * np][1], bh2[2 * np + 1][0], bh2[2 * np + 1][1],
                        sb + Tb + o);
                LDSM_X4(bl[2 * np][0], bl[2 * np][1], bl[2 * np + 1][0], bl[2 * np + 1][1],
                        sb + Tb + 32768 + o);
            }
#pragma unroll
            for (int mt = 0; mt < 2; mt++)
#pragma unroll
                for (int nt = 0; nt < 8; nt++) {
                    mma16816(acc[mt][nt], ah[mt], bh2[nt]);
                    mma16816(acc[mt][nt], al[mt], bh2[nt]);
                    mma16816(acc[mt][nt], ah[mt], bl[nt]);
                }
        }
    }

    // O epilogue
#pragma unroll
    for (int mt = 0; mt < 2; mt++)
#pragma unroll
        for (int hh = 0; hh < 2; hh++) {
            const int row_l = warp_m * 32 + mt * 16 + (lane >> 2) + hh * 8;
            float* orow = Obase + (size_t)row_l * D_ + warp_n * 64 + (lane & 3) * 2;
#pragma unroll
            for (int nt = 0; nt < 8; nt++)
                *(float2*)(orow + nt * 8) =
                    make_float2(acc[mt][nt][hh * 2], acc[mt][nt][hh * 2 + 1]);
        }
}

// ---------------------------------------------------------------------------
// kernel 3: present = (key copy, value permute)
// ---------------------------------------------------------------------------
__global__ void copy_kv_kernel(const float* __restrict__ K, const float* __restrict__ Vv,
                               float* __restrict__ out)
{
    const int i = blockIdx.x * 256 + threadIdx.x;
    if (i < 1048576) {
        ((float4*)(out + OUT_K))[i] = ((const float4*)K)[i];
    } else {
        const int j = i - 1048576;
        const int row = j >> 5;
        const int d4 = (j & 31) << 2;
        const int b = row >> 14;
        const int kvh = (row >> 11) & 7;
        const int s = row & 2047;
        const float4 v = *(const float4*)(Vv + ((((size_t)b * S_ + s) * KVH_ + kvh) << 7) + d4);
        *(float4*)(out + OUT_V + ((size_t)row << 7) + d4) = v;
    }
}

extern "C" void kernel_launch(void* const* d_in, const int* in_sizes, int n_in,
                              void* d_out, int out_size)
{
    (void)in_sizes; (void)n_in; (void)out_size;
    const float* Q     = (const float*)d_in[0];
    const float* K     = (const float*)d_in[1];
    const float* V     = (const float*)d_in[2];
    const float* scale = (const float*)d_in[4];
    float* out = (float*)d_out;

    cudaFuncSetAttribute(qk_kernel, cudaFuncAttributeMaxDynamicSharedMemorySize, SMEM_SZ);
    cudaFuncSetAttribute(pv_kernel, cudaFuncAttributeMaxDynamicSharedMemorySize, SMEM_SZ);

    cvtQ_kernel<<<16384, 256>>>(Q);
    cvtK_kernel<<<4096, 256>>>(K);
    cvtV_kernel<<<dim3(16, 4, 16), 256>>>(V);
    copy_kv_kernel<<<8192, 256>>>(K, V, out);

    dim3 grid(S_ / TT, H_, B_);
    qk_kernel<<<grid, 256, SMEM_SZ>>>(scale, out);
    pv_kernel<<<grid, 256, SMEM_SZ>>>(out);
}

// round 7
// speedup vs baseline: 2.1195x; 1.0567x over previous
#include <cuda_runtime.h>
#include <cuda_bf16.h>
#include <cstdint>

#define B_   2
#define H_   32
#define KVH_ 8
#define S_   2048
#define D_   128
#define TT   128

static const size_t OUT_P = (size_t)B_ * H_ * S_ * D_;            // attn_output end
static const size_t OUT_K = OUT_P + (size_t)B_ * H_ * S_ * S_;    // attn_weights end
static const size_t OUT_V = OUT_K + (size_t)B_ * KVH_ * S_ * D_;

// -------- scratch (__device__ BSS, no allocation) --------
__device__ __nv_bfloat16 gQhi[(size_t)B_ * H_ * S_ * D_];
__device__ __nv_bfloat16 gQlo[(size_t)B_ * H_ * S_ * D_];
__device__ __nv_bfloat16 gKhi[(size_t)B_ * KVH_ * S_ * D_];
__device__ __nv_bfloat16 gKlo[(size_t)B_ * KVH_ * S_ * D_];
__device__ __nv_bfloat16 gVthi[(size_t)B_ * KVH_ * D_ * S_];   // [b][kvh][d][s]
__device__ __nv_bfloat16 gVtlo[(size_t)B_ * KVH_ * D_ * S_];

__device__ __forceinline__ uint32_t smem_to_u32(const void* p) {
    uint32_t a;
    asm("{ .reg .u64 t; cvta.to.shared.u64 t, %1; cvt.u32.u64 %0, t; }" : "=r"(a) : "l"(p));
    return a;
}
__device__ __forceinline__ uint32_t b2u(__nv_bfloat162 x) { return *reinterpret_cast<uint32_t*>(&x); }

// byte offset inside a [128 x 128 bf16] tile, 256B rows, 16B-granule XOR swizzle
__device__ __forceinline__ uint32_t toff(int r, int c) {
    return (uint32_t)(r * 256 + ((((c >> 3) ^ (r & 7)) & 15) << 4) + (c & 7) * 2);
}

#define LDSM_X4(d0, d1, d2, d3, a) \
    asm volatile("ldmatrix.sync.aligned.m8n8.x4.shared.b16 {%0,%1,%2,%3}, [%4];" \
                 : "=r"(d0), "=r"(d1), "=r"(d2), "=r"(d3) : "r"(a))

__device__ __forceinline__ void mma16816(float* c, const uint32_t* a, const uint32_t* b) {
    asm volatile(
        "mma.sync.aligned.m16n8k16.row.col.f32.bf16.bf16.f32 "
        "{%0,%1,%2,%3}, {%4,%5,%6,%7}, {%8,%9}, {%0,%1,%2,%3};"
        : "+f"(c[0]), "+f"(c[1]), "+f"(c[2]), "+f"(c[3])
        : "r"(a[0]), "r"(a[1]), "r"(a[2]), "r"(a[3]), "r"(b[0]), "r"(b[1]));
}

#define CP_ASYNC16(dst, src) \
    asm volatile("cp.async.cg.shared.global [%0], [%1], 16;" :: "r"(dst), "l"(src))
#define CP_COMMIT() asm volatile("cp.async.commit_group;")
#define CP_WAIT0()  asm volatile("cp.async.wait_group 0;")
#define CP_WAIT1()  asm volatile("cp.async.wait_group 1;")

// smem layout (byte offsets)
#define Q_HI   0
#define Q_LO   32768
#define KP_HI  65536        // K tile, later reused for P~ staging
#define KP_LO  98304
#define VT_HI  131072
#define VT_LO  163840
#define TMAX_OFF 196608     // [2][128] per-half tile max
#define PM_OFF   (196608 + 1024)   // [128] final row max
#define PL_OFF   (196608 + 1536)   // [2][128] l partials
#define LSM_OFF  (196608 + 2560)   // [128] 1/l
#define MKT_OFF  (196608 + 3072)   // [16][128] running max per tile (later scales)
#define SMEM_SZ  (196608 + 3072 + 8192)

// ---------------------------------------------------------------------------
// conversion kernels
// ---------------------------------------------------------------------------
__global__ void cvtQ_kernel(const float* __restrict__ Q) {
    size_t i = (size_t)blockIdx.x * 256 + threadIdx.x;  // float4 index
    float4 v = ((const float4*)Q)[i];
    __nv_bfloat162 h01 = __floats2bfloat162_rn(v.x, v.y);
    __nv_bfloat162 h23 = __floats2bfloat162_rn(v.z, v.w);
    __nv_bfloat162 l01 = __floats2bfloat162_rn(v.x - __bfloat162float(h01.x),
                                               v.y - __bfloat162float(h01.y));
    __nv_bfloat162 l23 = __floats2bfloat162_rn(v.z - __bfloat162float(h23.x),
                                               v.w - __bfloat162float(h23.y));
    ((uint2*)gQhi)[i] = make_uint2(b2u(h01), b2u(h23));
    ((uint2*)gQlo)[i] = make_uint2(b2u(l01), b2u(l23));
}
__global__ void cvtK_kernel(const float* __restrict__ K) {
    size_t i = (size_t)blockIdx.x * 256 + threadIdx.x;
    float4 v = ((const float4*)K)[i];
    __nv_bfloat162 h01 = __floats2bfloat162_rn(v.x, v.y);
    __nv_bfloat162 h23 = __floats2bfloat162_rn(v.z, v.w);
    __nv_bfloat162 l01 = __floats2bfloat162_rn(v.x - __bfloat162float(h01.x),
                                               v.y - __bfloat162float(h01.y));
    __nv_bfloat162 l23 = __floats2bfloat162_rn(v.z - __bfloat162float(h23.x),
                                               v.w - __bfloat162float(h23.y));
    ((uint2*)gKhi)[i] = make_uint2(b2u(h01), b2u(h23));
    ((uint2*)gKlo)[i] = make_uint2(b2u(l01), b2u(l23));
}
// V [b,s,kvh,d] fp32 -> Vt [b,kvh,d,s] bf16 hi/lo (smem tile transpose)
__global__ void cvtV_kernel(const float* __restrict__ V) {
    __shared__ float sm[32][129];
    const int bk = blockIdx.z, b = bk >> 3, kvh = bk & 7;
    const int s0 = blockIdx.x * 128, d0 = blockIdx.y * 32;
    const int tid = threadIdx.x;
#pragma unroll
    for (int it = 0; it < 4; it++) {
        int idx = it * 256 + tid;
        int s = idx >> 3, d4 = (idx & 7) * 4;
        float4 v = *(const float4*)(V + ((((size_t)b * S_ + s0 + s) * KVH_ + kvh) * D_) + d0 + d4);
        sm[d4 + 0][s] = v.x; sm[d4 + 1][s] = v.y; sm[d4 + 2][s] = v.z; sm[d4 + 3][s] = v.w;
    }
    __syncthreads();
    const size_t obase = ((size_t)(b * KVH_ + kvh) * D_ + d0) * S_ + s0;
#pragma unroll
    for (int it = 0; it < 8; it++) {
        int idx = it * 256 + tid;
        int d = idx >> 6, j = idx & 63, s = 2 * j;
        float a = sm[d][s], c = sm[d][s + 1];
        __nv_bfloat162 h = __floats2bfloat162_rn(a, c);
        __nv_bfloat162 l = __floats2bfloat162_rn(a - __bfloat162float(h.x), c - __bfloat162float(h.y));
        *(uint32_t*)(&gVthi[obase + (size_t)d * S_ + s]) = b2u(h);
        *(uint32_t*)(&gVtlo[obase + (size_t)d * S_ + s]) = b2u(l);
    }
}

// ---------------------------------------------------------------------------
// fused flash kernel: QK -> online softmax -> PV in one pass, then per-CTA
// weights finalize (rescale + zero-fill)
// ---------------------------------------------------------------------------
__global__ void __launch_bounds__(256, 1)
fused_attn_kernel(const float* __restrict__ scale_ptr, float* __restrict__ out)
{
    extern __shared__ char smc[];
    const uint32_t sb = smem_to_u32(smc);
    float* tmax = (float*)(smc + TMAX_OFF);
    float* pmf  = (float*)(smc + PM_OFF);
    float* plf  = (float*)(smc + PL_OFF);
    float* lsm  = (float*)(smc + LSM_OFF);
    float* mkt  = (float*)(smc + MKT_OFF);

    const int tid = threadIdx.x, lane = tid & 31, wid = tid >> 5;
    const int warp_m = wid & 3, warp_n = wid >> 2;   // 4 x 2 warp grid
    const int qt = blockIdx.x, h = blockIdx.y, b = blockIdx.z;
    const int kvh = h >> 2, q0 = qt * TT;
    const int bh = b * H_ + h;
    const float inv_scale = 1.0f / scale_ptr[0];

    const size_t qbase = ((size_t)bh * S_ + q0) * D_;
    const size_t kbase = ((size_t)(b * KVH_ + kvh)) * S_ * D_;
    const size_t vbase = ((size_t)(b * KVH_ + kvh)) * D_ * S_;
    float* Pbase = out + OUT_P + ((size_t)bh * S_ + q0) * S_;
    float* Obase = out + ((size_t)bh * S_ + q0) * D_;

    // stage Q hi/lo tiles (once, direct)
#pragma unroll
    for (int it = 0; it < 16; it++) {
        int idx = it * 256 + tid;
        int arr = idx >> 11, rem = idx & 2047;
        int r = rem >> 4, c = (rem & 15) * 8;
        const __nv_bfloat16* src = (arr ? gQlo : gQhi) + qbase + (size_t)r * D_ + c;
        *(uint4*)(smc + (arr ? Q_LO : Q_HI) + toff(r, c)) = *(const uint4*)src;
    }

    // prefetch K tile 0 (group A), Vt tile 0 (group B)
#pragma unroll
    for (int it = 0; it < 16; it++) {
        int idx = it * 256 + tid;
        int arr = idx >> 11, rem = idx & 2047;
        int r = rem >> 4, c = (rem & 15) * 8;
        const __nv_bfloat16* src = (arr ? gKlo : gKhi) + kbase + (size_t)r * D_ + c;
        CP_ASYNC16(sb + (arr ? KP_LO : KP_HI) + toff(r, c), src);
    }
    CP_COMMIT();
#pragma unroll
    for (int it = 0; it < 16; it++) {
        int idx = it * 256 + tid;
        int arr = idx >> 11, rem = idx & 2047;
        int r = rem >> 4, c = (rem & 15) * 8;
        const __nv_bfloat16* src = (arr ? gVtlo : gVthi) + vbase + (size_t)r * S_ + c;
        CP_ASYNC16(sb + (arr ? VT_LO : VT_HI) + toff(r, c), src);
    }
    CP_COMMIT();

    float m_run[4], l_run[4];
#pragma unroll
    for (int i = 0; i < 4; i++) { m_run[i] = -3.0e38f; l_run[i] = 0.0f; }

    float acc_o[2][8][4];
#pragma unroll
    for (int mt = 0; mt < 2; mt++)
#pragma unroll
        for (int nt = 0; nt < 8; nt++)
#pragma unroll
            for (int k = 0; k < 4; k++) acc_o[mt][nt][k] = 0.0f;

    for (int kt = 0; kt <= qt; kt++) {
        const int k0 = kt * TT;
        CP_WAIT1();         // K tile ready (Vt may still be in flight)
        __syncthreads();

        // ---- QK MMA phase ----
        float acc[2][8][4];
#pragma unroll
        for (int mt = 0; mt < 2; mt++)
#pragma unroll
            for (int nt = 0; nt < 8; nt++)
#pragma unroll
                for (int k = 0; k < 4; k++) acc[mt][nt][k] = 0.0f;

#pragma unroll
        for (int ks = 0; ks < 8; ks++) {
            uint32_t ah[2][4], al[2][4], bh2[8][2], bl[8][2];
#pragma unroll
            for (int mt = 0; mt < 2; mt++) {
                int r = warp_m * 32 + mt * 16 + (lane & 15);
                int cc = ks * 16 + (lane >> 4) * 8;
                uint32_t o = toff(r, cc);
                LDSM_X4(ah[mt][0], ah[mt][1], ah[mt][2], ah[mt][3], sb + Q_HI + o);
                LDSM_X4(al[mt][0], al[mt][1], al[mt][2], al[mt][3], sb + Q_LO + o);
            }
#pragma unroll
            for (int np = 0; np < 4; np++) {
                int r = warp_n * 64 + np * 16 + ((lane >> 4) << 3) + (lane & 7);
                int cc = ks * 16 + ((lane >> 3) & 1) * 8;
                uint32_t o = toff(r, cc);
                LDSM_X4(bh2[2 * np][0], bh2[2 * np][1], bh2[2 * np + 1][0], bh2[2 * np + 1][1],
                        sb + KP_HI + o);
                LDSM_X4(bl[2 * np][0], bl[2 * np][1], bl[2 * np + 1][0], bl[2 * np + 1][1],
                        sb + KP_LO + o);
            }
#pragma unroll
            for (int mt = 0; mt < 2; mt++)
#pragma unroll
                for (int nt = 0; nt < 8; nt++) {
                    mma16816(acc[mt][nt], ah[mt], bh2[nt]);
                    mma16816(acc[mt][nt], al[mt], bh2[nt]);
                    mma16816(acc[mt][nt], ah[mt], bl[nt]);
                }
        }

        // ---- epilogue 1: per-half tile max -> smem ----
        const bool diag = (kt == qt);
#pragma unroll
        for (int mt = 0; mt < 2; mt++) {
#pragma unroll
            for (int hh = 0; hh < 2; hh++) {
                const int row_l = warp_m * 32 + mt * 16 + (lane >> 2) + hh * 8;
                float rmax = -3.0e38f;
#pragma unroll
                for (int nt = 0; nt < 8; nt++) {
                    float v0 = acc[mt][nt][hh * 2]     * inv_scale;
                    float v1 = acc[mt][nt][hh * 2 + 1] * inv_scale;
                    if (diag) {
                        int colb = warp_n * 64 + nt * 8 + (lane & 3) * 2;
                        if (colb > row_l)     v0 = -3.0e38f;
                        if (colb + 1 > row_l) v1 = -3.0e38f;
                    }
                    rmax = fmaxf(rmax, fmaxf(v0, v1));
                }
                rmax = fmaxf(rmax, __shfl_xor_sync(0xffffffffu, rmax, 1));
                rmax = fmaxf(rmax, __shfl_xor_sync(0xffffffffu, rmax, 2));
                if ((lane & 3) == 0) tmax[warp_n * 128 + row_l] = rmax;
            }
        }
        __syncthreads();   // also: all warps done reading K -> KP reusable

        // ---- epilogue 2: full-row newm, O rescale, p~, store + stage ----
#pragma unroll
        for (int mt = 0; mt < 2; mt++) {
#pragma unroll
            for (int hh = 0; hh < 2; hh++) {
                const int row_l = warp_m * 32 + mt * 16 + (lane >> 2) + hh * 8;
                const int si = mt * 2 + hh;
                const float newm =
                    fmaxf(m_run[si], fmaxf(tmax[row_l], tmax[128 + row_l]));
                const float corr = __expf(m_run[si] - newm);
#pragma unroll
                for (int nt = 0; nt < 8; nt++) {
                    acc_o[mt][nt][hh * 2]     *= corr;
                    acc_o[mt][nt][hh * 2 + 1] *= corr;
                }
                float pp[8][2];
                float se = 0.0f;
#pragma unroll
                for (int nt = 0; nt < 8; nt++) {
                    float v0 = acc[mt][nt][hh * 2]     * inv_scale;
                    float v1 = acc[mt][nt][hh * 2 + 1] * inv_scale;
                    if (diag) {
                        int colb = warp_n * 64 + nt * 8 + (lane & 3) * 2;
                        if (colb > row_l)     v0 = -3.0e38f;
                        if (colb + 1 > row_l) v1 = -3.0e38f;
                    }
                    pp[nt][0] = __expf(v0 - newm);
                    pp[nt][1] = __expf(v1 - newm);
                    se += pp[nt][0] + pp[nt][1];
                }
                se += __shfl_xor_sync(0xffffffffu, se, 1);
                se += __shfl_xor_sync(0xffffffffu, se, 2);
                l_run[si] = l_run[si] * corr + se;
                m_run[si] = newm;
                if (warp_n == 0 && (lane & 3) == 0) mkt[kt * 128 + row_l] = newm;

                // raw p~ to weights region (finalized in tail pass)
                float* prow = Pbase + (size_t)row_l * S_ + k0 + warp_n * 64 + (lane & 3) * 2;
#pragma unroll
                for (int nt = 0; nt < 8; nt++)
                    *(float2*)(prow + nt * 8) = make_float2(pp[nt][0], pp[nt][1]);

                // stage p~ as bf16 hi/lo into KP (K is dead)
#pragma unroll
                for (int nt = 0; nt < 8; nt++) {
                    const int colp = warp_n * 64 + nt * 8 + (lane & 3) * 2;
                    __nv_bfloat162 hi2 = __floats2bfloat162_rn(pp[nt][0], pp[nt][1]);
                    __nv_bfloat162 lo2 = __floats2bfloat162_rn(
                        pp[nt][0] - __bfloat162float(hi2.x),
                        pp[nt][1] - __bfloat162float(hi2.y));
                    uint32_t o = toff(row_l, colp);
                    *(uint32_t*)(smc + KP_HI + o) = b2u(hi2);
                    *(uint32_t*)(smc + KP_LO + o) = b2u(lo2);
                }
            }
        }
        CP_WAIT0();        // Vt tile ready
        __syncthreads();   // P~ staged

        // ---- PV MMA phase ----
#pragma unroll
        for (int ks = 0; ks < 8; ks++) {
            uint32_t ah[2][4], al[2][4], bh2[8][2], bl[8][2];
#pragma unroll
            for (int mt = 0; mt < 2; mt++) {
                int r = warp_m * 32 + mt * 16 + (lane & 15);
                int cc = ks * 16 + (lane >> 4) * 8;
                uint32_t o = toff(r, cc);
                LDSM_X4(ah[mt][0], ah[mt][1], ah[mt][2], ah[mt][3], sb + KP_HI + o);
                LDSM_X4(al[mt][0], al[mt][1], al[mt][2], al[mt][3], sb + KP_LO + o);
            }
#pragma unroll
            for (int np = 0; np < 4; np++) {
                int r = warp_n * 64 + np * 16 + ((lane >> 4) << 3) + (lane & 7);
                int cc = ks * 16 + ((lane >> 3) & 1) * 8;
                uint32_t o = toff(r, cc);
                LDSM_X4(bh2[2 * np][0], bh2[2 * np][1], bh2[2 * np + 1][0], bh2[2 * np + 1][1],
                        sb + VT_HI + o);
                LDSM_X4(bl[2 * np][0], bl[2 * np][1], bl[2 * np + 1][0], bl[2 * np + 1][1],
                        sb + VT_LO + o);
            }
#pragma unroll
            for (int mt = 0; mt < 2; mt++)
#pragma unroll
                for (int nt = 0; nt < 8; nt++) {
                    mma16816(acc_o[mt][nt], ah[mt], bh2[nt]);
                    mma16816(acc_o[mt][nt], al[mt], bh2[nt]);
                    mma16816(acc_o[mt][nt], ah[mt], bl[nt]);
                }
        }

        if (kt < qt) {
            __syncthreads();   // buffers fully consumed
#pragma unroll
            for (int it = 0; it < 16; it++) {
                int idx = it * 256 + tid;
                int arr = idx >> 11, rem = idx & 2047;
                int r = rem >> 4, c = (rem & 15) * 8;
                const __nv_bfloat16* src =
                    (arr ? gKlo : gKhi) + kbase + (size_t)(k0 + TT + r) * D_ + c;
                CP_ASYNC16(sb + (arr ? KP_LO : KP_HI) + toff(r, c), src);
            }
            CP_COMMIT();
#pragma unroll
            for (int it = 0; it < 16; it++) {
                int idx = it * 256 + tid;
                int arr = idx >> 11, rem = idx & 2047;
                int r = rem >> 4, c = (rem & 15) * 8;
                const __nv_bfloat16* src =
                    (arr ? gVtlo : gVthi) + vbase + (size_t)r * S_ + k0 + TT + c;
                CP_ASYNC16(sb + (arr ? VT_LO : VT_HI) + toff(r, c), src);
            }
            CP_COMMIT();
        }
    }

    // ---- merge l halves, final stats ----
    if ((lane & 3) == 0) {
#pragma unroll
        for (int mt = 0; mt < 2; mt++)
#pragma unroll
            for (int hh = 0; hh < 2; hh++) {
                const int row_l = warp_m * 32 + mt * 16 + (lane >> 2) + hh * 8;
                plf[warp_n * 128 + row_l] = l_run[mt * 2 + hh];
                if (warp_n == 0) pmf[row_l] = m_run[mt * 2 + hh];
            }
    }
    __syncthreads();
    if (tid < 128) lsm[tid] = 1.0f / (plf[tid] + plf[128 + tid]);
    __syncthreads();

    // ---- O epilogue ----
#pragma unroll
    for (int mt = 0; mt < 2; mt++)
#pragma unroll
        for (int hh = 0; hh < 2; hh++) {
            const int row_l = warp_m * 32 + mt * 16 + (lane >> 2) + hh * 8;
            const float li = lsm[row_l];
            float* orow = Obase + (size_t)row_l * D_ + warp_n * 64 + (lane & 3) * 2;
#pragma unroll
            for (int nt = 0; nt < 8; nt++)
                *(float2*)(orow + nt * 8) =
                    make_float2(acc_o[mt][nt][hh * 2] * li, acc_o[mt][nt][hh * 2 + 1] * li);
        }

    // ---- tail: finalize weights (in-place rescale) + zero-fill ----
    for (int i = tid; i < (qt + 1) * 128; i += 256) {
        const int r = i & 127;
        mkt[i] = __expf(mkt[i] - pmf[r]) * lsm[r];
    }
    __syncthreads();
    for (int kt2 = 0; kt2 <= qt; kt2++) {
#pragma unroll 4
        for (int it = 0; it < 16; it++) {
            int idx = it * 256 + tid;
            int r = idx >> 5, c4 = (idx & 31) << 2;
            float* pp = Pbase + (size_t)r * S_ + kt2 * TT + c4;
            const float sc = mkt[kt2 * 128 + r];
            float4 s4 = *(const float4*)pp;
            s4.x *= sc; s4.y *= sc; s4.z *= sc; s4.w *= sc;
            *(float4*)pp = s4;
        }
    }
    const int zbase = (qt + 1) * TT;
    const int zc4 = (S_ - zbase) >> 2;
    if (zc4 > 0) {
        const float4 z4 = make_float4(0.f, 0.f, 0.f, 0.f);
        for (int r = 0; r < TT; r++) {
            float* prow = Pbase + (size_t)r * S_ + zbase;
            for (int c4 = tid; c4 < zc4; c4 += 256)
                *(float4*)(prow + (c4 << 2)) = z4;
        }
    }
}

// ---------------------------------------------------------------------------
// present = (key copy, value permute)
// ---------------------------------------------------------------------------
__global__ void copy_kv_kernel(const float* __restrict__ K, const float* __restrict__ Vv,
                               float* __restrict__ out)
{
    const int i = blockIdx.x * 256 + threadIdx.x;
    if (i < 1048576) {
        ((float4*)(out + OUT_K))[i] = ((const float4*)K)[i];
    } else {
        const int j = i - 1048576;
        const int row = j >> 5;
        const int d4 = (j & 31) << 2;
        const int b = row >> 14;
        const int kvh = (row >> 11) & 7;
        const int s = row & 2047;
        const float4 v = *(const float4*)(Vv + ((((size_t)b * S_ + s) * KVH_ + kvh) << 7) + d4);
        *(float4*)(out + OUT_V + ((size_t)row << 7) + d4) = v;
    }
}

extern "C" void kernel_launch(void* const* d_in, const int* in_sizes, int n_in,
                              void* d_out, int out_size)
{
    (void)in_sizes; (void)n_in; (void)out_size;
    const float* Q     = (const float*)d_in[0];
    const float* K     = (const float*)d_in[1];
    const float* V     = (const float*)d_in[2];
    const float* scale = (const float*)d_in[4];
    float* out = (float*)d_out;

    cudaFuncSetAttribute(fused_attn_kernel, cudaFuncAttributeMaxDynamicSharedMemorySize, SMEM_SZ);

    cvtQ_kernel<<<16384, 256>>>(Q);
    cvtK_kernel<<<4096, 256>>>(K);
    cvtV_kernel<<<dim3(16, 4, 16), 256>>>(V);
    copy_kv_kernel<<<8192, 256>>>(K, V, out);

    dim3 grid(S_ / TT, H_, B_);
    fused_attn_kernel<<<grid, 256, SMEM_SZ>>>(scale, out);
}

// round 8
// speedup vs baseline: 2.5660x; 1.2107x over previous
#include <cuda_runtime.h>
#include <cuda_bf16.h>
#include <cstdint>

#define B_   2
#define H_   32
#define KVH_ 8
#define S_   2048
#define D_   128
#define TT   128

static const size_t OUT_P = (size_t)B_ * H_ * S_ * D_;            // attn_output end
static const size_t OUT_K = OUT_P + (size_t)B_ * H_ * S_ * S_;    // attn_weights end
static const size_t OUT_V = OUT_K + (size_t)B_ * KVH_ * S_ * D_;

// -------- scratch (__device__ BSS, no allocation) --------
__device__ __nv_bfloat16 gQhi[(size_t)B_ * H_ * S_ * D_];
__device__ __nv_bfloat16 gQlo[(size_t)B_ * H_ * S_ * D_];
__device__ __nv_bfloat16 gKhi[(size_t)B_ * KVH_ * S_ * D_];
__device__ __nv_bfloat16 gKlo[(size_t)B_ * KVH_ * S_ * D_];
__device__ __nv_bfloat16 gVthi[(size_t)B_ * KVH_ * D_ * S_];   // [b][kvh][d][s]
__device__ __nv_bfloat16 gVtlo[(size_t)B_ * KVH_ * D_ * S_];

__device__ __forceinline__ uint32_t smem_to_u32(const void* p) {
    uint32_t a;
    asm("{ .reg .u64 t; cvta.to.shared.u64 t, %1; cvt.u32.u64 %0, t; }" : "=r"(a) : "l"(p));
    return a;
}
__device__ __forceinline__ uint32_t b2u(__nv_bfloat162 x) { return *reinterpret_cast<uint32_t*>(&x); }

// byte offset inside a [128 x 128 bf16] tile, 256B rows, 16B-granule XOR swizzle
__device__ __forceinline__ uint32_t toff(int r, int c) {
    return (uint32_t)(r * 256 + ((((c >> 3) ^ (r & 7)) & 15) << 4) + (c & 7) * 2);
}

#define LDSM_X4(d0, d1, d2, d3, a) \
    asm volatile("ldmatrix.sync.aligned.m8n8.x4.shared.b16 {%0,%1,%2,%3}, [%4];" \
                 : "=r"(d0), "=r"(d1), "=r"(d2), "=r"(d3) : "r"(a))

__device__ __forceinline__ void mma16816(float* c, const uint32_t* a, const uint32_t* b) {
    asm volatile(
        "mma.sync.aligned.m16n8k16.row.col.f32.bf16.bf16.f32 "
        "{%0,%1,%2,%3}, {%4,%5,%6,%7}, {%8,%9}, {%0,%1,%2,%3};"
        : "+f"(c[0]), "+f"(c[1]), "+f"(c[2]), "+f"(c[3])
        : "r"(a[0]), "r"(a[1]), "r"(a[2]), "r"(a[3]), "r"(b[0]), "r"(b[1]));
}

#define CP_ASYNC16(dst, src) \
    asm volatile("cp.async.cg.shared.global [%0], [%1], 16;" :: "r"(dst), "l"(src))
#define CP_COMMIT() asm volatile("cp.async.commit_group;")
#define CP_WAIT0()  asm volatile("cp.async.wait_group 0;")
#define CP_WAIT1()  asm volatile("cp.async.wait_group 1;")

// streaming (evict-first) stores: keep the 1.1GB weights stream out of L2
#define STG_CS_F2(p, a, b) \
    asm volatile("st.global.cs.v2.f32 [%0], {%1,%2};" :: "l"(p), "f"(a), "f"(b))
#define STG_CS_F4(p, v) \
    asm volatile("st.global.cs.v4.f32 [%0], {%1,%2,%3,%4};" \
                 :: "l"(p), "f"((v).x), "f"((v).y), "f"((v).z), "f"((v).w))

// smem layout (byte offsets)
#define Q_HI   0
#define Q_LO   32768
#define KP_HI  65536        // K tile / P~ staging / finalize-pass buffer 0
#define KP_LO  98304
#define VT_HI  131072       // Vt tile / finalize-pass buffer 1
#define VT_LO  163840
#define TMAX_OFF 196608     // [2][128] per-half tile max
#define PM_OFF   (196608 + 1024)   // [128] final row max
#define PL_OFF   (196608 + 1536)   // [2][128] l partials
#define LSM_OFF  (196608 + 2560)   // [128] 1/l
#define SMEM_SZ  (196608 + 3072)

// ---------------------------------------------------------------------------
// conversion kernels
// ---------------------------------------------------------------------------
__global__ void cvtQ_kernel(const float* __restrict__ Q) {
    size_t i = (size_t)blockIdx.x * 256 + threadIdx.x;  // float4 index
    float4 v = ((const float4*)Q)[i];
    __nv_bfloat162 h01 = __floats2bfloat162_rn(v.x, v.y);
    __nv_bfloat162 h23 = __floats2bfloat162_rn(v.z, v.w);
    __nv_bfloat162 l01 = __floats2bfloat162_rn(v.x - __bfloat162float(h01.x),
                                               v.y - __bfloat162float(h01.y));
    __nv_bfloat162 l23 = __floats2bfloat162_rn(v.z - __bfloat162float(h23.x),
                                               v.w - __bfloat162float(h23.y));
    ((uint2*)gQhi)[i] = make_uint2(b2u(h01), b2u(h23));
    ((uint2*)gQlo)[i] = make_uint2(b2u(l01), b2u(l23));
}
__global__ void cvtK_kernel(const float* __restrict__ K) {
    size_t i = (size_t)blockIdx.x * 256 + threadIdx.x;
    float4 v = ((const float4*)K)[i];
    __nv_bfloat162 h01 = __floats2bfloat162_rn(v.x, v.y);
    __nv_bfloat162 h23 = __floats2bfloat162_rn(v.z, v.w);
    __nv_bfloat162 l01 = __floats2bfloat162_rn(v.x - __bfloat162float(h01.x),
                                               v.y - __bfloat162float(h01.y));
    __nv_bfloat162 l23 = __floats2bfloat162_rn(v.z - __bfloat162float(h23.x),
                                               v.w - __bfloat162float(h23.y));
    ((uint2*)gKhi)[i] = make_uint2(b2u(h01), b2u(h23));
    ((uint2*)gKlo)[i] = make_uint2(b2u(l01), b2u(l23));
}
// V [b,s,kvh,d] fp32 -> Vt [b,kvh,d,s] bf16 hi/lo (smem tile transpose)
__global__ void cvtV_kernel(const float* __restrict__ V) {
    __shared__ float sm[32][129];
    const int bk = blockIdx.z, b = bk >> 3, kvh = bk & 7;
    const int s0 = blockIdx.x * 128, d0 = blockIdx.y * 32;
    const int tid = threadIdx.x;
#pragma unroll
    for (int it = 0; it < 4; it++) {
        int idx = it * 256 + tid;
        int s = idx >> 3, d4 = (idx & 7) * 4;
        float4 v = *(const float4*)(V + ((((size_t)b * S_ + s0 + s) * KVH_ + kvh) * D_) + d0 + d4);
        sm[d4 + 0][s] = v.x; sm[d4 + 1][s] = v.y; sm[d4 + 2][s] = v.z; sm[d4 + 3][s] = v.w;
    }
    __syncthreads();
    const size_t obase = ((size_t)(b * KVH_ + kvh) * D_ + d0) * S_ + s0;
#pragma unroll
    for (int it = 0; it < 8; it++) {
        int idx = it * 256 + tid;
        int d = idx >> 6, j = idx & 63, s = 2 * j;
        float a = sm[d][s], c = sm[d][s + 1];
        __nv_bfloat162 h = __floats2bfloat162_rn(a, c);
        __nv_bfloat162 l = __floats2bfloat162_rn(a - __bfloat162float(h.x), c - __bfloat162float(h.y));
        *(uint32_t*)(&gVthi[obase + (size_t)d * S_ + s]) = b2u(h);
        *(uint32_t*)(&gVtlo[obase + (size_t)d * S_ + s]) = b2u(l);
    }
}

// ---------------------------------------------------------------------------
// fused flash kernel: pass A = QK -> online softmax -> PV (no weight stores);
// pass B = recompute QK per tile, write FINAL weights once (.cs); zero-fill.
// ---------------------------------------------------------------------------
__global__ void __launch_bounds__(256, 1)
fused_attn_kernel(const float* __restrict__ scale_ptr, float* __restrict__ out)
{
    extern __shared__ char smc[];
    const uint32_t sb = smem_to_u32(smc);
    float* tmax = (float*)(smc + TMAX_OFF);
    float* pmf  = (float*)(smc + PM_OFF);
    float* plf  = (float*)(smc + PL_OFF);
    float* lsm  = (float*)(smc + LSM_OFF);

    const int tid = threadIdx.x, lane = tid & 31, wid = tid >> 5;
    const int warp_m = wid & 3, warp_n = wid >> 2;   // 4 x 2 warp grid
    const int qt = blockIdx.x, h = blockIdx.y, b = blockIdx.z;
    const int kvh = h >> 2, q0 = qt * TT;
    const int bh = b * H_ + h;
    const float inv_scale = 1.0f / scale_ptr[0];

    const size_t qbase = ((size_t)bh * S_ + q0) * D_;
    const size_t kbase = ((size_t)(b * KVH_ + kvh)) * S_ * D_;
    const size_t vbase = ((size_t)(b * KVH_ + kvh)) * D_ * S_;
    float* Pbase = out + OUT_P + ((size_t)bh * S_ + q0) * S_;
    float* Obase = out + ((size_t)bh * S_ + q0) * D_;

    // stage Q hi/lo tiles (once, direct)
#pragma unroll
    for (int it = 0; it < 16; it++) {
        int idx = it * 256 + tid;
        int arr = idx >> 11, rem = idx & 2047;
        int r = rem >> 4, c = (rem & 15) * 8;
        const __nv_bfloat16* src = (arr ? gQlo : gQhi) + qbase + (size_t)r * D_ + c;
        *(uint4*)(smc + (arr ? Q_LO : Q_HI) + toff(r, c)) = *(const uint4*)src;
    }

    // prefetch K tile 0 (group A), Vt tile 0 (group B)
#pragma unroll
    for (int it = 0; it < 16; it++) {
        int idx = it * 256 + tid;
        int arr = idx >> 11, rem = idx & 2047;
        int r = rem >> 4, c = (rem & 15) * 8;
        const __nv_bfloat16* src = (arr ? gKlo : gKhi) + kbase + (size_t)r * D_ + c;
        CP_ASYNC16(sb + (arr ? KP_LO : KP_HI) + toff(r, c), src);
    }
    CP_COMMIT();
#pragma unroll
    for (int it = 0; it < 16; it++) {
        int idx = it * 256 + tid;
        int arr = idx >> 11, rem = idx & 2047;
        int r = rem >> 4, c = (rem & 15) * 8;
        const __nv_bfloat16* src = (arr ? gVtlo : gVthi) + vbase + (size_t)r * S_ + c;
        CP_ASYNC16(sb + (arr ? VT_LO : VT_HI) + toff(r, c), src);
    }
    CP_COMMIT();

    float m_run[4], l_run[4];
#pragma unroll
    for (int i = 0; i < 4; i++) { m_run[i] = -3.0e38f; l_run[i] = 0.0f; }

    float acc_o[2][8][4];
#pragma unroll
    for (int mt = 0; mt < 2; mt++)
#pragma unroll
        for (int nt = 0; nt < 8; nt++)
#pragma unroll
            for (int k = 0; k < 4; k++) acc_o[mt][nt][k] = 0.0f;

    // ================= pass A: online softmax + O accumulation =================
    for (int kt = 0; kt <= qt; kt++) {
        const int k0 = kt * TT;
        CP_WAIT1();         // K tile ready (Vt may still be in flight)
        __syncthreads();

        // ---- QK MMA phase ----
        float acc[2][8][4];
#pragma unroll
        for (int mt = 0; mt < 2; mt++)
#pragma unroll
            for (int nt = 0; nt < 8; nt++)
#pragma unroll
                for (int k = 0; k < 4; k++) acc[mt][nt][k] = 0.0f;

#pragma unroll
        for (int ks = 0; ks < 8; ks++) {
            uint32_t ah[2][4], al[2][4], bh2[8][2], bl[8][2];
#pragma unroll
            for (int mt = 0; mt < 2; mt++) {
                int r = warp_m * 32 + mt * 16 + (lane & 15);
                int cc = ks * 16 + (lane >> 4) * 8;
                uint32_t o = toff(r, cc);
                LDSM_X4(ah[mt][0], ah[mt][1], ah[mt][2], ah[mt][3], sb + Q_HI + o);
                LDSM_X4(al[mt][0], al[mt][1], al[mt][2], al[mt][3], sb + Q_LO + o);
            }
#pragma unroll
            for (int np = 0; np < 4; np++) {
                int r = warp_n * 64 + np * 16 + ((lane >> 4) << 3) + (lane & 7);
                int cc = ks * 16 + ((lane >> 3) & 1) * 8;
                uint32_t o = toff(r, cc);
                LDSM_X4(bh2[2 * np][0], bh2[2 * np][1], bh2[2 * np + 1][0], bh2[2 * np + 1][1],
                        sb + KP_HI + o);
                LDSM_X4(bl[2 * np][0], bl[2 * np][1], bl[2 * np + 1][0], bl[2 * np + 1][1],
                        sb + KP_LO + o);
            }
#pragma unroll
            for (int mt = 0; mt < 2; mt++)
#pragma unroll
                for (int nt = 0; nt < 8; nt++) {
                    mma16816(acc[mt][nt], ah[mt], bh2[nt]);
                    mma16816(acc[mt][nt], al[mt], bh2[nt]);
                    mma16816(acc[mt][nt], ah[mt], bl[nt]);
                }
        }

        // ---- epilogue 1: per-half tile max -> smem ----
        const bool diag = (kt == qt);
#pragma unroll
        for (int mt = 0; mt < 2; mt++) {
#pragma unroll
            for (int hh = 0; hh < 2; hh++) {
                const int row_l = warp_m * 32 + mt * 16 + (lane >> 2) + hh * 8;
                float rmax = -3.0e38f;
#pragma unroll
                for (int nt = 0; nt < 8; nt++) {
                    float v0 = acc[mt][nt][hh * 2]     * inv_scale;
                    float v1 = acc[mt][nt][hh * 2 + 1] * inv_scale;
                    if (diag) {
                        int colb = warp_n * 64 + nt * 8 + (lane & 3) * 2;
                        if (colb > row_l)     v0 = -3.0e38f;
                        if (colb + 1 > row_l) v1 = -3.0e38f;
                    }
                    rmax = fmaxf(rmax, fmaxf(v0, v1));
                }
                rmax = fmaxf(rmax, __shfl_xor_sync(0xffffffffu, rmax, 1));
                rmax = fmaxf(rmax, __shfl_xor_sync(0xffffffffu, rmax, 2));
                if ((lane & 3) == 0) tmax[warp_n * 128 + row_l] = rmax;
            }
        }
        __syncthreads();   // also: all warps done reading K -> KP reusable

        // ---- epilogue 2: full-row newm, O rescale, p~, stage to smem ----
#pragma unroll
        for (int mt = 0; mt < 2; mt++) {
#pragma unroll
            for (int hh = 0; hh < 2; hh++) {
                const int row_l = warp_m * 32 + mt * 16 + (lane >> 2) + hh * 8;
                const int si = mt * 2 + hh;
                const float newm =
                    fmaxf(m_run[si], fmaxf(tmax[row_l], tmax[128 + row_l]));
                const float corr = __expf(m_run[si] - newm);
#pragma unroll
                for (int nt = 0; nt < 8; nt++) {
                    acc_o[mt][nt][hh * 2]     *= corr;
                    acc_o[mt][nt][hh * 2 + 1] *= corr;
                }
                float pp[8][2];
                float se = 0.0f;
#pragma unroll
                for (int nt = 0; nt < 8; nt++) {
                    float v0 = acc[mt][nt][hh * 2]     * inv_scale;
                    float v1 = acc[mt][nt][hh * 2 + 1] * inv_scale;
                    if (diag) {
                        int colb = warp_n * 64 + nt * 8 + (lane & 3) * 2;
                        if (colb > row_l)     v0 = -3.0e38f;
                        if (colb + 1 > row_l) v1 = -3.0e38f;
                    }
                    pp[nt][0] = __expf(v0 - newm);
                    pp[nt][1] = __expf(v1 - newm);
                    se += pp[nt][0] + pp[nt][1];
                }
                se += __shfl_xor_sync(0xffffffffu, se, 1);
                se += __shfl_xor_sync(0xffffffffu, se, 2);
                l_run[si] = l_run[si] * corr + se;
                m_run[si] = newm;

                // stage p~ as bf16 hi/lo into KP (K is dead)
#pragma unroll
                for (int nt = 0; nt < 8; nt++) {
                    const int colp = warp_n * 64 + nt * 8 + (lane & 3) * 2;
                    __nv_bfloat162 hi2 = __floats2bfloat162_rn(pp[nt][0], pp[nt][1]);
                    __nv_bfloat162 lo2 = __floats2bfloat162_rn(
                        pp[nt][0] - __bfloat162float(hi2.x),
                        pp[nt][1] - __bfloat162float(hi2.y));
                    uint32_t o = toff(row_l, colp);
                    *(uint32_t*)(smc + KP_HI + o) = b2u(hi2);
                    *(uint32_t*)(smc + KP_LO + o) = b2u(lo2);
                }
            }
        }
        CP_WAIT0();        // Vt tile ready
        __syncthreads();   // P~ staged

        // ---- PV MMA phase ----
#pragma unroll
        for (int ks = 0; ks < 8; ks++) {
            uint32_t ah[2][4], al[2][4], bh2[8][2], bl[8][2];
#pragma unroll
            for (int mt = 0; mt < 2; mt++) {
                int r = warp_m * 32 + mt * 16 + (lane & 15);
                int cc = ks * 16 + (lane >> 4) * 8;
                uint32_t o = toff(r, cc);
                LDSM_X4(ah[mt][0], ah[mt][1], ah[mt][2], ah[mt][3], sb + KP_HI + o);
                LDSM_X4(al[mt][0], al[mt][1], al[mt][2], al[mt][3], sb + KP_LO + o);
            }
#pragma unroll
            for (int np = 0; np < 4; np++) {
                int r = warp_n * 64 + np * 16 + ((lane >> 4) << 3) + (lane & 7);
                int cc = ks * 16 + ((lane >> 3) & 1) * 8;
                uint32_t o = toff(r, cc);
                LDSM_X4(bh2[2 * np][0], bh2[2 * np][1], bh2[2 * np + 1][0], bh2[2 * np + 1][1],
                        sb + VT_HI + o);
                LDSM_X4(bl[2 * np][0], bl[2 * np][1], bl[2 * np + 1][0], bl[2 * np + 1][1],
                        sb + VT_LO + o);
            }
#pragma unroll
            for (int mt = 0; mt < 2; mt++)
#pragma unroll
                for (int nt = 0; nt < 8; nt++) {
                    mma16816(acc_o[mt][nt], ah[mt], bh2[nt]);
                    mma16816(acc_o[mt][nt], al[mt], bh2[nt]);
                    mma16816(acc_o[mt][nt], ah[mt], bl[nt]);
                }
        }

        if (kt < qt) {
            __syncthreads();   // buffers fully consumed
#pragma unroll
            for (int it = 0; it < 16; it++) {
                int idx = it * 256 + tid;
                int arr = idx >> 11, rem = idx & 2047;
                int r = rem >> 4, c = (rem & 15) * 8;
                const __nv_bfloat16* src =
                    (arr ? gKlo : gKhi) + kbase + (size_t)(k0 + TT + r) * D_ + c;
                CP_ASYNC16(sb + (arr ? KP_LO : KP_HI) + toff(r, c), src);
            }
            CP_COMMIT();
#pragma unroll
            for (int it = 0; it < 16; it++) {
                int idx = it * 256 + tid;
                int arr = idx >> 11, rem = idx & 2047;
                int r = rem >> 4, c = (rem & 15) * 8;
                const __nv_bfloat16* src =
                    (arr ? gVtlo : gVthi) + vbase + (size_t)r * S_ + k0 + TT + c;
                CP_ASYNC16(sb + (arr ? VT_LO : VT_HI) + toff(r, c), src);
            }
            CP_COMMIT();
        }
    }

    // ---- merge l halves, final stats ----
    if ((lane & 3) == 0) {
#pragma unroll
        for (int mt = 0; mt < 2; mt++)
#pragma unroll
            for (int hh = 0; hh < 2; hh++) {
                const int row_l = warp_m * 32 + mt * 16 + (lane >> 2) + hh * 8;
                plf[warp_n * 128 + row_l] = l_run[mt * 2 + hh];
                if (warp_n == 0) pmf[row_l] = m_run[mt * 2 + hh];
            }
    }
    __syncthreads();
    if (tid < 128) lsm[tid] = 1.0f / (plf[tid] + plf[128 + tid]);
    __syncthreads();

    // prefetch K tile 0 for pass B (into KP; p~ fully consumed by PV above)
#pragma unroll
    for (int it = 0; it < 16; it++) {
        int idx = it * 256 + tid;
        int arr = idx >> 11, rem = idx & 2047;
        int r = rem >> 4, c = (rem & 15) * 8;
        const __nv_bfloat16* src = (arr ? gKlo : gKhi) + kbase + (size_t)r * D_ + c;
        CP_ASYNC16(sb + KP_HI + (arr ? 32768 : 0) + toff(r, c), src);
    }
    CP_COMMIT();

    // ---- O epilogue (overlaps with pass-B prefetch) ----
#pragma unroll
    for (int mt = 0; mt < 2; mt++)
#pragma unroll
        for (int hh = 0; hh < 2; hh++) {
            const int row_l = warp_m * 32 + mt * 16 + (lane >> 2) + hh * 8;
            const float li = lsm[row_l];
            float* orow = Obase + (size_t)row_l * D_ + warp_n * 64 + (lane & 3) * 2;
#pragma unroll
            for (int nt = 0; nt < 8; nt++)
                STG_CS_F2(orow + nt * 8,
                          acc_o[mt][nt][hh * 2] * li, acc_o[mt][nt][hh * 2 + 1] * li);
        }

    // ================= pass B: recompute QK, write final weights =============
    for (int kt = 0; kt <= qt; kt++) {
        const int k0 = kt * TT;
        CP_WAIT0();
        __syncthreads();
        const uint32_t Tb = (kt & 1) ? VT_HI : KP_HI;
        if (kt < qt) {
            const uint32_t nb = ((kt + 1) & 1) ? VT_HI : KP_HI;
#pragma unroll
            for (int it = 0; it < 16; it++) {
                int idx = it * 256 + tid;
                int arr = idx >> 11, rem = idx & 2047;
                int r = rem >> 4, c = (rem & 15) * 8;
                const __nv_bfloat16* src =
                    (arr ? gKlo : gKhi) + kbase + (size_t)(k0 + TT + r) * D_ + c;
                CP_ASYNC16(sb + nb + (arr ? 32768 : 0) + toff(r, c), src);
            }
            CP_COMMIT();
        }

        float acc[2][8][4];
#pragma unroll
        for (int mt = 0; mt < 2; mt++)
#pragma unroll
            for (int nt = 0; nt < 8; nt++)
#pragma unroll
                for (int k = 0; k < 4; k++) acc[mt][nt][k] = 0.0f;

#pragma unroll
        for (int ks = 0; ks < 8; ks++) {
            uint32_t ah[2][4], al[2][4], bh2[8][2], bl[8][2];
#pragma unroll
            for (int mt = 0; mt < 2; mt++) {
                int r = warp_m * 32 + mt * 16 + (lane & 15);
                int cc = ks * 16 + (lane >> 4) * 8;
                uint32_t o = toff(r, cc);
                LDSM_X4(ah[mt][0], ah[mt][1], ah[mt][2], ah[mt][3], sb + Q_HI + o);
                LDSM_X4(al[mt][0], al[mt][1], al[mt][2], al[mt][3], sb + Q_LO + o);
            }
#pragma unroll
            for (int np = 0; np < 4; np++) {
                int r = warp_n * 64 + np * 16 + ((lane >> 4) << 3) + (lane & 7);
                int cc = ks * 16 + ((lane >> 3) & 1) * 8;
                uint32_t o = toff(r, cc);
                LDSM_X4(bh2[2 * np][0], bh2[2 * np][1], bh2[2 * np + 1][0], bh2[2 * np + 1][1],
                        sb + Tb + o);
                LDSM_X4(bl[2 * np][0], bl[2 * np][1], bl[2 * np + 1][0], bl[2 * np + 1][1],
                        sb + Tb + 32768 + o);
            }
#pragma unroll
            for (int mt = 0; mt < 2; mt++)
#pragma unroll
                for (int nt = 0; nt < 8; nt++) {
                    mma16816(acc[mt][nt], ah[mt], bh2[nt]);
                    mma16816(acc[mt][nt], al[mt], bh2[nt]);
                    mma16816(acc[mt][nt], ah[mt], bl[nt]);
                }
        }

        // finalize + store (streaming)
        const bool diag = (kt == qt);
#pragma unroll
        for (int mt = 0; mt < 2; mt++) {
#pragma unroll
            for (int hh = 0; hh < 2; hh++) {
                const int row_l = warp_m * 32 + mt * 16 + (lane >> 2) + hh * 8;
                const float mfin = pmf[row_l];
                const float li = lsm[row_l];
                float* prow = Pbase + (size_t)row_l * S_ + k0 + warp_n * 64 + (lane & 3) * 2;
#pragma unroll
                for (int nt = 0; nt < 8; nt++) {
                    float v0 = acc[mt][nt][hh * 2]     * inv_scale;
                    float v1 = acc[mt][nt][hh * 2 + 1] * inv_scale;
                    if (diag) {
                        int colb = warp_n * 64 + nt * 8 + (lane & 3) * 2;
                        if (colb > row_l)     v0 = -3.0e38f;
                        if (colb + 1 > row_l) v1 = -3.0e38f;
                    }
                    STG_CS_F2(prow + nt * 8,
                              __expf(v0 - mfin) * li, __expf(v1 - mfin) * li);
                }
            }
        }
    }

    // ---- zero-fill causal upper triangle (streaming) ----
    const int zbase = (qt + 1) * TT;
    const int zc4 = (S_ - zbase) >> 2;
    if (zc4 > 0) {
        const float4 z4 = make_float4(0.f, 0.f, 0.f, 0.f);
        for (int r = 0; r < TT; r++) {
            float* prow = Pbase + (size_t)r * S_ + zbase;
            for (int c4 = tid; c4 < zc4; c4 += 256)
                STG_CS_F4(prow + (c4 << 2), z4);
        }
    }
}

// ---------------------------------------------------------------------------
// present = (key copy, value permute)
// ---------------------------------------------------------------------------
__global__ void copy_kv_kernel(const float* __restrict__ K, const float* __restrict__ Vv,
                               float* __restrict__ out)
{
    const int i = blockIdx.x * 256 + threadIdx.x;
    if (i < 1048576) {
        float4 v = ((const float4*)K)[i];
        STG_CS_F4((float*)(out + OUT_K) + ((size_t)i << 2), v);
    } else {
        const int j = i - 1048576;
        const int row = j >> 5;
        const int d4 = (j & 31) << 2;
        const int b = row >> 14;
        const int kvh = (row >> 11) & 7;
        const int s = row & 2047;
        const float4 v = *(const float4*)(Vv + ((((size_t)b * S_ + s) * KVH_ + kvh) << 7) + d4);
        STG_CS_F4(out + OUT_V + ((size_t)row << 7) + d4, v);
    }
}

extern "C" void kernel_launch(void* const* d_in, const int* in_sizes, int n_in,
                              void* d_out, int out_size)
{
    (void)in_sizes; (void)n_in; (void)out_size;
    const float* Q     = (const float*)d_in[0];
    const float* K     = (const float*)d_in[1];
    const float* V     = (const float*)d_in[2];
    const float* scale = (const float*)d_in[4];
    float* out = (float*)d_out;

    cudaFuncSetAttribute(fused_attn_kernel, cudaFuncAttributeMaxDynamicSharedMemorySize, SMEM_SZ);

    cvtQ_kernel<<<16384, 256>>>(Q);
    cvtK_kernel<<<4096, 256>>>(K);
    cvtV_kernel<<<dim3(16, 4, 16), 256>>>(V);
    copy_kv_kernel<<<8192, 256>>>(K, V, out);

    dim3 grid(S_ / TT, H_, B_);
    fused_attn_kernel<<<grid, 256, SMEM_SZ>>>(scale, out);
}

// round 9
// speedup vs baseline: 2.6310x; 1.0253x over previous
#include <cuda_runtime.h>
#include <cuda_bf16.h>
#include <cstdint>

#define B_   2
#define H_   32
#define KVH_ 8
#define S_   2048
#define D_   128
#define TT   128

static const size_t OUT_P = (size_t)B_ * H_ * S_ * D_;            // attn_output end
static const size_t OUT_K = OUT_P + (size_t)B_ * H_ * S_ * S_;    // attn_weights end
static const size_t OUT_V = OUT_K + (size_t)B_ * KVH_ * S_ * D_;

// -------- scratch (__device__ BSS, no allocation) --------
__device__ __nv_bfloat16 gQhi[(size_t)B_ * H_ * S_ * D_];
__device__ __nv_bfloat16 gQlo[(size_t)B_ * H_ * S_ * D_];
__device__ __nv_bfloat16 gKhi[(size_t)B_ * KVH_ * S_ * D_];
__device__ __nv_bfloat16 gKlo[(size_t)B_ * KVH_ * S_ * D_];
__device__ __nv_bfloat16 gVthi[(size_t)B_ * KVH_ * D_ * S_];   // [b][kvh][d][s]
__device__ __nv_bfloat16 gVtlo[(size_t)B_ * KVH_ * D_ * S_];

__device__ __forceinline__ uint32_t smem_to_u32(const void* p) {
    uint32_t a;
    asm("{ .reg .u64 t; cvta.to.shared.u64 t, %1; cvt.u32.u64 %0, t; }" : "=r"(a) : "l"(p));
    return a;
}
__device__ __forceinline__ uint32_t b2u(__nv_bfloat162 x) { return *reinterpret_cast<uint32_t*>(&x); }

// byte offset inside a [128 x 128 bf16] tile, 256B rows, 16B-granule XOR swizzle
__device__ __forceinline__ uint32_t toff(int r, int c) {
    return (uint32_t)(r * 256 + ((((c >> 3) ^ (r & 7)) & 15) << 4) + (c & 7) * 2);
}

#define LDSM_X4(d0, d1, d2, d3, a) \
    asm volatile("ldmatrix.sync.aligned.m8n8.x4.shared.b16 {%0,%1,%2,%3}, [%4];" \
                 : "=r"(d0), "=r"(d1), "=r"(d2), "=r"(d3) : "r"(a))

__device__ __forceinline__ void mma16816(float* c, const uint32_t* a, const uint32_t* b) {
    asm volatile(
        "mma.sync.aligned.m16n8k16.row.col.f32.bf16.bf16.f32 "
        "{%0,%1,%2,%3}, {%4,%5,%6,%7}, {%8,%9}, {%0,%1,%2,%3};"
        : "+f"(c[0]), "+f"(c[1]), "+f"(c[2]), "+f"(c[3])
        : "r"(a[0]), "r"(a[1]), "r"(a[2]), "r"(a[3]), "r"(b[0]), "r"(b[1]));
}

#define CP_ASYNC16(dst, src) \
    asm volatile("cp.async.cg.shared.global [%0], [%1], 16;" :: "r"(dst), "l"(src))
#define CP_COMMIT() asm volatile("cp.async.commit_group;")
#define CP_WAIT0()  asm volatile("cp.async.wait_group 0;")
#define CP_WAIT1()  asm volatile("cp.async.wait_group 1;")

// streaming (evict-first) stores
#define STG_CS_F2(p, a, b) \
    asm volatile("st.global.cs.v2.f32 [%0], {%1,%2};" :: "l"(p), "f"(a), "f"(b))
#define STG_CS_F4(p, v) \
    asm volatile("st.global.cs.v4.f32 [%0], {%1,%2,%3,%4};" \
                 :: "l"(p), "f"((v).x), "f"((v).y), "f"((v).z), "f"((v).w))

// smem layout (byte offsets)
#define Q_HI   0
#define Q_LO   32768
#define KP_HI  65536
#define KP_LO  98304
#define VT_HI  131072
#define VT_LO  163840
#define SMEM_SZ 196608

// ---------------------------------------------------------------------------
// conversion kernels
// ---------------------------------------------------------------------------
__global__ void cvtQ_kernel(const float* __restrict__ Q) {
    size_t i = (size_t)blockIdx.x * 256 + threadIdx.x;  // float4 index
    float4 v = ((const float4*)Q)[i];
    __nv_bfloat162 h01 = __floats2bfloat162_rn(v.x, v.y);
    __nv_bfloat162 h23 = __floats2bfloat162_rn(v.z, v.w);
    __nv_bfloat162 l01 = __floats2bfloat162_rn(v.x - __bfloat162float(h01.x),
                                               v.y - __bfloat162float(h01.y));
    __nv_bfloat162 l23 = __floats2bfloat162_rn(v.z - __bfloat162float(h23.x),
                                               v.w - __bfloat162float(h23.y));
    ((uint2*)gQhi)[i] = make_uint2(b2u(h01), b2u(h23));
    ((uint2*)gQlo)[i] = make_uint2(b2u(l01), b2u(l23));
}
__global__ void cvtK_kernel(const float* __restrict__ K) {
    size_t i = (size_t)blockIdx.x * 256 + threadIdx.x;
    float4 v = ((const float4*)K)[i];
    __nv_bfloat162 h01 = __floats2bfloat162_rn(v.x, v.y);
    __nv_bfloat162 h23 = __floats2bfloat162_rn(v.z, v.w);
    __nv_bfloat162 l01 = __floats2bfloat162_rn(v.x - __bfloat162float(h01.x),
                                               v.y - __bfloat162float(h01.y));
    __nv_bfloat162 l23 = __floats2bfloat162_rn(v.z - __bfloat162float(h23.x),
                                               v.w - __bfloat162float(h23.y));
    ((uint2*)gKhi)[i] = make_uint2(b2u(h01), b2u(h23));
    ((uint2*)gKlo)[i] = make_uint2(b2u(l01), b2u(l23));
}
// V [b,s,kvh,d] fp32 -> Vt [b,kvh,d,s] bf16 hi/lo (smem tile transpose)
__global__ void cvtV_kernel(const float* __restrict__ V) {
    __shared__ float sm[32][129];
    const int bk = blockIdx.z, b = bk >> 3, kvh = bk & 7;
    const int s0 = blockIdx.x * 128, d0 = blockIdx.y * 32;
    const int tid = threadIdx.x;
#pragma unroll
    for (int it = 0; it < 4; it++) {
        int idx = it * 256 + tid;
        int s = idx >> 3, d4 = (idx & 7) * 4;
        float4 v = *(const float4*)(V + ((((size_t)b * S_ + s0 + s) * KVH_ + kvh) * D_) + d0 + d4);
        sm[d4 + 0][s] = v.x; sm[d4 + 1][s] = v.y; sm[d4 + 2][s] = v.z; sm[d4 + 3][s] = v.w;
    }
    __syncthreads();
    const size_t obase = ((size_t)(b * KVH_ + kvh) * D_ + d0) * S_ + s0;
#pragma unroll
    for (int it = 0; it < 8; it++) {
        int idx = it * 256 + tid;
        int d = idx >> 6, j = idx & 63, s = 2 * j;
        float a = sm[d][s], c = sm[d][s + 1];
        __nv_bfloat162 h = __floats2bfloat162_rn(a, c);
        __nv_bfloat162 l = __floats2bfloat162_rn(a - __bfloat162float(h.x), c - __bfloat162float(h.y));
        *(uint32_t*)(&gVthi[obase + (size_t)d * S_ + s]) = b2u(h);
        *(uint32_t*)(&gVtlo[obase + (size_t)d * S_ + s]) = b2u(l);
    }
}

// ---------------------------------------------------------------------------
// fused flash kernel, full-row warps (8 warps x 16 rows), P kept in registers
// ---------------------------------------------------------------------------
__global__ void __launch_bounds__(256, 1)
fused_attn_kernel(const float* __restrict__ scale_ptr, float* __restrict__ out)
{
    extern __shared__ char smc[];
    const uint32_t sb = smem_to_u32(smc);

    const int tid = threadIdx.x, lane = tid & 31, wid = tid >> 5;
    const int wrow = wid * 16;                      // warp's 16-row slab
    const int qt = blockIdx.x, h = blockIdx.y, b = blockIdx.z;
    const int kvh = h >> 2, q0 = qt * TT;
    const int bh = b * H_ + h;
    const float inv_scale = 1.0f / scale_ptr[0];

    const size_t qbase = ((size_t)bh * S_ + q0) * D_;
    const size_t kbase = ((size_t)(b * KVH_ + kvh)) * S_ * D_;
    const size_t vbase = ((size_t)(b * KVH_ + kvh)) * D_ * S_;
    float* Pbase = out + OUT_P + ((size_t)bh * S_ + q0) * S_;
    float* Obase = out + ((size_t)bh * S_ + q0) * D_;

    // stage Q hi/lo tiles (once, direct)
#pragma unroll
    for (int it = 0; it < 16; it++) {
        int idx = it * 256 + tid;
        int arr = idx >> 11, rem = idx & 2047;
        int r = rem >> 4, c = (rem & 15) * 8;
        const __nv_bfloat16* src = (arr ? gQlo : gQhi) + qbase + (size_t)r * D_ + c;
        *(uint4*)(smc + (arr ? Q_LO : Q_HI) + toff(r, c)) = *(const uint4*)src;
    }

    // prefetch K tile 0 (group), Vt tile 0 (group)
#pragma unroll
    for (int it = 0; it < 16; it++) {
        int idx = it * 256 + tid;
        int arr = idx >> 11, rem = idx & 2047;
        int r = rem >> 4, c = (rem & 15) * 8;
        const __nv_bfloat16* src = (arr ? gKlo : gKhi) + kbase + (size_t)r * D_ + c;
        CP_ASYNC16(sb + (arr ? KP_LO : KP_HI) + toff(r, c), src);
    }
    CP_COMMIT();
#pragma unroll
    for (int it = 0; it < 16; it++) {
        int idx = it * 256 + tid;
        int arr = idx >> 11, rem = idx & 2047;
        int r = rem >> 4, c = (rem & 15) * 8;
        const __nv_bfloat16* src = (arr ? gVtlo : gVthi) + vbase + (size_t)r * S_ + c;
        CP_ASYNC16(sb + (arr ? VT_LO : VT_HI) + toff(r, c), src);
    }
    CP_COMMIT();

    float m_run[2], l_run[2];
#pragma unroll
    for (int i = 0; i < 2; i++) { m_run[i] = -3.0e38f; l_run[i] = 0.0f; }

    float acc_o[16][4];
#pragma unroll
    for (int nt = 0; nt < 16; nt++)
#pragma unroll
        for (int k = 0; k < 4; k++) acc_o[nt][k] = 0.0f;

    // ================= pass A: online softmax + O accumulation ==============
    for (int kt = 0; kt <= qt; kt++) {
        const int k0 = kt * TT;
        CP_WAIT1();         // K(kt) ready (V may still be in flight)
        __syncthreads();

        // ---- QK MMA ----
        float acc[16][4];
#pragma unroll
        for (int nt = 0; nt < 16; nt++)
#pragma unroll
            for (int k = 0; k < 4; k++) acc[nt][k] = 0.0f;

#pragma unroll
        for (int ks = 0; ks < 8; ks++) {
            uint32_t ah[4], al[4];
            {
                int r = wrow + (lane & 15);
                int cc = ks * 16 + (lane >> 4) * 8;
                uint32_t o = toff(r, cc);
                LDSM_X4(ah[0], ah[1], ah[2], ah[3], sb + Q_HI + o);
                LDSM_X4(al[0], al[1], al[2], al[3], sb + Q_LO + o);
            }
#pragma unroll
            for (int np = 0; np < 8; np++) {
                uint32_t bh2[2][2], bl2[2][2];
                int r = np * 16 + ((lane >> 4) << 3) + (lane & 7);
                int cc = ks * 16 + ((lane >> 3) & 1) * 8;
                uint32_t o = toff(r, cc);
                LDSM_X4(bh2[0][0], bh2[0][1], bh2[1][0], bh2[1][1], sb + KP_HI + o);
                LDSM_X4(bl2[0][0], bl2[0][1], bl2[1][0], bl2[1][1], sb + KP_LO + o);
#pragma unroll
                for (int t = 0; t < 2; t++) {
                    mma16816(acc[2 * np + t], ah, bh2[t]);
                    mma16816(acc[2 * np + t], al, bh2[t]);
                    mma16816(acc[2 * np + t], ah, bl2[t]);
                }
            }
        }
        __syncthreads();   // KP consumed by all warps

        // issue K(kt+1) early -> overlaps epilogue + PV
        if (kt < qt) {
#pragma unroll
            for (int it = 0; it < 16; it++) {
                int idx = it * 256 + tid;
                int arr = idx >> 11, rem = idx & 2047;
                int r = rem >> 4, c = (rem & 15) * 8;
                const __nv_bfloat16* src =
                    (arr ? gKlo : gKhi) + kbase + (size_t)(k0 + TT + r) * D_ + c;
                CP_ASYNC16(sb + (arr ? KP_LO : KP_HI) + toff(r, c), src);
            }
            CP_COMMIT();
        }

        // ---- epilogue: warp-local full-row stats, p~ -> packed registers ----
        const bool diag = (kt == qt);
        uint32_t php[16][2], plp[16][2];
#pragma unroll
        for (int hh = 0; hh < 2; hh++) {
            const int row_l = wrow + (lane >> 2) + hh * 8;
            float rmax = -3.0e38f;
#pragma unroll
            for (int nt = 0; nt < 16; nt++) {
                float v0 = acc[nt][hh * 2]     * inv_scale;
                float v1 = acc[nt][hh * 2 + 1] * inv_scale;
                if (diag) {
                    int colb = nt * 8 + (lane & 3) * 2;
                    if (colb > row_l)     v0 = -3.0e38f;
                    if (colb + 1 > row_l) v1 = -3.0e38f;
                }
                rmax = fmaxf(rmax, fmaxf(v0, v1));
            }
            rmax = fmaxf(rmax, __shfl_xor_sync(0xffffffffu, rmax, 1));
            rmax = fmaxf(rmax, __shfl_xor_sync(0xffffffffu, rmax, 2));
            const float newm = fmaxf(m_run[hh], rmax);
            const float corr = __expf(m_run[hh] - newm);
            float se = 0.0f;
#pragma unroll
            for (int nt = 0; nt < 16; nt++) {
                float v0 = acc[nt][hh * 2]     * inv_scale;
                float v1 = acc[nt][hh * 2 + 1] * inv_scale;
                if (diag) {
                    int colb = nt * 8 + (lane & 3) * 2;
                    if (colb > row_l)     v0 = -3.0e38f;
                    if (colb + 1 > row_l) v1 = -3.0e38f;
                }
                float p0 = __expf(v0 - newm);
                float p1 = __expf(v1 - newm);
                se += p0 + p1;
                acc_o[nt][hh * 2]     *= corr;
                acc_o[nt][hh * 2 + 1] *= corr;
                __nv_bfloat162 hi2 = __floats2bfloat162_rn(p0, p1);
                __nv_bfloat162 lo2 = __floats2bfloat162_rn(p0 - __bfloat162float(hi2.x),
                                                           p1 - __bfloat162float(hi2.y));
                php[nt][hh] = b2u(hi2);
                plp[nt][hh] = b2u(lo2);
            }
            se += __shfl_xor_sync(0xffffffffu, se, 1);
            se += __shfl_xor_sync(0xffffffffu, se, 2);
            l_run[hh] = l_run[hh] * corr + se;
            m_run[hh] = newm;
        }

        if (kt < qt) CP_WAIT1(); else CP_WAIT0();   // V(kt) ready
        __syncthreads();

        // ---- PV MMA: A from registers ----
#pragma unroll
        for (int ks = 0; ks < 8; ks++) {
            uint32_t aph[4] = {php[2 * ks][0], php[2 * ks][1],
                               php[2 * ks + 1][0], php[2 * ks + 1][1]};
            uint32_t apl[4] = {plp[2 * ks][0], plp[2 * ks][1],
                               plp[2 * ks + 1][0], plp[2 * ks + 1][1]};
#pragma unroll
            for (int np = 0; np < 8; np++) {
                uint32_t bh2[2][2], bl2[2][2];
                int r = np * 16 + ((lane >> 4) << 3) + (lane & 7);
                int cc = ks * 16 + ((lane >> 3) & 1) * 8;
                uint32_t o = toff(r, cc);
                LDSM_X4(bh2[0][0], bh2[0][1], bh2[1][0], bh2[1][1], sb + VT_HI + o);
                LDSM_X4(bl2[0][0], bl2[0][1], bl2[1][0], bl2[1][1], sb + VT_LO + o);
#pragma unroll
                for (int t = 0; t < 2; t++) {
                    mma16816(acc_o[2 * np + t], aph, bh2[t]);
                    mma16816(acc_o[2 * np + t], apl, bh2[t]);
                    mma16816(acc_o[2 * np + t], aph, bl2[t]);
                }
            }
        }
        __syncthreads();   // VT consumed

        if (kt < qt) {
#pragma unroll
            for (int it = 0; it < 16; it++) {
                int idx = it * 256 + tid;
                int arr = idx >> 11, rem = idx & 2047;
                int r = rem >> 4, c = (rem & 15) * 8;
                const __nv_bfloat16* src =
                    (arr ? gVtlo : gVthi) + vbase + (size_t)r * S_ + k0 + TT + c;
                CP_ASYNC16(sb + (arr ? VT_LO : VT_HI) + toff(r, c), src);
            }
            CP_COMMIT();
        }
    }

    const float linv[2] = {1.0f / l_run[0], 1.0f / l_run[1]};

    // prefetch K tile 0 for pass B into KP
#pragma unroll
    for (int it = 0; it < 16; it++) {
        int idx = it * 256 + tid;
        int arr = idx >> 11, rem = idx & 2047;
        int r = rem >> 4, c = (rem & 15) * 8;
        const __nv_bfloat16* src = (arr ? gKlo : gKhi) + kbase + (size_t)r * D_ + c;
        CP_ASYNC16(sb + KP_HI + (arr ? 32768 : 0) + toff(r, c), src);
    }
    CP_COMMIT();

    // ---- O epilogue (overlaps with pass-B prefetch) ----
#pragma unroll
    for (int hh = 0; hh < 2; hh++) {
        const int row_l = wrow + (lane >> 2) + hh * 8;
        float* orow = Obase + (size_t)row_l * D_ + (lane & 3) * 2;
#pragma unroll
        for (int nt = 0; nt < 16; nt++)
            STG_CS_F2(orow + nt * 8,
                      acc_o[nt][hh * 2] * linv[hh], acc_o[nt][hh * 2 + 1] * linv[hh]);
    }

    // ================= pass B: recompute QK, write final weights ============
    for (int kt = 0; kt <= qt; kt++) {
        const int k0 = kt * TT;
        CP_WAIT0();
        __syncthreads();
        const uint32_t Tb = (kt & 1) ? VT_HI : KP_HI;
        if (kt < qt) {
            const uint32_t nb = ((kt + 1) & 1) ? VT_HI : KP_HI;
#pragma unroll
            for (int it = 0; it < 16; it++) {
                int idx = it * 256 + tid;
                int arr = idx >> 11, rem = idx & 2047;
                int r = rem >> 4, c = (rem & 15) * 8;
                const __nv_bfloat16* src =
                    (arr ? gKlo : gKhi) + kbase + (size_t)(k0 + TT + r) * D_ + c;
                CP_ASYNC16(sb + nb + (arr ? 32768 : 0) + toff(r, c), src);
            }
            CP_COMMIT();
        }

        float acc[16][4];
#pragma unroll
        for (int nt = 0; nt < 16; nt++)
#pragma unroll
            for (int k = 0; k < 4; k++) acc[nt][k] = 0.0f;

#pragma unroll
        for (int ks = 0; ks < 8; ks++) {
            uint32_t ah[4], al[4];
            {
                int r = wrow + (lane & 15);
                int cc = ks * 16 + (lane >> 4) * 8;
                uint32_t o = toff(r, cc);
                LDSM_X4(ah[0], ah[1], ah[2], ah[3], sb + Q_HI + o);
                LDSM_X4(al[0], al[1], al[2], al[3], sb + Q_LO + o);
            }
#pragma unroll
            for (int np = 0; np < 8; np++) {
                uint32_t bh2[2][2], bl2[2][2];
                int r = np * 16 + ((lane >> 4) << 3) + (lane & 7);
                int cc = ks * 16 + ((lane >> 3) & 1) * 8;
                uint32_t o = toff(r, cc);
                LDSM_X4(bh2[0][0], bh2[0][1], bh2[1][0], bh2[1][1], sb + Tb + o);
                LDSM_X4(bl2[0][0], bl2[0][1], bl2[1][0], bl2[1][1], sb + Tb + 32768 + o);
#pragma unroll
                for (int t = 0; t < 2; t++) {
                    mma16816(acc[2 * np + t], ah, bh2[t]);
                    mma16816(acc[2 * np + t], al, bh2[t]);
                    mma16816(acc[2 * np + t], ah, bl2[t]);
                }
            }
        }

        // finalize + store (streaming); stats straight from registers
        const bool diag = (kt == qt);
#pragma unroll
        for (int hh = 0; hh < 2; hh++) {
            const int row_l = wrow + (lane >> 2) + hh * 8;
            const float mfin = m_run[hh];
            const float li = linv[hh];
            float* prow = Pbase + (size_t)row_l * S_ + k0 + (lane & 3) * 2;
#pragma unroll
            for (int nt = 0; nt < 16; nt++) {
                float v0 = acc[nt][hh * 2]     * inv_scale;
                float v1 = acc[nt][hh * 2 + 1] * inv_scale;
                if (diag) {
                    int colb = nt * 8 + (lane & 3) * 2;
                    if (colb > row_l)     v0 = -3.0e38f;
                    if (colb + 1 > row_l) v1 = -3.0e38f;
                }
                STG_CS_F2(prow + nt * 8, __expf(v0 - mfin) * li, __expf(v1 - mfin) * li);
            }
        }
    }

    // ---- zero-fill causal upper triangle (streaming) ----
    const int zbase = (qt + 1) * TT;
    const int zc4 = (S_ - zbase) >> 2;
    if (zc4 > 0) {
        const float4 z4 = make_float4(0.f, 0.f, 0.f, 0.f);
        for (int r = 0; r < TT; r++) {
            float* prow = Pbase + (size_t)r * S_ + zbase;
            for (int c4 = tid; c4 < zc4; c4 += 256)
                STG_CS_F4(prow + (c4 << 2), z4);
        }
    }
}

// ---------------------------------------------------------------------------
// present = (key copy, value permute)
// ---------------------------------------------------------------------------
__global__ void copy_kv_kernel(const float* __restrict__ K, const float* __restrict__ Vv,
                               float* __restrict__ out)
{
    const int i = blockIdx.x * 256 + threadIdx.x;
    if (i < 1048576) {
        float4 v = ((const float4*)K)[i];
        STG_CS_F4((float*)(out + OUT_K) + ((size_t)i << 2), v);
    } else {
        const int j = i - 1048576;
        const int row = j >> 5;
        const int d4 = (j & 31) << 2;
        const int b = row >> 14;
        const int kvh = (row >> 11) & 7;
        const int s = row & 2047;
        const float4 v = *(const float4*)(Vv + ((((size_t)b * S_ + s) * KVH_ + kvh) << 7) + d4);
        STG_CS_F4(out + OUT_V + ((size_t)row << 7) + d4, v);
    }
}

extern "C" void kernel_launch(void* const* d_in, const int* in_sizes, int n_in,
                              void* d_out, int out_size)
{
    (void)in_sizes; (void)n_in; (void)out_size;
    const float* Q     = (const float*)d_in[0];
    const float* K     = (const float*)d_in[1];
    const float* V     = (const float*)d_in[2];
    const float* scale = (const float*)d_in[4];
    float* out = (float*)d_out;

    cudaFuncSetAttribute(fused_attn_kernel, cudaFuncAttributeMaxDynamicSharedMemorySize, SMEM_SZ);

    cvtQ_kernel<<<16384, 256>>>(Q);
    cvtK_kernel<<<4096, 256>>>(K);
    cvtV_kernel<<<dim3(16, 4, 16), 256>>>(V);
    copy_kv_kernel<<<8192, 256>>>(K, V, out);

    dim3 grid(S_ / TT, H_, B_);
    fused_attn_kernel<<<grid, 256, SMEM_SZ>>>(scale, out);
}

// round 10
// speedup vs baseline: 3.9161x; 1.4884x over previous
#include <cuda_runtime.h>
#include <cuda_fp16.h>
#include <cstdint>

#define B_   2
#define H_   32
#define KVH_ 8
#define S_   2048
#define D_   128
#define TT   128

static const size_t OUT_P = (size_t)B_ * H_ * S_ * D_;            // attn_output end
static const size_t OUT_K = OUT_P + (size_t)B_ * H_ * S_ * S_;    // attn_weights end
static const size_t OUT_V = OUT_K + (size_t)B_ * KVH_ * S_ * D_;

// -------- scratch (__device__ BSS, no allocation) --------
__device__ __half gQhi[(size_t)B_ * H_ * S_ * D_];
__device__ __half gQlo[(size_t)B_ * H_ * S_ * D_];
__device__ __half gK  [(size_t)B_ * KVH_ * S_ * D_];
__device__ __half gVt [(size_t)B_ * KVH_ * D_ * S_];   // [b][kvh][d][s]

__device__ __forceinline__ uint32_t smem_to_u32(const void* p) {
    uint32_t a;
    asm("{ .reg .u64 t; cvta.to.shared.u64 t, %1; cvt.u32.u64 %0, t; }" : "=r"(a) : "l"(p));
    return a;
}
__device__ __forceinline__ uint32_t h2u(__half2 x) { return *reinterpret_cast<uint32_t*>(&x); }

// byte offset inside a [128 x 128 half] tile, 256B rows, 16B-granule XOR swizzle
__device__ __forceinline__ uint32_t toff(int r, int c) {
    return (uint32_t)(r * 256 + ((((c >> 3) ^ (r & 7)) & 15) << 4) + (c & 7) * 2);
}

#define LDSM_X4(d0, d1, d2, d3, a) \
    asm volatile("ldmatrix.sync.aligned.m8n8.x4.shared.b16 {%0,%1,%2,%3}, [%4];" \
                 : "=r"(d0), "=r"(d1), "=r"(d2), "=r"(d3) : "r"(a))

__device__ __forceinline__ void mma16816(float* c, const uint32_t* a, const uint32_t* b) {
    asm volatile(
        "mma.sync.aligned.m16n8k16.row.col.f32.f16.f16.f32 "
        "{%0,%1,%2,%3}, {%4,%5,%6,%7}, {%8,%9}, {%0,%1,%2,%3};"
        : "+f"(c[0]), "+f"(c[1]), "+f"(c[2]), "+f"(c[3])
        : "r"(a[0]), "r"(a[1]), "r"(a[2]), "r"(a[3]), "r"(b[0]), "r"(b[1]));
}

#define CP_ASYNC16(dst, src) \
    asm volatile("cp.async.cg.shared.global [%0], [%1], 16;" :: "r"(dst), "l"(src))
#define CP_COMMIT() asm volatile("cp.async.commit_group;")
#define CP_WAIT0()  asm volatile("cp.async.wait_group 0;")

// streaming (evict-first) stores
#define STG_CS_F2(p, a, b) \
    asm volatile("st.global.cs.v2.f32 [%0], {%1,%2};" :: "l"(p), "f"(a), "f"(b))
#define STG_CS_F4(p, v) \
    asm volatile("st.global.cs.v4.f32 [%0], {%1,%2,%3,%4};" \
                 :: "l"(p), "f"((v).x), "f"((v).y), "f"((v).z), "f"((v).w))

// smem layout (byte offsets): Q hi/lo fixed, K + V double-buffered
#define Q_HI   0
#define Q_LO   32768
#define KB0    65536
#define KB1    98304
#define VB0    131072
#define VB1    163840
#define SMEM_SZ 196608

// ---------------------------------------------------------------------------
// conversion kernels
// ---------------------------------------------------------------------------
__global__ void cvtQ_kernel(const float* __restrict__ Q) {
    size_t i = (size_t)blockIdx.x * 256 + threadIdx.x;  // float4 index
    float4 v = ((const float4*)Q)[i];
    __half2 h01 = __floats2half2_rn(v.x, v.y);
    __half2 h23 = __floats2half2_rn(v.z, v.w);
    __half2 l01 = __floats2half2_rn(v.x - __half2float(h01.x), v.y - __half2float(h01.y));
    __half2 l23 = __floats2half2_rn(v.z - __half2float(h23.x), v.w - __half2float(h23.y));
    ((uint2*)gQhi)[i] = make_uint2(h2u(h01), h2u(h23));
    ((uint2*)gQlo)[i] = make_uint2(h2u(l01), h2u(l23));
}
__global__ void cvtK_kernel(const float* __restrict__ K) {
    size_t i = (size_t)blockIdx.x * 256 + threadIdx.x;
    float4 v = ((const float4*)K)[i];
    __half2 h01 = __floats2half2_rn(v.x, v.y);
    __half2 h23 = __floats2half2_rn(v.z, v.w);
    ((uint2*)gK)[i] = make_uint2(h2u(h01), h2u(h23));
}
// V [b,s,kvh,d] fp32 -> Vt [b,kvh,d,s] fp16 (smem tile transpose)
__global__ void cvtV_kernel(const float* __restrict__ V) {
    __shared__ float sm[32][129];
    const int bk = blockIdx.z, b = bk >> 3, kvh = bk & 7;
    const int s0 = blockIdx.x * 128, d0 = blockIdx.y * 32;
    const int tid = threadIdx.x;
#pragma unroll
    for (int it = 0; it < 4; it++) {
        int idx = it * 256 + tid;
        int s = idx >> 3, d4 = (idx & 7) * 4;
        float4 v = *(const float4*)(V + ((((size_t)b * S_ + s0 + s) * KVH_ + kvh) * D_) + d0 + d4);
        sm[d4 + 0][s] = v.x; sm[d4 + 1][s] = v.y; sm[d4 + 2][s] = v.z; sm[d4 + 3][s] = v.w;
    }
    __syncthreads();
    const size_t obase = ((size_t)(b * KVH_ + kvh) * D_ + d0) * S_ + s0;
#pragma unroll
    for (int it = 0; it < 8; it++) {
        int idx = it * 256 + tid;
        int d = idx >> 6, j = idx & 63, s = 2 * j;
        __half2 h = __floats2half2_rn(sm[d][s], sm[d][s + 1]);
        *(uint32_t*)(&gVt[obase + (size_t)d * S_ + s]) = h2u(h);
    }
}

// ---------------------------------------------------------------------------
// fused flash kernel, full-row warps, fp16 split: QK 2-combo, PV 1-combo
// ---------------------------------------------------------------------------
__global__ void __launch_bounds__(256, 1)
fused_attn_kernel(const float* __restrict__ scale_ptr, float* __restrict__ out)
{
    extern __shared__ char smc[];
    const uint32_t sb = smem_to_u32(smc);

    const int tid = threadIdx.x, lane = tid & 31, wid = tid >> 5;
    const int wrow = wid * 16;                      // warp's 16-row slab
    const int qt = blockIdx.x, h = blockIdx.y, b = blockIdx.z;
    const int kvh = h >> 2, q0 = qt * TT;
    const int bh = b * H_ + h;
    const float inv_scale = 1.0f / scale_ptr[0];

    const size_t qbase = ((size_t)bh * S_ + q0) * D_;
    const size_t kbase = ((size_t)(b * KVH_ + kvh)) * S_ * D_;
    const size_t vbase = ((size_t)(b * KVH_ + kvh)) * D_ * S_;
    float* Pbase = out + OUT_P + ((size_t)bh * S_ + q0) * S_;
    float* Obase = out + ((size_t)bh * S_ + q0) * D_;

    // stage Q hi/lo tiles (once, direct)
#pragma unroll
    for (int it = 0; it < 16; it++) {
        int idx = it * 256 + tid;
        int arr = idx >> 11, rem = idx & 2047;
        int r = rem >> 4, c = (rem & 15) * 8;
        const __half* src = (arr ? gQlo : gQhi) + qbase + (size_t)r * D_ + c;
        *(uint4*)(smc + (arr ? Q_LO : Q_HI) + toff(r, c)) = *(const uint4*)src;
    }

    // prefetch K(0) -> KB0 and V(0) -> VB0 as ONE group
#pragma unroll
    for (int it = 0; it < 8; it++) {
        int idx = it * 256 + tid;
        int r = idx >> 4, c = (idx & 15) * 8;
        CP_ASYNC16(sb + KB0 + toff(r, c), gK + kbase + (size_t)r * D_ + c);
    }
#pragma unroll
    for (int it = 0; it < 8; it++) {
        int idx = it * 256 + tid;
        int r = idx >> 4, c = (idx & 15) * 8;
        CP_ASYNC16(sb + VB0 + toff(r, c), gVt + vbase + (size_t)r * S_ + c);
    }
    CP_COMMIT();

    float m_run[2], l_run[2];
#pragma unroll
    for (int i = 0; i < 2; i++) { m_run[i] = -3.0e38f; l_run[i] = 0.0f; }

    float acc_o[16][4];
#pragma unroll
    for (int nt = 0; nt < 16; nt++)
#pragma unroll
        for (int k = 0; k < 4; k++) acc_o[nt][k] = 0.0f;

    // ================= pass A: online softmax + O accumulation ==============
    for (int kt = 0; kt <= qt; kt++) {
        const int k0 = kt * TT;
        CP_WAIT0();
        __syncthreads();   // tile (kt) data visible; all warps past tile kt-1
        const uint32_t KB = (kt & 1) ? KB1 : KB0;
        const uint32_t VB = (kt & 1) ? VB1 : VB0;

        // prefetch tile kt+1 into the other buffers (overlaps whole tile)
        if (kt < qt) {
            const uint32_t nKB = (kt & 1) ? KB0 : KB1;
            const uint32_t nVB = (kt & 1) ? VB0 : VB1;
#pragma unroll
            for (int it = 0; it < 8; it++) {
                int idx = it * 256 + tid;
                int r = idx >> 4, c = (idx & 15) * 8;
                CP_ASYNC16(sb + nKB + toff(r, c),
                           gK + kbase + (size_t)(k0 + TT + r) * D_ + c);
            }
#pragma unroll
            for (int it = 0; it < 8; it++) {
                int idx = it * 256 + tid;
                int r = idx >> 4, c = (idx & 15) * 8;
                CP_ASYNC16(sb + nVB + toff(r, c),
                           gVt + vbase + (size_t)r * S_ + k0 + TT + c);
            }
            CP_COMMIT();
        }

        // ---- QK MMA (2 combos) ----
        float acc[16][4];
#pragma unroll
        for (int nt = 0; nt < 16; nt++)
#pragma unroll
            for (int k = 0; k < 4; k++) acc[nt][k] = 0.0f;

#pragma unroll
        for (int ks = 0; ks < 8; ks++) {
            uint32_t ah[4], al[4];
            {
                int r = wrow + (lane & 15);
                int cc = ks * 16 + (lane >> 4) * 8;
                uint32_t o = toff(r, cc);
                LDSM_X4(ah[0], ah[1], ah[2], ah[3], sb + Q_HI + o);
                LDSM_X4(al[0], al[1], al[2], al[3], sb + Q_LO + o);
            }
#pragma unroll
            for (int np = 0; np < 8; np++) {
                uint32_t bb[2][2];
                int r = np * 16 + ((lane >> 4) << 3) + (lane & 7);
                int cc = ks * 16 + ((lane >> 3) & 1) * 8;
                uint32_t o = toff(r, cc);
                LDSM_X4(bb[0][0], bb[0][1], bb[1][0], bb[1][1], sb + KB + o);
#pragma unroll
                for (int t = 0; t < 2; t++) {
                    mma16816(acc[2 * np + t], ah, bb[t]);
                    mma16816(acc[2 * np + t], al, bb[t]);
                }
            }
        }

        // ---- epilogue: warp-local full-row stats, p~ -> fp16 registers ----
        const bool diag = (kt == qt);
        uint32_t php[16][2];
#pragma unroll
        for (int hh = 0; hh < 2; hh++) {
            const int row_l = wrow + (lane >> 2) + hh * 8;
            float rmax = -3.0e38f;
#pragma unroll
            for (int nt = 0; nt < 16; nt++) {
                float v0 = acc[nt][hh * 2]     * inv_scale;
                float v1 = acc[nt][hh * 2 + 1] * inv_scale;
                if (diag) {
                    int colb = nt * 8 + (lane & 3) * 2;
                    if (colb > row_l)     v0 = -3.0e38f;
                    if (colb + 1 > row_l) v1 = -3.0e38f;
                }
                rmax = fmaxf(rmax, fmaxf(v0, v1));
            }
            rmax = fmaxf(rmax, __shfl_xor_sync(0xffffffffu, rmax, 1));
            rmax = fmaxf(rmax, __shfl_xor_sync(0xffffffffu, rmax, 2));
            const float newm = fmaxf(m_run[hh], rmax);
            const float corr = __expf(m_run[hh] - newm);
            float se = 0.0f;
#pragma unroll
            for (int nt = 0; nt < 16; nt++) {
                float v0 = acc[nt][hh * 2]     * inv_scale;
                float v1 = acc[nt][hh * 2 + 1] * inv_scale;
                if (diag) {
                    int colb = nt * 8 + (lane & 3) * 2;
                    if (colb > row_l)     v0 = -3.0e38f;
                    if (colb + 1 > row_l) v1 = -3.0e38f;
                }
                float p0 = __expf(v0 - newm);
                float p1 = __expf(v1 - newm);
                se += p0 + p1;
                acc_o[nt][hh * 2]     *= corr;
                acc_o[nt][hh * 2 + 1] *= corr;
                php[nt][hh] = h2u(__floats2half2_rn(p0, p1));
            }
            se += __shfl_xor_sync(0xffffffffu, se, 1);
            se += __shfl_xor_sync(0xffffffffu, se, 2);
            l_run[hh] = l_run[hh] * corr + se;
            m_run[hh] = newm;
        }

        // ---- PV MMA (1 combo), A from registers ----
#pragma unroll
        for (int ks = 0; ks < 8; ks++) {
            uint32_t aph[4] = {php[2 * ks][0], php[2 * ks][1],
                               php[2 * ks + 1][0], php[2 * ks + 1][1]};
#pragma unroll
            for (int np = 0; np < 8; np++) {
                uint32_t bb[2][2];
                int r = np * 16 + ((lane >> 4) << 3) + (lane & 7);
                int cc = ks * 16 + ((lane >> 3) & 1) * 8;
                uint32_t o = toff(r, cc);
                LDSM_X4(bb[0][0], bb[0][1], bb[1][0], bb[1][1], sb + VB + o);
#pragma unroll
                for (int t = 0; t < 2; t++)
                    mma16816(acc_o[2 * np + t], aph, bb[t]);
            }
        }
    }

    const float linv[2] = {1.0f / l_run[0], 1.0f / l_run[1]};

    __syncthreads();   // all warps done reading pass-A buffers

    // prefetch K(0) for pass B -> KB0
#pragma unroll
    for (int it = 0; it < 8; it++) {
        int idx = it * 256 + tid;
        int r = idx >> 4, c = (idx & 15) * 8;
        CP_ASYNC16(sb + KB0 + toff(r, c), gK + kbase + (size_t)r * D_ + c);
    }
    CP_COMMIT();

    // ---- O epilogue (overlaps pass-B prefetch) ----
#pragma unroll
    for (int hh = 0; hh < 2; hh++) {
        const int row_l = wrow + (lane >> 2) + hh * 8;
        float* orow = Obase + (size_t)row_l * D_ + (lane & 3) * 2;
#pragma unroll
        for (int nt = 0; nt < 16; nt++)
            STG_CS_F2(orow + nt * 8,
                      acc_o[nt][hh * 2] * linv[hh], acc_o[nt][hh * 2 + 1] * linv[hh]);
    }

    // ================= pass B: recompute QK, write final weights ============
    for (int kt = 0; kt <= qt; kt++) {
        const int k0 = kt * TT;
        CP_WAIT0();
        __syncthreads();
        const uint32_t KB = (kt & 1) ? KB1 : KB0;
        if (kt < qt) {
            const uint32_t nKB = (kt & 1) ? KB0 : KB1;
#pragma unroll
            for (int it = 0; it < 8; it++) {
                int idx = it * 256 + tid;
                int r = idx >> 4, c = (idx & 15) * 8;
                CP_ASYNC16(sb + nKB + toff(r, c),
                           gK + kbase + (size_t)(k0 + TT + r) * D_ + c);
            }
            CP_COMMIT();
        }

        float acc[16][4];
#pragma unroll
        for (int nt = 0; nt < 16; nt++)
#pragma unroll
            for (int k = 0; k < 4; k++) acc[nt][k] = 0.0f;

#pragma unroll
        for (int ks = 0; ks < 8; ks++) {
            uint32_t ah[4], al[4];
            {
                int r = wrow + (lane & 15);
                int cc = ks * 16 + (lane >> 4) * 8;
                uint32_t o = toff(r, cc);
                LDSM_X4(ah[0], ah[1], ah[2], ah[3], sb + Q_HI + o);
                LDSM_X4(al[0], al[1], al[2], al[3], sb + Q_LO + o);
            }
#pragma unroll
            for (int np = 0; np < 8; np++) {
                uint32_t bb[2][2];
                int r = np * 16 + ((lane >> 4) << 3) + (lane & 7);
                int cc = ks * 16 + ((lane >> 3) & 1) * 8;
                uint32_t o = toff(r, cc);
                LDSM_X4(bb[0][0], bb[0][1], bb[1][0], bb[1][1], sb + KB + o);
#pragma unroll
                for (int t = 0; t < 2; t++) {
                    mma16816(acc[2 * np + t], ah, bb[t]);
                    mma16816(acc[2 * np + t], al, bb[t]);
                }
            }
        }

        // finalize + store (streaming); stats from registers
        const bool diag = (kt == qt);
#pragma unroll
        for (int hh = 0; hh < 2; hh++) {
            const int row_l = wrow + (lane >> 2) + hh * 8;
            const float mfin = m_run[hh];
            const float li = linv[hh];
            float* prow = Pbase + (size_t)row_l * S_ + k0 + (lane & 3) * 2;
#pragma unroll
            for (int nt = 0; nt < 16; nt++) {
                float v0 = acc[nt][hh * 2]     * inv_scale;
                float v1 = acc[nt][hh * 2 + 1] * inv_scale;
                if (diag) {
                    int colb = nt * 8 + (lane & 3) * 2;
                    if (colb > row_l)     v0 = -3.0e38f;
                    if (colb + 1 > row_l) v1 = -3.0e38f;
                }
                STG_CS_F2(prow + nt * 8, __expf(v0 - mfin) * li, __expf(v1 - mfin) * li);
            }
        }
    }

    // ---- zero-fill causal upper triangle (streaming) ----
    const int zbase = (qt + 1) * TT;
    const int zc4 = (S_ - zbase) >> 2;
    if (zc4 > 0) {
        const float4 z4 = make_float4(0.f, 0.f, 0.f, 0.f);
        for (int r = 0; r < TT; r++) {
            float* prow = Pbase + (size_t)r * S_ + zbase;
            for (int c4 = tid; c4 < zc4; c4 += 256)
                STG_CS_F4(prow + (c4 << 2), z4);
        }
    }
}

// ---------------------------------------------------------------------------
// present = (key copy, value permute)
// ---------------------------------------------------------------------------
__global__ void copy_kv_kernel(const float* __restrict__ K, const float* __restrict__ Vv,
                               float* __restrict__ out)
{
    const int i = blockIdx.x * 256 + threadIdx.x;
    if (i < 1048576) {
        float4 v = ((const float4*)K)[i];
        STG_CS_F4((float*)(out + OUT_K) + ((size_t)i << 2), v);
    } else {
        const int j = i - 1048576;
        const int row = j >> 5;
        const int d4 = (j & 31) << 2;
        const int b = row >> 14;
        const int kvh = (row >> 11) & 7;
        const int s = row & 2047;
        const float4 v = *(const float4*)(Vv + ((((size_t)b * S_ + s) * KVH_ + kvh) << 7) + d4);
        STG_CS_F4(out + OUT_V + ((size_t)row << 7) + d4, v);
    }
}

extern "C" void kernel_launch(void* const* d_in, const int* in_sizes, int n_in,
                              void* d_out, int out_size)
{
    (void)in_sizes; (void)n_in; (void)out_size;
    const float* Q     = (const float*)d_in[0];
    const float* K     = (const float*)d_in[1];
    const float* V     = (const float*)d_in[2];
    const float* scale = (const float*)d_in[4];
    float* out = (float*)d_out;

    cudaFuncSetAttribute(fused_attn_kernel, cudaFuncAttributeMaxDynamicSharedMemorySize, SMEM_SZ);

    cvtQ_kernel<<<16384, 256>>>(Q);
    cvtK_kernel<<<4096, 256>>>(K);
    cvtV_kernel<<<dim3(16, 4, 16), 256>>>(V);
    copy_kv_kernel<<<8192, 256>>>(K, V, out);

    dim3 grid(S_ / TT, H_, B_);
    fused_attn_kernel<<<grid, 256, SMEM_SZ>>>(scale, out);
}

// round 11
// speedup vs baseline: 4.2131x; 1.0758x over previous
#include <cuda_runtime.h>
#include <cuda_fp16.h>
#include <cstdint>

#define B_   2
#define H_   32
#define KVH_ 8
#define S_   2048
#define D_   128
#define TT   128

static const size_t OUT_P = (size_t)B_ * H_ * S_ * D_;            // attn_output end
static const size_t OUT_K = OUT_P + (size_t)B_ * H_ * S_ * S_;    // attn_weights end
static const size_t OUT_V = OUT_K + (size_t)B_ * KVH_ * S_ * D_;

// -------- scratch (__device__ BSS, no allocation) --------
__device__ __half gQhi[(size_t)B_ * H_ * S_ * D_];
__device__ __half gQlo[(size_t)B_ * H_ * S_ * D_];
__device__ __half gK  [(size_t)B_ * KVH_ * S_ * D_];
__device__ __half gVt [(size_t)B_ * KVH_ * D_ * S_];   // [b][kvh][d][s]

__device__ __forceinline__ uint32_t smem_to_u32(const void* p) {
    uint32_t a;
    asm("{ .reg .u64 t; cvta.to.shared.u64 t, %1; cvt.u32.u64 %0, t; }" : "=r"(a) : "l"(p));
    return a;
}
__device__ __forceinline__ uint32_t h2u(__half2 x) { return *reinterpret_cast<uint32_t*>(&x); }

// byte offset inside a [128 x 128 half] tile, 256B rows, 16B-granule XOR swizzle
__device__ __forceinline__ uint32_t toff(int r, int c) {
    return (uint32_t)(r * 256 + ((((c >> 3) ^ (r & 7)) & 15) << 4) + (c & 7) * 2);
}

#define LDSM_X4(d0, d1, d2, d3, a) \
    asm volatile("ldmatrix.sync.aligned.m8n8.x4.shared.b16 {%0,%1,%2,%3}, [%4];" \
                 : "=r"(d0), "=r"(d1), "=r"(d2), "=r"(d3) : "r"(a))

__device__ __forceinline__ void mma16816(float* c, const uint32_t* a, const uint32_t* b) {
    asm volatile(
        "mma.sync.aligned.m16n8k16.row.col.f32.f16.f16.f32 "
        "{%0,%1,%2,%3}, {%4,%5,%6,%7}, {%8,%9}, {%0,%1,%2,%3};"
        : "+f"(c[0]), "+f"(c[1]), "+f"(c[2]), "+f"(c[3])
        : "r"(a[0]), "r"(a[1]), "r"(a[2]), "r"(a[3]), "r"(b[0]), "r"(b[1]));
}

#define CP_ASYNC16(dst, src) \
    asm volatile("cp.async.cg.shared.global [%0], [%1], 16;" :: "r"(dst), "l"(src))
#define CP_COMMIT() asm volatile("cp.async.commit_group;")
#define CP_WAIT0()  asm volatile("cp.async.wait_group 0;")

// streaming (evict-first) stores
#define STG_CS_F2(p, a, b) \
    asm volatile("st.global.cs.v2.f32 [%0], {%1,%2};" :: "l"(p), "f"(a), "f"(b))
#define STG_CS_F4(p, v) \
    asm volatile("st.global.cs.v4.f32 [%0], {%1,%2,%3,%4};" \
                 :: "l"(p), "f"((v).x), "f"((v).y), "f"((v).z), "f"((v).w))

// smem layout (byte offsets): Q hi/lo fixed, K + V double-buffered
#define Q_HI   0
#define Q_LO   32768
#define KB0    65536
#define KB1    98304
#define VB0    131072
#define VB1    163840
#define SMEM_SZ 196608

// ---------------------------------------------------------------------------
// conversion kernels
// ---------------------------------------------------------------------------
__global__ void cvtQ_kernel(const float* __restrict__ Q) {
    size_t i = (size_t)blockIdx.x * 256 + threadIdx.x;  // float4 index
    float4 v = ((const float4*)Q)[i];
    __half2 h01 = __floats2half2_rn(v.x, v.y);
    __half2 h23 = __floats2half2_rn(v.z, v.w);
    __half2 l01 = __floats2half2_rn(v.x - __half2float(h01.x), v.y - __half2float(h01.y));
    __half2 l23 = __floats2half2_rn(v.z - __half2float(h23.x), v.w - __half2float(h23.y));
    ((uint2*)gQhi)[i] = make_uint2(h2u(h01), h2u(h23));
    ((uint2*)gQlo)[i] = make_uint2(h2u(l01), h2u(l23));
}
__global__ void cvtK_kernel(const float* __restrict__ K) {
    size_t i = (size_t)blockIdx.x * 256 + threadIdx.x;
    float4 v = ((const float4*)K)[i];
    __half2 h01 = __floats2half2_rn(v.x, v.y);
    __half2 h23 = __floats2half2_rn(v.z, v.w);
    ((uint2*)gK)[i] = make_uint2(h2u(h01), h2u(h23));
}
// V [b,s,kvh,d] fp32 -> Vt [b,kvh,d,s] fp16 (smem tile transpose)
__global__ void cvtV_kernel(const float* __restrict__ V) {
    __shared__ float sm[32][129];
    const int bk = blockIdx.z, b = bk >> 3, kvh = bk & 7;
    const int s0 = blockIdx.x * 128, d0 = blockIdx.y * 32;
    const int tid = threadIdx.x;
#pragma unroll
    for (int it = 0; it < 4; it++) {
        int idx = it * 256 + tid;
        int s = idx >> 3, d4 = (idx & 7) * 4;
        float4 v = *(const float4*)(V + ((((size_t)b * S_ + s0 + s) * KVH_ + kvh) * D_) + d0 + d4);
        sm[d4 + 0][s] = v.x; sm[d4 + 1][s] = v.y; sm[d4 + 2][s] = v.z; sm[d4 + 3][s] = v.w;
    }
    __syncthreads();
    const size_t obase = ((size_t)(b * KVH_ + kvh) * D_ + d0) * S_ + s0;
#pragma unroll
    for (int it = 0; it < 8; it++) {
        int idx = it * 256 + tid;
        int d = idx >> 6, j = idx & 63, s = 2 * j;
        __half2 h = __floats2half2_rn(sm[d][s], sm[d][s + 1]);
        *(uint32_t*)(&gVt[obase + (size_t)d * S_ + s]) = h2u(h);
    }
}

// ---------------------------------------------------------------------------
// fused flash kernel; each CTA handles the complementary q-tile pair
// {pair, 15-pair} for uniform work. fp16 split: QK-A 2-combo, PV 1-combo,
// QK-B (weights recompute) 1-combo.
// ---------------------------------------------------------------------------
__global__ void __launch_bounds__(256, 1)
fused_attn_kernel(const float* __restrict__ scale_ptr, float* __restrict__ out)
{
    extern __shared__ char smc[];
    const uint32_t sb = smem_to_u32(smc);

    const int tid = threadIdx.x, lane = tid & 31, wid = tid >> 5;
    const int wrow = wid * 16;                      // warp's 16-row slab
    const int pair = blockIdx.x, h = blockIdx.y, b = blockIdx.z;
    const int kvh = h >> 2;
    const int bh = b * H_ + h;
    const float inv_scale = 1.0f / scale_ptr[0];

    const size_t kbase = ((size_t)(b * KVH_ + kvh)) * S_ * D_;
    const size_t vbase = ((size_t)(b * KVH_ + kvh)) * D_ * S_;

    for (int qi = 0; qi < 2; qi++) {
        const int qt = qi ? (15 - pair) : pair;
        const int q0 = qt * TT;
        const size_t qbase = ((size_t)bh * S_ + q0) * D_;
        float* Pbase = out + OUT_P + ((size_t)bh * S_ + q0) * S_;
        float* Obase = out + ((size_t)bh * S_ + q0) * D_;

        // stage Q hi/lo tiles
#pragma unroll
        for (int it = 0; it < 16; it++) {
            int idx = it * 256 + tid;
            int arr = idx >> 11, rem = idx & 2047;
            int r = rem >> 4, c = (rem & 15) * 8;
            const __half* src = (arr ? gQlo : gQhi) + qbase + (size_t)r * D_ + c;
            *(uint4*)(smc + (arr ? Q_LO : Q_HI) + toff(r, c)) = *(const uint4*)src;
        }

        // prefetch K(0) -> KB0 and V(0) -> VB0 as ONE group
#pragma unroll
        for (int it = 0; it < 8; it++) {
            int idx = it * 256 + tid;
            int r = idx >> 4, c = (idx & 15) * 8;
            CP_ASYNC16(sb + KB0 + toff(r, c), gK + kbase + (size_t)r * D_ + c);
        }
#pragma unroll
        for (int it = 0; it < 8; it++) {
            int idx = it * 256 + tid;
            int r = idx >> 4, c = (idx & 15) * 8;
            CP_ASYNC16(sb + VB0 + toff(r, c), gVt + vbase + (size_t)r * S_ + c);
        }
        CP_COMMIT();

        float m_run[2], l_run[2];
#pragma unroll
        for (int i = 0; i < 2; i++) { m_run[i] = -3.0e38f; l_run[i] = 0.0f; }

        float acc_o[16][4];
#pragma unroll
        for (int nt = 0; nt < 16; nt++)
#pragma unroll
            for (int k = 0; k < 4; k++) acc_o[nt][k] = 0.0f;

        // ============== pass A: online softmax + O accumulation =============
        for (int kt = 0; kt <= qt; kt++) {
            const int k0 = kt * TT;
            CP_WAIT0();
            __syncthreads();   // tile (kt) visible; all warps past tile kt-1
            const uint32_t KB = (kt & 1) ? KB1 : KB0;
            const uint32_t VB = (kt & 1) ? VB1 : VB0;

            if (kt < qt) {  // prefetch tile kt+1 (overlaps whole tile)
                const uint32_t nKB = (kt & 1) ? KB0 : KB1;
                const uint32_t nVB = (kt & 1) ? VB0 : VB1;
#pragma unroll
                for (int it = 0; it < 8; it++) {
                    int idx = it * 256 + tid;
                    int r = idx >> 4, c = (idx & 15) * 8;
                    CP_ASYNC16(sb + nKB + toff(r, c),
                               gK + kbase + (size_t)(k0 + TT + r) * D_ + c);
                }
#pragma unroll
                for (int it = 0; it < 8; it++) {
                    int idx = it * 256 + tid;
                    int r = idx >> 4, c = (idx & 15) * 8;
                    CP_ASYNC16(sb + nVB + toff(r, c),
                               gVt + vbase + (size_t)r * S_ + k0 + TT + c);
                }
                CP_COMMIT();
            }

            // ---- QK MMA (2 combos) ----
            float acc[16][4];
#pragma unroll
            for (int nt = 0; nt < 16; nt++)
#pragma unroll
                for (int k = 0; k < 4; k++) acc[nt][k] = 0.0f;

#pragma unroll
            for (int ks = 0; ks < 8; ks++) {
                uint32_t ah[4], al[4];
                {
                    int r = wrow + (lane & 15);
                    int cc = ks * 16 + (lane >> 4) * 8;
                    uint32_t o = toff(r, cc);
                    LDSM_X4(ah[0], ah[1], ah[2], ah[3], sb + Q_HI + o);
                    LDSM_X4(al[0], al[1], al[2], al[3], sb + Q_LO + o);
                }
#pragma unroll
                for (int np = 0; np < 8; np++) {
                    uint32_t bb[2][2];
                    int r = np * 16 + ((lane >> 4) << 3) + (lane & 7);
                    int cc = ks * 16 + ((lane >> 3) & 1) * 8;
                    uint32_t o = toff(r, cc);
                    LDSM_X4(bb[0][0], bb[0][1], bb[1][0], bb[1][1], sb + KB + o);
#pragma unroll
                    for (int t = 0; t < 2; t++) {
                        mma16816(acc[2 * np + t], ah, bb[t]);
                        mma16816(acc[2 * np + t], al, bb[t]);
                    }
                }
            }

            // ---- epilogue: warp-local full-row stats, p~ -> fp16 regs ----
            const bool diag = (kt == qt);
            uint32_t php[16][2];
#pragma unroll
            for (int hh = 0; hh < 2; hh++) {
                const int row_l = wrow + (lane >> 2) + hh * 8;
                float rmax = -3.0e38f;
#pragma unroll
                for (int nt = 0; nt < 16; nt++) {
                    float v0 = acc[nt][hh * 2]     * inv_scale;
                    float v1 = acc[nt][hh * 2 + 1] * inv_scale;
                    if (diag) {
                        int colb = nt * 8 + (lane & 3) * 2;
                        if (colb > row_l)     v0 = -3.0e38f;
                        if (colb + 1 > row_l) v1 = -3.0e38f;
                    }
                    rmax = fmaxf(rmax, fmaxf(v0, v1));
                }
                rmax = fmaxf(rmax, __shfl_xor_sync(0xffffffffu, rmax, 1));
                rmax = fmaxf(rmax, __shfl_xor_sync(0xffffffffu, rmax, 2));
                const float newm = fmaxf(m_run[hh], rmax);
                const float corr = __expf(m_run[hh] - newm);
                float se = 0.0f;
#pragma unroll
                for (int nt = 0; nt < 16; nt++) {
                    float v0 = acc[nt][hh * 2]     * inv_scale;
                    float v1 = acc[nt][hh * 2 + 1] * inv_scale;
                    if (diag) {
                        int colb = nt * 8 + (lane & 3) * 2;
                        if (colb > row_l)     v0 = -3.0e38f;
                        if (colb + 1 > row_l) v1 = -3.0e38f;
                    }
                    float p0 = __expf(v0 - newm);
                    float p1 = __expf(v1 - newm);
                    se += p0 + p1;
                    acc_o[nt][hh * 2]     *= corr;
                    acc_o[nt][hh * 2 + 1] *= corr;
                    php[nt][hh] = h2u(__floats2half2_rn(p0, p1));
                }
                se += __shfl_xor_sync(0xffffffffu, se, 1);
                se += __shfl_xor_sync(0xffffffffu, se, 2);
                l_run[hh] = l_run[hh] * corr + se;
                m_run[hh] = newm;
            }

            // ---- PV MMA (1 combo), A from registers ----
#pragma unroll
            for (int ks = 0; ks < 8; ks++) {
                uint32_t aph[4] = {php[2 * ks][0], php[2 * ks][1],
                                   php[2 * ks + 1][0], php[2 * ks + 1][1]};
#pragma unroll
                for (int np = 0; np < 8; np++) {
                    uint32_t bb[2][2];
                    int r = np * 16 + ((lane >> 4) << 3) + (lane & 7);
                    int cc = ks * 16 + ((lane >> 3) & 1) * 8;
                    uint32_t o = toff(r, cc);
                    LDSM_X4(bb[0][0], bb[0][1], bb[1][0], bb[1][1], sb + VB + o);
#pragma unroll
                    for (int t = 0; t < 2; t++)
                        mma16816(acc_o[2 * np + t], aph, bb[t]);
                }
            }
        }

        const float linv[2] = {1.0f / l_run[0], 1.0f / l_run[1]};

        __syncthreads();   // all warps done reading pass-A buffers

        // prefetch K(0) for pass B -> KB0
#pragma unroll
        for (int it = 0; it < 8; it++) {
            int idx = it * 256 + tid;
            int r = idx >> 4, c = (idx & 15) * 8;
            CP_ASYNC16(sb + KB0 + toff(r, c), gK + kbase + (size_t)r * D_ + c);
        }
        CP_COMMIT();

        // ---- O epilogue (overlaps pass-B prefetch) ----
#pragma unroll
        for (int hh = 0; hh < 2; hh++) {
            const int row_l = wrow + (lane >> 2) + hh * 8;
            float* orow = Obase + (size_t)row_l * D_ + (lane & 3) * 2;
#pragma unroll
            for (int nt = 0; nt < 16; nt++)
                STG_CS_F2(orow + nt * 8,
                          acc_o[nt][hh * 2] * linv[hh], acc_o[nt][hh * 2 + 1] * linv[hh]);
        }

        // ============== pass B: recompute QK (1 combo), final weights ========
        for (int kt = 0; kt <= qt; kt++) {
            const int k0 = kt * TT;
            CP_WAIT0();
            __syncthreads();
            const uint32_t KB = (kt & 1) ? KB1 : KB0;
            if (kt < qt) {
                const uint32_t nKB = (kt & 1) ? KB0 : KB1;
#pragma unroll
                for (int it = 0; it < 8; it++) {
                    int idx = it * 256 + tid;
                    int r = idx >> 4, c = (idx & 15) * 8;
                    CP_ASYNC16(sb + nKB + toff(r, c),
                               gK + kbase + (size_t)(k0 + TT + r) * D_ + c);
                }
                CP_COMMIT();
            }

            float acc[16][4];
#pragma unroll
            for (int nt = 0; nt < 16; nt++)
#pragma unroll
                for (int k = 0; k < 4; k++) acc[nt][k] = 0.0f;

#pragma unroll
            for (int ks = 0; ks < 8; ks++) {
                uint32_t ah[4];
                {
                    int r = wrow + (lane & 15);
                    int cc = ks * 16 + (lane >> 4) * 8;
                    LDSM_X4(ah[0], ah[1], ah[2], ah[3], sb + Q_HI + toff(r, cc));
                }
#pragma unroll
                for (int np = 0; np < 8; np++) {
                    uint32_t bb[2][2];
                    int r = np * 16 + ((lane >> 4) << 3) + (lane & 7);
                    int cc = ks * 16 + ((lane >> 3) & 1) * 8;
                    uint32_t o = toff(r, cc);
                    LDSM_X4(bb[0][0], bb[0][1], bb[1][0], bb[1][1], sb + KB + o);
#pragma unroll
                    for (int t = 0; t < 2; t++)
                        mma16816(acc[2 * np + t], ah, bb[t]);
                }
            }

            // finalize + store (streaming); stats from registers
            const bool diag = (kt == qt);
#pragma unroll
            for (int hh = 0; hh < 2; hh++) {
                const int row_l = wrow + (lane >> 2) + hh * 8;
                const float mfin = m_run[hh];
                const float li = linv[hh];
                float* prow = Pbase + (size_t)row_l * S_ + k0 + (lane & 3) * 2;
#pragma unroll
                for (int nt = 0; nt < 16; nt++) {
                    float v0 = acc[nt][hh * 2]     * inv_scale;
                    float v1 = acc[nt][hh * 2 + 1] * inv_scale;
                    if (diag) {
                        int colb = nt * 8 + (lane & 3) * 2;
                        if (colb > row_l)     v0 = -3.0e38f;
                        if (colb + 1 > row_l) v1 = -3.0e38f;
                    }
                    STG_CS_F2(prow + nt * 8, __expf(v0 - mfin) * li, __expf(v1 - mfin) * li);
                }
            }
        }

        // ---- zero-fill causal upper triangle (streaming) ----
        const int zbase = (qt + 1) * TT;
        const int zc4 = (S_ - zbase) >> 2;
        if (zc4 > 0) {
            const float4 z4 = make_float4(0.f, 0.f, 0.f, 0.f);
            for (int r = 0; r < TT; r++) {
                float* prow = Pbase + (size_t)r * S_ + zbase;
                for (int c4 = tid; c4 < zc4; c4 += 256)
                    STG_CS_F4(prow + (c4 << 2), z4);
            }
        }
        __syncthreads();   // smem safe for next q-tile iteration
    }
}

// ---------------------------------------------------------------------------
// present = (key copy, value permute)
// ---------------------------------------------------------------------------
__global__ void copy_kv_kernel(const float* __restrict__ K, const float* __restrict__ Vv,
                               float* __restrict__ out)
{
    const int i = blockIdx.x * 256 + threadIdx.x;
    if (i < 1048576) {
        float4 v = ((const float4*)K)[i];
        STG_CS_F4((float*)(out + OUT_K) + ((size_t)i << 2), v);
    } else {
        const int j = i - 1048576;
        const int row = j >> 5;
        const int d4 = (j & 31) << 2;
        const int b = row >> 14;
        const int kvh = (row >> 11) & 7;
        const int s = row & 2047;
        const float4 v = *(const float4*)(Vv + ((((size_t)b * S_ + s) * KVH_ + kvh) << 7) + d4);
        STG_CS_F4(out + OUT_V + ((size_t)row << 7) + d4, v);
    }
}

extern "C" void kernel_launch(void* const* d_in, const int* in_sizes, int n_in,
                              void* d_out, int out_size)
{
    (void)in_sizes; (void)n_in; (void)out_size;
    const float* Q     = (const float*)d_in[0];
    const float* K     = (const float*)d_in[1];
    const float* V     = (const float*)d_in[2];
    const float* scale = (const float*)d_in[4];
    float* out = (float*)d_out;

    cudaFuncSetAttribute(fused_attn_kernel, cudaFuncAttributeMaxDynamicSharedMemorySize, SMEM_SZ);

    cvtQ_kernel<<<16384, 256>>>(Q);
    cvtK_kernel<<<4096, 256>>>(K);
    cvtV_kernel<<<dim3(16, 4, 16), 256>>>(V);
    copy_kv_kernel<<<8192, 256>>>(K, V, out);

    dim3 grid(8, H_, B_);
    fused_attn_kernel<<<grid, 256, SMEM_SZ>>>(scale, out);
}

// round 12
// speedup vs baseline: 4.7360x; 1.1241x over previous
#include <cuda_runtime.h>
#include <cuda_fp16.h>
#include <cstdint>

#define B_   2
#define H_   32
#define KVH_ 8
#define S_   2048
#define D_   128
#define TT   128

static const size_t OUT_P = (size_t)B_ * H_ * S_ * D_;            // attn_output end
static const size_t OUT_K = OUT_P + (size_t)B_ * H_ * S_ * S_;    // attn_weights end
static const size_t OUT_V = OUT_K + (size_t)B_ * KVH_ * S_ * D_;

// -------- scratch (__device__ BSS, no allocation) --------
__device__ __half gQ [(size_t)B_ * H_ * S_ * D_];
__device__ __half gK [(size_t)B_ * KVH_ * S_ * D_];
__device__ __half gVt[(size_t)B_ * KVH_ * D_ * S_];   // [b][kvh][d][s]

__device__ __forceinline__ uint32_t smem_to_u32(const void* p) {
    uint32_t a;
    asm("{ .reg .u64 t; cvta.to.shared.u64 t, %1; cvt.u32.u64 %0, t; }" : "=r"(a) : "l"(p));
    return a;
}
__device__ __forceinline__ uint32_t h2u(__half2 x) { return *reinterpret_cast<uint32_t*>(&x); }

// byte offset inside a [128 x 128 half] tile, 256B rows, 16B-granule XOR swizzle
__device__ __forceinline__ uint32_t toff(int r, int c) {
    return (uint32_t)(r * 256 + ((((c >> 3) ^ (r & 7)) & 15) << 4) + (c & 7) * 2);
}

#define LDSM_X4(d0, d1, d2, d3, a) \
    asm volatile("ldmatrix.sync.aligned.m8n8.x4.shared.b16 {%0,%1,%2,%3}, [%4];" \
                 : "=r"(d0), "=r"(d1), "=r"(d2), "=r"(d3) : "r"(a))

__device__ __forceinline__ void mma16816(float* c, const uint32_t* a, const uint32_t* b) {
    asm volatile(
        "mma.sync.aligned.m16n8k16.row.col.f32.f16.f16.f32 "
        "{%0,%1,%2,%3}, {%4,%5,%6,%7}, {%8,%9}, {%0,%1,%2,%3};"
        : "+f"(c[0]), "+f"(c[1]), "+f"(c[2]), "+f"(c[3])
        : "r"(a[0]), "r"(a[1]), "r"(a[2]), "r"(a[3]), "r"(b[0]), "r"(b[1]));
}

#define CP_ASYNC16(dst, src) \
    asm volatile("cp.async.cg.shared.global [%0], [%1], 16;" :: "r"(dst), "l"(src))
#define CP_COMMIT() asm volatile("cp.async.commit_group;")
#define CP_WAIT0()  asm volatile("cp.async.wait_group 0;")

// streaming (evict-first) stores
#define STG_CS_F2(p, a, b) \
    asm volatile("st.global.cs.v2.f32 [%0], {%1,%2};" :: "l"(p), "f"(a), "f"(b))
#define STG_CS_F4(p, v) \
    asm volatile("st.global.cs.v4.f32 [%0], {%1,%2,%3,%4};" \
                 :: "l"(p), "f"((v).x), "f"((v).y), "f"((v).z), "f"((v).w))

// smem layout (byte offsets): Q fixed, K + V double-buffered
#define Q_B    0
#define KB0    32768
#define KB1    65536
#define VB0    98304
#define VB1    131072
#define SMEM_SZ 163840

// ---------------------------------------------------------------------------
// conversion kernels
// ---------------------------------------------------------------------------
__global__ void cvtQ_kernel(const float* __restrict__ Q) {
    size_t i = (size_t)blockIdx.x * 256 + threadIdx.x;  // float4 index
    float4 v = ((const float4*)Q)[i];
    __half2 h01 = __floats2half2_rn(v.x, v.y);
    __half2 h23 = __floats2half2_rn(v.z, v.w);
    ((uint2*)gQ)[i] = make_uint2(h2u(h01), h2u(h23));
}
__global__ void cvtK_kernel(const float* __restrict__ K) {
    size_t i = (size_t)blockIdx.x * 256 + threadIdx.x;
    float4 v = ((const float4*)K)[i];
    __half2 h01 = __floats2half2_rn(v.x, v.y);
    __half2 h23 = __floats2half2_rn(v.z, v.w);
    ((uint2*)gK)[i] = make_uint2(h2u(h01), h2u(h23));
}
// V [b,s,kvh,d] fp32 -> Vt [b,kvh,d,s] fp16 (smem tile transpose)
__global__ void cvtV_kernel(const float* __restrict__ V) {
    __shared__ float sm[32][129];
    const int bk = blockIdx.z, b = bk >> 3, kvh = bk & 7;
    const int s0 = blockIdx.x * 128, d0 = blockIdx.y * 32;
    const int tid = threadIdx.x;
#pragma unroll
    for (int it = 0; it < 4; it++) {
        int idx = it * 256 + tid;
        int s = idx >> 3, d4 = (idx & 7) * 4;
        float4 v = *(const float4*)(V + ((((size_t)b * S_ + s0 + s) * KVH_ + kvh) * D_) + d0 + d4);
        sm[d4 + 0][s] = v.x; sm[d4 + 1][s] = v.y; sm[d4 + 2][s] = v.z; sm[d4 + 3][s] = v.w;
    }
    __syncthreads();
    const size_t obase = ((size_t)(b * KVH_ + kvh) * D_ + d0) * S_ + s0;
#pragma unroll
    for (int it = 0; it < 8; it++) {
        int idx = it * 256 + tid;
        int d = idx >> 6, j = idx & 63, s = 2 * j;
        __half2 h = __floats2half2_rn(sm[d][s], sm[d][s + 1]);
        *(uint32_t*)(&gVt[obase + (size_t)d * S_ + s]) = h2u(h);
    }
}

// ---------------------------------------------------------------------------
// fused flash kernel; complementary q-tile pairs; all-fp16 single-combo MMAs
// ---------------------------------------------------------------------------
__global__ void __launch_bounds__(256, 1)
fused_attn_kernel(const float* __restrict__ scale_ptr, float* __restrict__ out)
{
    extern __shared__ char smc[];
    const uint32_t sb = smem_to_u32(smc);

    const int tid = threadIdx.x, lane = tid & 31, wid = tid >> 5;
    const int wrow = wid * 16;                      // warp's 16-row slab
    const int pair = blockIdx.x, h = blockIdx.y, b = blockIdx.z;
    const int kvh = h >> 2;
    const int bh = b * H_ + h;
    const float inv_scale = 1.0f / scale_ptr[0];

    const size_t kbase = ((size_t)(b * KVH_ + kvh)) * S_ * D_;
    const size_t vbase = ((size_t)(b * KVH_ + kvh)) * D_ * S_;

    for (int qi = 0; qi < 2; qi++) {
        const int qt = qi ? (15 - pair) : pair;
        const int q0 = qt * TT;
        const size_t qbase = ((size_t)bh * S_ + q0) * D_;
        float* Pbase = out + OUT_P + ((size_t)bh * S_ + q0) * S_;
        float* Obase = out + ((size_t)bh * S_ + q0) * D_;

        // stage Q tile
#pragma unroll
        for (int it = 0; it < 8; it++) {
            int idx = it * 256 + tid;
            int r = idx >> 4, c = (idx & 15) * 8;
            *(uint4*)(smc + Q_B + toff(r, c)) =
                *(const uint4*)(gQ + qbase + (size_t)r * D_ + c);
        }

        // prefetch K(0) -> KB0 and V(0) -> VB0 as ONE group
#pragma unroll
        for (int it = 0; it < 8; it++) {
            int idx = it * 256 + tid;
            int r = idx >> 4, c = (idx & 15) * 8;
            CP_ASYNC16(sb + KB0 + toff(r, c), gK + kbase + (size_t)r * D_ + c);
        }
#pragma unroll
        for (int it = 0; it < 8; it++) {
            int idx = it * 256 + tid;
            int r = idx >> 4, c = (idx & 15) * 8;
            CP_ASYNC16(sb + VB0 + toff(r, c), gVt + vbase + (size_t)r * S_ + c);
        }
        CP_COMMIT();

        float m_run[2], l_run[2];
#pragma unroll
        for (int i = 0; i < 2; i++) { m_run[i] = -3.0e38f; l_run[i] = 0.0f; }

        float acc_o[16][4];
#pragma unroll
        for (int nt = 0; nt < 16; nt++)
#pragma unroll
            for (int k = 0; k < 4; k++) acc_o[nt][k] = 0.0f;

        // ============== pass A: online softmax + O accumulation =============
        for (int kt = 0; kt <= qt; kt++) {
            const int k0 = kt * TT;
            CP_WAIT0();
            __syncthreads();   // tile (kt) visible; all warps past tile kt-1
            const uint32_t KB = (kt & 1) ? KB1 : KB0;
            const uint32_t VB = (kt & 1) ? VB1 : VB0;

            if (kt < qt) {  // prefetch tile kt+1 (overlaps whole tile)
                const uint32_t nKB = (kt & 1) ? KB0 : KB1;
                const uint32_t nVB = (kt & 1) ? VB0 : VB1;
#pragma unroll
                for (int it = 0; it < 8; it++) {
                    int idx = it * 256 + tid;
                    int r = idx >> 4, c = (idx & 15) * 8;
                    CP_ASYNC16(sb + nKB + toff(r, c),
                               gK + kbase + (size_t)(k0 + TT + r) * D_ + c);
                }
#pragma unroll
                for (int it = 0; it < 8; it++) {
                    int idx = it * 256 + tid;
                    int r = idx >> 4, c = (idx & 15) * 8;
                    CP_ASYNC16(sb + nVB + toff(r, c),
                               gVt + vbase + (size_t)r * S_ + k0 + TT + c);
                }
                CP_COMMIT();
            }

            // ---- QK MMA (single combo) ----
            float acc[16][4];
#pragma unroll
            for (int nt = 0; nt < 16; nt++)
#pragma unroll
                for (int k = 0; k < 4; k++) acc[nt][k] = 0.0f;

#pragma unroll
            for (int ks = 0; ks < 8; ks++) {
                uint32_t ah[4];
                {
                    int r = wrow + (lane & 15);
                    int cc = ks * 16 + (lane >> 4) * 8;
                    LDSM_X4(ah[0], ah[1], ah[2], ah[3], sb + Q_B + toff(r, cc));
                }
#pragma unroll
                for (int np = 0; np < 8; np++) {
                    uint32_t bb[2][2];
                    int r = np * 16 + ((lane >> 4) << 3) + (lane & 7);
                    int cc = ks * 16 + ((lane >> 3) & 1) * 8;
                    uint32_t o = toff(r, cc);
                    LDSM_X4(bb[0][0], bb[0][1], bb[1][0], bb[1][1], sb + KB + o);
#pragma unroll
                    for (int t = 0; t < 2; t++)
                        mma16816(acc[2 * np + t], ah, bb[t]);
                }
            }

            // ---- epilogue: warp-local full-row stats, p~ -> fp16 regs ----
            const bool diag = (kt == qt);
            uint32_t php[16][2];
#pragma unroll
            for (int hh = 0; hh < 2; hh++) {
                const int row_l = wrow + (lane >> 2) + hh * 8;
                float rmax = -3.0e38f;
#pragma unroll
                for (int nt = 0; nt < 16; nt++) {
                    float v0 = acc[nt][hh * 2]     * inv_scale;
                    float v1 = acc[nt][hh * 2 + 1] * inv_scale;
                    if (diag) {
                        int colb = nt * 8 + (lane & 3) * 2;
                        if (colb > row_l)     v0 = -3.0e38f;
                        if (colb + 1 > row_l) v1 = -3.0e38f;
                    }
                    rmax = fmaxf(rmax, fmaxf(v0, v1));
                }
                rmax = fmaxf(rmax, __shfl_xor_sync(0xffffffffu, rmax, 1));
                rmax = fmaxf(rmax, __shfl_xor_sync(0xffffffffu, rmax, 2));
                const float newm = fmaxf(m_run[hh], rmax);
                const float corr = __expf(m_run[hh] - newm);
                float se = 0.0f;
#pragma unroll
                for (int nt = 0; nt < 16; nt++) {
                    float v0 = acc[nt][hh * 2]     * inv_scale;
                    float v1 = acc[nt][hh * 2 + 1] * inv_scale;
                    if (diag) {
                        int colb = nt * 8 + (lane & 3) * 2;
                        if (colb > row_l)     v0 = -3.0e38f;
                        if (colb + 1 > row_l) v1 = -3.0e38f;
                    }
                    float p0 = __expf(v0 - newm);
                    float p1 = __expf(v1 - newm);
                    se += p0 + p1;
                    acc_o[nt][hh * 2]     *= corr;
                    acc_o[nt][hh * 2 + 1] *= corr;
                    php[nt][hh] = h2u(__floats2half2_rn(p0, p1));
                }
                se += __shfl_xor_sync(0xffffffffu, se, 1);
                se += __shfl_xor_sync(0xffffffffu, se, 2);
                l_run[hh] = l_run[hh] * corr + se;
                m_run[hh] = newm;
            }

            // ---- PV MMA (1 combo), A from registers ----
#pragma unroll
            for (int ks = 0; ks < 8; ks++) {
                uint32_t aph[4] = {php[2 * ks][0], php[2 * ks][1],
                                   php[2 * ks + 1][0], php[2 * ks + 1][1]};
#pragma unroll
                for (int np = 0; np < 8; np++) {
                    uint32_t bb[2][2];
                    int r = np * 16 + ((lane >> 4) << 3) + (lane & 7);
                    int cc = ks * 16 + ((lane >> 3) & 1) * 8;
                    uint32_t o = toff(r, cc);
                    LDSM_X4(bb[0][0], bb[0][1], bb[1][0], bb[1][1], sb + VB + o);
#pragma unroll
                    for (int t = 0; t < 2; t++)
                        mma16816(acc_o[2 * np + t], aph, bb[t]);
                }
            }
        }

        const float linv[2] = {1.0f / l_run[0], 1.0f / l_run[1]};

        __syncthreads();   // all warps done reading pass-A buffers

        // prefetch K(0) for pass B -> KB0
#pragma unroll
        for (int it = 0; it < 8; it++) {
            int idx = it * 256 + tid;
            int r = idx >> 4, c = (idx & 15) * 8;
            CP_ASYNC16(sb + KB0 + toff(r, c), gK + kbase + (size_t)r * D_ + c);
        }
        CP_COMMIT();

        // ---- O epilogue (overlaps pass-B prefetch) ----
#pragma unroll
        for (int hh = 0; hh < 2; hh++) {
            const int row_l = wrow + (lane >> 2) + hh * 8;
            float* orow = Obase + (size_t)row_l * D_ + (lane & 3) * 2;
#pragma unroll
            for (int nt = 0; nt < 16; nt++)
                STG_CS_F2(orow + nt * 8,
                          acc_o[nt][hh * 2] * linv[hh], acc_o[nt][hh * 2 + 1] * linv[hh]);
        }

        // ============== pass B: recompute QK (1 combo), final weights ========
        for (int kt = 0; kt <= qt; kt++) {
            const int k0 = kt * TT;
            CP_WAIT0();
            __syncthreads();
            const uint32_t KB = (kt & 1) ? KB1 : KB0;
            if (kt < qt) {
                const uint32_t nKB = (kt & 1) ? KB0 : KB1;
#pragma unroll
                for (int it = 0; it < 8; it++) {
                    int idx = it * 256 + tid;
                    int r = idx >> 4, c = (idx & 15) * 8;
                    CP_ASYNC16(sb + nKB + toff(r, c),
                               gK + kbase + (size_t)(k0 + TT + r) * D_ + c);
                }
                CP_COMMIT();
            }

            float acc[16][4];
#pragma unroll
            for (int nt = 0; nt < 16; nt++)
#pragma unroll
                for (int k = 0; k < 4; k++) acc[nt][k] = 0.0f;

#pragma unroll
            for (int ks = 0; ks < 8; ks++) {
                uint32_t ah[4];
                {
                    int r = wrow + (lane & 15);
                    int cc = ks * 16 + (lane >> 4) * 8;
                    LDSM_X4(ah[0], ah[1], ah[2], ah[3], sb + Q_B + toff(r, cc));
                }
#pragma unroll
                for (int np = 0; np < 8; np++) {
                    uint32_t bb[2][2];
                    int r = np * 16 + ((lane >> 4) << 3) + (lane & 7);
                    int cc = ks * 16 + ((lane >> 3) & 1) * 8;
                    uint32_t o = toff(r, cc);
                    LDSM_X4(bb[0][0], bb[0][1], bb[1][0], bb[1][1], sb + KB + o);
#pragma unroll
                    for (int t = 0; t < 2; t++)
                        mma16816(acc[2 * np + t], ah, bb[t]);
                }
            }

            // finalize + store (streaming); stats from registers
            const bool diag = (kt == qt);
#pragma unroll
            for (int hh = 0; hh < 2; hh++) {
                const int row_l = wrow + (lane >> 2) + hh * 8;
                const float mfin = m_run[hh];
                const float li = linv[hh];
                float* prow = Pbase + (size_t)row_l * S_ + k0 + (lane & 3) * 2;
#pragma unroll
                for (int nt = 0; nt < 16; nt++) {
                    float v0 = acc[nt][hh * 2]     * inv_scale;
                    float v1 = acc[nt][hh * 2 + 1] * inv_scale;
                    if (diag) {
                        int colb = nt * 8 + (lane & 3) * 2;
                        if (colb > row_l)     v0 = -3.0e38f;
                        if (colb + 1 > row_l) v1 = -3.0e38f;
                    }
                    STG_CS_F2(prow + nt * 8, __expf(v0 - mfin) * li, __expf(v1 - mfin) * li);
                }
            }
        }

        // ---- zero-fill causal upper triangle (streaming) ----
        const int zbase = (qt + 1) * TT;
        const int zc4 = (S_ - zbase) >> 2;
        if (zc4 > 0) {
            const float4 z4 = make_float4(0.f, 0.f, 0.f, 0.f);
            for (int r = 0; r < TT; r++) {
                float* prow = Pbase + (size_t)r * S_ + zbase;
                for (int c4 = tid; c4 < zc4; c4 += 256)
                    STG_CS_F4(prow + (c4 << 2), z4);
            }
        }
        __syncthreads();   // smem safe for next q-tile iteration
    }
}

// ---------------------------------------------------------------------------
// present = (key copy, value permute)
// ---------------------------------------------------------------------------
__global__ void copy_kv_kernel(const float* __restrict__ K, const float* __restrict__ Vv,
                               float* __restrict__ out)
{
    const int i = blockIdx.x * 256 + threadIdx.x;
    if (i < 1048576) {
        float4 v = ((const float4*)K)[i];
        STG_CS_F4((float*)(out + OUT_K) + ((size_t)i << 2), v);
    } else {
        const int j = i - 1048576;
        const int row = j >> 5;
        const int d4 = (j & 31) << 2;
        const int b = row >> 14;
        const int kvh = (row >> 11) & 7;
        const int s = row & 2047;
        const float4 v = *(const float4*)(Vv + ((((size_t)b * S_ + s) * KVH_ + kvh) << 7) + d4);
        STG_CS_F4(out + OUT_V + ((size_t)row << 7) + d4, v);
    }
}

extern "C" void kernel_launch(void* const* d_in, const int* in_sizes, int n_in,
                              void* d_out, int out_size)
{
    (void)in_sizes; (void)n_in; (void)out_size;
    const float* Q     = (const float*)d_in[0];
    const float* K     = (const float*)d_in[1];
    const float* V     = (const float*)d_in[2];
    const float* scale = (const float*)d_in[4];
    float* out = (float*)d_out;

    cudaFuncSetAttribute(fused_attn_kernel, cudaFuncAttributeMaxDynamicSharedMemorySize, SMEM_SZ);

    cvtQ_kernel<<<16384, 256>>>(Q);
    cvtK_kernel<<<4096, 256>>>(K);
    cvtV_kernel<<<dim3(16, 4, 16), 256>>>(V);
    copy_kv_kernel<<<8192, 256>>>(K, V, out);

    dim3 grid(8, H_, B_);
    fused_attn_kernel<<<grid, 256, SMEM_SZ>>>(scale, out);
}

// round 13
// speedup vs baseline: 5.2617x; 1.1110x over previous
#include <cuda_runtime.h>
#include <cuda_fp16.h>
#include <cstdint>

#define B_   2
#define H_   32
#define KVH_ 8
#define S_   2048
#define D_   128
#define TT   128

static const size_t OUT_P = (size_t)B_ * H_ * S_ * D_;            // attn_output end
static const size_t OUT_K = OUT_P + (size_t)B_ * H_ * S_ * S_;    // attn_weights end
static const size_t OUT_V = OUT_K + (size_t)B_ * KVH_ * S_ * D_;

// -------- scratch (__device__ BSS, no allocation) --------
__device__ __half gQ [(size_t)B_ * H_ * S_ * D_];
__device__ __half gK [(size_t)B_ * KVH_ * S_ * D_];
__device__ __half gVt[(size_t)B_ * KVH_ * D_ * S_];   // [b][kvh][d][s]

__device__ __forceinline__ uint32_t smem_to_u32(const void* p) {
    uint32_t a;
    asm("{ .reg .u64 t; cvta.to.shared.u64 t, %1; cvt.u32.u64 %0, t; }" : "=r"(a) : "l"(p));
    return a;
}
__device__ __forceinline__ uint32_t h2u(__half2 x) { return *reinterpret_cast<uint32_t*>(&x); }

// byte offset inside a [128 x 128 half] tile, 256B rows, 16B-granule XOR swizzle
__device__ __forceinline__ uint32_t toff(int r, int c) {
    return (uint32_t)(r * 256 + ((((c >> 3) ^ (r & 7)) & 15) << 4) + (c & 7) * 2);
}

#define LDSM_X4(d0, d1, d2, d3, a) \
    asm volatile("ldmatrix.sync.aligned.m8n8.x4.shared.b16 {%0,%1,%2,%3}, [%4];" \
                 : "=r"(d0), "=r"(d1), "=r"(d2), "=r"(d3) : "r"(a))

__device__ __forceinline__ void mma16816(float* c, const uint32_t* a, const uint32_t* b) {
    asm volatile(
        "mma.sync.aligned.m16n8k16.row.col.f32.f16.f16.f32 "
        "{%0,%1,%2,%3}, {%4,%5,%6,%7}, {%8,%9}, {%0,%1,%2,%3};"
        : "+f"(c[0]), "+f"(c[1]), "+f"(c[2]), "+f"(c[3])
        : "r"(a[0]), "r"(a[1]), "r"(a[2]), "r"(a[3]), "r"(b[0]), "r"(b[1]));
}

#define CP_ASYNC16(dst, src) \
    asm volatile("cp.async.cg.shared.global [%0], [%1], 16;" :: "r"(dst), "l"(src))
#define CP_COMMIT() asm volatile("cp.async.commit_group;")
#define CP_WAIT0()  asm volatile("cp.async.wait_group 0;")

// streaming (evict-first) stores
#define STG_CS_F2(p, a, b) \
    asm volatile("st.global.cs.v2.f32 [%0], {%1,%2};" :: "l"(p), "f"(a), "f"(b))
#define STG_CS_F4(p, v) \
    asm volatile("st.global.cs.v4.f32 [%0], {%1,%2,%3,%4};" \
                 :: "l"(p), "f"((v).x), "f"((v).y), "f"((v).z), "f"((v).w))

// smem layout (byte offsets): Q fixed, K + V double-buffered
#define Q_B    0
#define KB0    32768
#define KB1    65536
#define VB0    98304
#define VB1    131072
#define SMEM_SZ 163840

// ---------------------------------------------------------------------------
// conversion kernels
// ---------------------------------------------------------------------------
__global__ void cvtQ_kernel(const float* __restrict__ Q) {
    size_t i = (size_t)blockIdx.x * 256 + threadIdx.x;  // float4 index
    float4 v = ((const float4*)Q)[i];
    __half2 h01 = __floats2half2_rn(v.x, v.y);
    __half2 h23 = __floats2half2_rn(v.z, v.w);
    ((uint2*)gQ)[i] = make_uint2(h2u(h01), h2u(h23));
}
__global__ void cvtK_kernel(const float* __restrict__ K) {
    size_t i = (size_t)blockIdx.x * 256 + threadIdx.x;
    float4 v = ((const float4*)K)[i];
    __half2 h01 = __floats2half2_rn(v.x, v.y);
    __half2 h23 = __floats2half2_rn(v.z, v.w);
    ((uint2*)gK)[i] = make_uint2(h2u(h01), h2u(h23));
}
// V [b,s,kvh,d] fp32 -> Vt [b,kvh,d,s] fp16 (smem tile transpose)
__global__ void cvtV_kernel(const float* __restrict__ V) {
    __shared__ float sm[32][129];
    const int bk = blockIdx.z, b = bk >> 3, kvh = bk & 7;
    const int s0 = blockIdx.x * 128, d0 = blockIdx.y * 32;
    const int tid = threadIdx.x;
#pragma unroll
    for (int it = 0; it < 4; it++) {
        int idx = it * 256 + tid;
        int s = idx >> 3, d4 = (idx & 7) * 4;
        float4 v = *(const float4*)(V + ((((size_t)b * S_ + s0 + s) * KVH_ + kvh) * D_) + d0 + d4);
        sm[d4 + 0][s] = v.x; sm[d4 + 1][s] = v.y; sm[d4 + 2][s] = v.z; sm[d4 + 3][s] = v.w;
    }
    __syncthreads();
    const size_t obase = ((size_t)(b * KVH_ + kvh) * D_ + d0) * S_ + s0;
#pragma unroll
    for (int it = 0; it < 8; it++) {
        int idx = it * 256 + tid;
        int d = idx >> 6, j = idx & 63, s = 2 * j;
        __half2 h = __floats2half2_rn(sm[d][s], sm[d][s + 1]);
        *(uint32_t*)(&gVt[obase + (size_t)d * S_ + s]) = h2u(h);
    }
}

// ---------------------------------------------------------------------------
// fused flash kernel; complementary q-tile pairs; all-fp16 single-combo MMAs;
// zero-fill of the PAIRED tile interleaved into pass A (DRAM-idle phase)
// ---------------------------------------------------------------------------
__global__ void __launch_bounds__(256, 1)
fused_attn_kernel(const float* __restrict__ scale_ptr, float* __restrict__ out)
{
    extern __shared__ char smc[];
    const uint32_t sb = smem_to_u32(smc);

    const int tid = threadIdx.x, lane = tid & 31, wid = tid >> 5;
    const int wrow = wid * 16;                      // warp's 16-row slab
    const int pair = blockIdx.x, h = blockIdx.y, b = blockIdx.z;
    const int kvh = h >> 2;
    const int bh = b * H_ + h;
    const float inv_scale = 1.0f / scale_ptr[0];

    const size_t kbase = ((size_t)(b * KVH_ + kvh)) * S_ * D_;
    const size_t vbase = ((size_t)(b * KVH_ + kvh)) * D_ * S_;

    for (int qi = 0; qi < 2; qi++) {
        const int qt = qi ? (15 - pair) : pair;
        const int q0 = qt * TT;
        const size_t qbase = ((size_t)bh * S_ + q0) * D_;
        float* Pbase = out + OUT_P + ((size_t)bh * S_ + q0) * S_;
        float* Obase = out + ((size_t)bh * S_ + q0) * D_;

        // zero-fill plan for the PAIRED tile (zqt = 15 - qt):
        //   its zero region is (15 - zqt) = qt tiles; we have qt+1 pass-A
        //   iterations -> just under one 64KB tile of zeros per iteration.
        const int zqt = 15 - qt;
        float* zPbase = out + OUT_P + ((size_t)bh * S_ + (size_t)zqt * TT) * S_;
        const int zcol0 = (zqt + 1) * TT;
        const int rl_total = 128 * (15 - zqt);          // 512B rowlets
        const int rl_per = (rl_total + qt) / (qt + 1);  // ceil(rl_total/(qt+1))

        // stage Q tile
#pragma unroll
        for (int it = 0; it < 8; it++) {
            int idx = it * 256 + tid;
            int r = idx >> 4, c = (idx & 15) * 8;
            *(uint4*)(smc + Q_B + toff(r, c)) =
                *(const uint4*)(gQ + qbase + (size_t)r * D_ + c);
        }

        // prefetch K(0) -> KB0 and V(0) -> VB0 as ONE group
#pragma unroll
        for (int it = 0; it < 8; it++) {
            int idx = it * 256 + tid;
            int r = idx >> 4, c = (idx & 15) * 8;
            CP_ASYNC16(sb + KB0 + toff(r, c), gK + kbase + (size_t)r * D_ + c);
        }
#pragma unroll
        for (int it = 0; it < 8; it++) {
            int idx = it * 256 + tid;
            int r = idx >> 4, c = (idx & 15) * 8;
            CP_ASYNC16(sb + VB0 + toff(r, c), gVt + vbase + (size_t)r * S_ + c);
        }
        CP_COMMIT();

        float m_run[2], l_run[2];
#pragma unroll
        for (int i = 0; i < 2; i++) { m_run[i] = -3.0e38f; l_run[i] = 0.0f; }

        float acc_o[16][4];
#pragma unroll
        for (int nt = 0; nt < 16; nt++)
#pragma unroll
            for (int k = 0; k < 4; k++) acc_o[nt][k] = 0.0f;

        // ============== pass A: online softmax + O accumulation =============
        for (int kt = 0; kt <= qt; kt++) {
            const int k0 = kt * TT;
            CP_WAIT0();
            __syncthreads();   // tile (kt) visible; all warps past tile kt-1
            const uint32_t KB = (kt & 1) ? KB1 : KB0;
            const uint32_t VB = (kt & 1) ? VB1 : VB0;

            if (kt < qt) {  // prefetch tile kt+1 (overlaps whole tile)
                const uint32_t nKB = (kt & 1) ? KB0 : KB1;
                const uint32_t nVB = (kt & 1) ? VB0 : VB1;
#pragma unroll
                for (int it = 0; it < 8; it++) {
                    int idx = it * 256 + tid;
                    int r = idx >> 4, c = (idx & 15) * 8;
                    CP_ASYNC16(sb + nKB + toff(r, c),
                               gK + kbase + (size_t)(k0 + TT + r) * D_ + c);
                }
#pragma unroll
                for (int it = 0; it < 8; it++) {
                    int idx = it * 256 + tid;
                    int r = idx >> 4, c = (idx & 15) * 8;
                    CP_ASYNC16(sb + nVB + toff(r, c),
                               gVt + vbase + (size_t)r * S_ + k0 + TT + c);
                }
                CP_COMMIT();
            }

            // ---- QK MMA (single combo) ----
            float acc[16][4];
#pragma unroll
            for (int nt = 0; nt < 16; nt++)
#pragma unroll
                for (int k = 0; k < 4; k++) acc[nt][k] = 0.0f;

#pragma unroll
            for (int ks = 0; ks < 8; ks++) {
                uint32_t ah[4];
                {
                    int r = wrow + (lane & 15);
                    int cc = ks * 16 + (lane >> 4) * 8;
                    LDSM_X4(ah[0], ah[1], ah[2], ah[3], sb + Q_B + toff(r, cc));
                }
#pragma unroll
                for (int np = 0; np < 8; np++) {
                    uint32_t bb[2][2];
                    int r = np * 16 + ((lane >> 4) << 3) + (lane & 7);
                    int cc = ks * 16 + ((lane >> 3) & 1) * 8;
                    uint32_t o = toff(r, cc);
                    LDSM_X4(bb[0][0], bb[0][1], bb[1][0], bb[1][1], sb + KB + o);
#pragma unroll
                    for (int t = 0; t < 2; t++)
                        mma16816(acc[2 * np + t], ah, bb[t]);
                }
            }

            // ---- epilogue: warp-local full-row stats, p~ -> fp16 regs ----
            const bool diag = (kt == qt);
            uint32_t php[16][2];
#pragma unroll
            for (int hh = 0; hh < 2; hh++) {
                const int row_l = wrow + (lane >> 2) + hh * 8;
                float rmax = -3.0e38f;
#pragma unroll
                for (int nt = 0; nt < 16; nt++) {
                    float v0 = acc[nt][hh * 2]     * inv_scale;
                    float v1 = acc[nt][hh * 2 + 1] * inv_scale;
                    if (diag) {
                        int colb = nt * 8 + (lane & 3) * 2;
                        if (colb > row_l)     v0 = -3.0e38f;
                        if (colb + 1 > row_l) v1 = -3.0e38f;
                    }
                    rmax = fmaxf(rmax, fmaxf(v0, v1));
                }
                rmax = fmaxf(rmax, __shfl_xor_sync(0xffffffffu, rmax, 1));
                rmax = fmaxf(rmax, __shfl_xor_sync(0xffffffffu, rmax, 2));
                const float newm = fmaxf(m_run[hh], rmax);
                const float corr = __expf(m_run[hh] - newm);
                float se = 0.0f;
#pragma unroll
                for (int nt = 0; nt < 16; nt++) {
                    float v0 = acc[nt][hh * 2]     * inv_scale;
                    float v1 = acc[nt][hh * 2 + 1] * inv_scale;
                    if (diag) {
                        int colb = nt * 8 + (lane & 3) * 2;
                        if (colb > row_l)     v0 = -3.0e38f;
                        if (colb + 1 > row_l) v1 = -3.0e38f;
                    }
                    float p0 = __expf(v0 - newm);
                    float p1 = __expf(v1 - newm);
                    se += p0 + p1;
                    acc_o[nt][hh * 2]     *= corr;
                    acc_o[nt][hh * 2 + 1] *= corr;
                    php[nt][hh] = h2u(__floats2half2_rn(p0, p1));
                }
                se += __shfl_xor_sync(0xffffffffu, se, 1);
                se += __shfl_xor_sync(0xffffffffu, se, 2);
                l_run[hh] = l_run[hh] * corr + se;
                m_run[hh] = newm;
            }

            // ---- PV MMA (1 combo), A from registers ----
#pragma unroll
            for (int ks = 0; ks < 8; ks++) {
                uint32_t aph[4] = {php[2 * ks][0], php[2 * ks][1],
                                   php[2 * ks + 1][0], php[2 * ks + 1][1]};
#pragma unroll
                for (int np = 0; np < 8; np++) {
                    uint32_t bb[2][2];
                    int r = np * 16 + ((lane >> 4) << 3) + (lane & 7);
                    int cc = ks * 16 + ((lane >> 3) & 1) * 8;
                    uint32_t o = toff(r, cc);
                    LDSM_X4(bb[0][0], bb[0][1], bb[1][0], bb[1][1], sb + VB + o);
#pragma unroll
                    for (int t = 0; t < 2; t++)
                        mma16816(acc_o[2 * np + t], aph, bb[t]);
                }
            }

            // ---- interleaved zero-fill chunk for the paired tile ----
            {
                int rl0 = kt * rl_per + wid;
                int rl1 = (kt + 1) * rl_per;
                if (rl1 > rl_total) rl1 = rl_total;
                const float4 z4 = make_float4(0.f, 0.f, 0.f, 0.f);
                for (int rl = rl0; rl < rl1; rl += 8) {
                    int ktile = rl >> 7, row = rl & 127;
                    STG_CS_F4(zPbase + (size_t)row * S_ + zcol0 + (ktile << 7) + (lane << 2),
                              z4);
                }
            }
        }

        const float linv[2] = {1.0f / l_run[0], 1.0f / l_run[1]};

        __syncthreads();   // all warps done reading pass-A buffers

        // prefetch K(0) for pass B -> KB0
#pragma unroll
        for (int it = 0; it < 8; it++) {
            int idx = it * 256 + tid;
            int r = idx >> 4, c = (idx & 15) * 8;
            CP_ASYNC16(sb + KB0 + toff(r, c), gK + kbase + (size_t)r * D_ + c);
        }
        CP_COMMIT();

        // ---- O epilogue (overlaps pass-B prefetch) ----
#pragma unroll
        for (int hh = 0; hh < 2; hh++) {
            const int row_l = wrow + (lane >> 2) + hh * 8;
            float* orow = Obase + (size_t)row_l * D_ + (lane & 3) * 2;
#pragma unroll
            for (int nt = 0; nt < 16; nt++)
                STG_CS_F2(orow + nt * 8,
                          acc_o[nt][hh * 2] * linv[hh], acc_o[nt][hh * 2 + 1] * linv[hh]);
        }

        // ============== pass B: recompute QK (1 combo), final weights ========
        for (int kt = 0; kt <= qt; kt++) {
            const int k0 = kt * TT;
            CP_WAIT0();
            __syncthreads();
            const uint32_t KB = (kt & 1) ? KB1 : KB0;
            if (kt < qt) {
                const uint32_t nKB = (kt & 1) ? KB0 : KB1;
#pragma unroll
                for (int it = 0; it < 8; it++) {
                    int idx = it * 256 + tid;
                    int r = idx >> 4, c = (idx & 15) * 8;
                    CP_ASYNC16(sb + nKB + toff(r, c),
                               gK + kbase + (size_t)(k0 + TT + r) * D_ + c);
                }
                CP_COMMIT();
            }

            float acc[16][4];
#pragma unroll
            for (int nt = 0; nt < 16; nt++)
#pragma unroll
                for (int k = 0; k < 4; k++) acc[nt][k] = 0.0f;

#pragma unroll
            for (int ks = 0; ks < 8; ks++) {
                uint32_t ah[4];
                {
                    int r = wrow + (lane & 15);
                    int cc = ks * 16 + (lane >> 4) * 8;
                    LDSM_X4(ah[0], ah[1], ah[2], ah[3], sb + Q_B + toff(r, cc));
                }
#pragma unroll
                for (int np = 0; np < 8; np++) {
                    uint32_t bb[2][2];
                    int r = np * 16 + ((lane >> 4) << 3) + (lane & 7);
                    int cc = ks * 16 + ((lane >> 3) & 1) * 8;
                    uint32_t o = toff(r, cc);
                    LDSM_X4(bb[0][0], bb[0][1], bb[1][0], bb[1][1], sb + KB + o);
#pragma unroll
                    for (int t = 0; t < 2; t++)
                        mma16816(acc[2 * np + t], ah, bb[t]);
                }
            }

            // finalize + store (streaming); stats from registers
            const bool diag = (kt == qt);
#pragma unroll
            for (int hh = 0; hh < 2; hh++) {
                const int row_l = wrow + (lane >> 2) + hh * 8;
                const float mfin = m_run[hh];
                const float li = linv[hh];
                float* prow = Pbase + (size_t)row_l * S_ + k0 + (lane & 3) * 2;
#pragma unroll
                for (int nt = 0; nt < 16; nt++) {
                    float v0 = acc[nt][hh * 2]     * inv_scale;
                    float v1 = acc[nt][hh * 2 + 1] * inv_scale;
                    if (diag) {
                        int colb = nt * 8 + (lane & 3) * 2;
                        if (colb > row_l)     v0 = -3.0e38f;
                        if (colb + 1 > row_l) v1 = -3.0e38f;
                    }
                    STG_CS_F2(prow + nt * 8, __expf(v0 - mfin) * li, __expf(v1 - mfin) * li);
                }
            }
        }

        __syncthreads();   // smem safe for next q-tile iteration
    }
}

// ---------------------------------------------------------------------------
// present = (key copy, value permute)
// ---------------------------------------------------------------------------
__global__ void copy_kv_kernel(const float* __restrict__ K, const float* __restrict__ Vv,
                               float* __restrict__ out)
{
    const int i = blockIdx.x * 256 + threadIdx.x;
    if (i < 1048576) {
        float4 v = ((const float4*)K)[i];
        STG_CS_F4((float*)(out + OUT_K) + ((size_t)i << 2), v);
    } else {
        const int j = i - 1048576;
        const int row = j >> 5;
        const int d4 = (j & 31) << 2;
        const int b = row >> 14;
        const int kvh = (row >> 11) & 7;
        const int s = row & 2047;
        const float4 v = *(const float4*)(Vv + ((((size_t)b * S_ + s) * KVH_ + kvh) << 7) + d4);
        STG_CS_F4(out + OUT_V + ((size_t)row << 7) + d4, v);
    }
}

extern "C" void kernel_launch(void* const* d_in, const int* in_sizes, int n_in,
                              void* d_out, int out_size)
{
    (void)in_sizes; (void)n_in; (void)out_size;
    const float* Q     = (const float*)d_in[0];
    const float* K     = (const float*)d_in[1];
    const float* V     = (const float*)d_in[2];
    const float* scale = (const float*)d_in[4];
    float* out = (float*)d_out;

    cudaFuncSetAttribute(fused_attn_kernel, cudaFuncAttributeMaxDynamicSharedMemorySize, SMEM_SZ);

    cvtQ_kernel<<<16384, 256>>>(Q);
    cvtK_kernel<<<4096, 256>>>(K);
    cvtV_kernel<<<dim3(16, 4, 16), 256>>>(V);
    copy_kv_kernel<<<8192, 256>>>(K, V, out);

    dim3 grid(8, H_, B_);
    fused_attn_kernel<<<grid, 256, SMEM_SZ>>>(scale, out);
}

// round 14
// speedup vs baseline: 5.5194x; 1.0490x over previous
#include <cuda_runtime.h>
#include <cuda_fp16.h>
#include <cstdint>

#define B_   2
#define H_   32
#define KVH_ 8
#define S_   2048
#define D_   128
#define TT   128

static const size_t OUT_P = (size_t)B_ * H_ * S_ * D_;            // attn_output end
static const size_t OUT_K = OUT_P + (size_t)B_ * H_ * S_ * S_;    // attn_weights end
static const size_t OUT_V = OUT_K + (size_t)B_ * KVH_ * S_ * D_;

// -------- scratch (__device__ BSS, no allocation) --------
__device__ __half gK [(size_t)B_ * KVH_ * S_ * D_];
__device__ __half gVt[(size_t)B_ * KVH_ * D_ * S_];   // [b][kvh][d][s]

__device__ __forceinline__ uint32_t smem_to_u32(const void* p) {
    uint32_t a;
    asm("{ .reg .u64 t; cvta.to.shared.u64 t, %1; cvt.u32.u64 %0, t; }" : "=r"(a) : "l"(p));
    return a;
}
__device__ __forceinline__ uint32_t h2u(__half2 x) { return *reinterpret_cast<uint32_t*>(&x); }

// byte offset inside a [128 x 128 half] tile, 256B rows, 16B-granule XOR swizzle
__device__ __forceinline__ uint32_t toff(int r, int c) {
    return (uint32_t)(r * 256 + ((((c >> 3) ^ (r & 7)) & 15) << 4) + (c & 7) * 2);
}

#define LDSM_X4(d0, d1, d2, d3, a) \
    asm volatile("ldmatrix.sync.aligned.m8n8.x4.shared.b16 {%0,%1,%2,%3}, [%4];" \
                 : "=r"(d0), "=r"(d1), "=r"(d2), "=r"(d3) : "r"(a))

__device__ __forceinline__ void mma16816(float* c, const uint32_t* a, const uint32_t* b) {
    asm volatile(
        "mma.sync.aligned.m16n8k16.row.col.f32.f16.f16.f32 "
        "{%0,%1,%2,%3}, {%4,%5,%6,%7}, {%8,%9}, {%0,%1,%2,%3};"
        : "+f"(c[0]), "+f"(c[1]), "+f"(c[2]), "+f"(c[3])
        : "r"(a[0]), "r"(a[1]), "r"(a[2]), "r"(a[3]), "r"(b[0]), "r"(b[1]));
}

#define CP_ASYNC16(dst, src) \
    asm volatile("cp.async.cg.shared.global [%0], [%1], 16;" :: "r"(dst), "l"(src))
#define CP_COMMIT() asm volatile("cp.async.commit_group;")
#define CP_WAIT0()  asm volatile("cp.async.wait_group 0;")

// streaming (evict-first) stores
#define STG_CS_F2(p, a, b) \
    asm volatile("st.global.cs.v2.f32 [%0], {%1,%2};" :: "l"(p), "f"(a), "f"(b))
#define STG_CS_F4(p, v) \
    asm volatile("st.global.cs.v4.f32 [%0], {%1,%2,%3,%4};" \
                 :: "l"(p), "f"((v).x), "f"((v).y), "f"((v).z), "f"((v).w))

// smem layout (byte offsets): Q fixed, K + V double-buffered
#define Q_B    0
#define KB0    32768
#define KB1    65536
#define VB0    98304
#define VB1    131072
#define SMEM_SZ 163840

// ---------------------------------------------------------------------------
// cvtK + key copy fused: read K fp32 once, emit fp16 scratch + fp32 copy
// ---------------------------------------------------------------------------
__global__ void cvtK_copy_kernel(const float* __restrict__ K, float* __restrict__ out) {
    size_t i = (size_t)blockIdx.x * 256 + threadIdx.x;  // float4 index
    float4 v = ((const float4*)K)[i];
    __half2 h01 = __floats2half2_rn(v.x, v.y);
    __half2 h23 = __floats2half2_rn(v.z, v.w);
    ((uint2*)gK)[i] = make_uint2(h2u(h01), h2u(h23));
    STG_CS_F4(out + OUT_K + (i << 2), v);
}
// cvtV + value permute fused: read V once, emit fp16 transposed scratch +
// fp32 permuted copy [b,s,kvh,d] -> [b,kvh,s,d]
__global__ void cvtV_copy_kernel(const float* __restrict__ V, float* __restrict__ out) {
    __shared__ float sm[32][129];
    const int bk = blockIdx.z, b = bk >> 3, kvh = bk & 7;
    const int s0 = blockIdx.x * 128, d0 = blockIdx.y * 32;
    const int tid = threadIdx.x;
    const size_t cbase = OUT_V + (((size_t)(b * KVH_ + kvh) * S_ + s0) << 7) + d0;
#pragma unroll
    for (int it = 0; it < 4; it++) {
        int idx = it * 256 + tid;
        int s = idx >> 3, d4 = (idx & 7) * 4;
        float4 v = *(const float4*)(V + ((((size_t)b * S_ + s0 + s) * KVH_ + kvh) * D_) + d0 + d4);
        sm[d4 + 0][s] = v.x; sm[d4 + 1][s] = v.y; sm[d4 + 2][s] = v.z; sm[d4 + 3][s] = v.w;
        STG_CS_F4(out + cbase + ((size_t)s << 7) + d4, v);
    }
    __syncthreads();
    const size_t obase = ((size_t)(b * KVH_ + kvh) * D_ + d0) * S_ + s0;
#pragma unroll
    for (int it = 0; it < 8; it++) {
        int idx = it * 256 + tid;
        int d = idx >> 6, j = idx & 63, s = 2 * j;
        __half2 h = __floats2half2_rn(sm[d][s], sm[d][s + 1]);
        *(uint32_t*)(&gVt[obase + (size_t)d * S_ + s]) = h2u(h);
    }
}

// ---------------------------------------------------------------------------
// fused flash kernel; one q-tile per CTA, heavy tiles launched first (LPT);
// inline Q fp32->fp16; all-fp16 single-combo MMAs; own-tile zero-fill
// interleaved into pass A
// ---------------------------------------------------------------------------
__global__ void __launch_bounds__(256, 1)
fused_attn_kernel(const float* __restrict__ Q, const float* __restrict__ scale_ptr,
                  float* __restrict__ out)
{
    extern __shared__ char smc[];
    const uint32_t sb = smem_to_u32(smc);

    const int tid = threadIdx.x, lane = tid & 31, wid = tid >> 5;
    const int wrow = wid * 16;                      // warp's 16-row slab
    const int qt = 15 - blockIdx.x;                 // heavy-first (LPT)
    const int h = blockIdx.y, b = blockIdx.z;
    const int kvh = h >> 2;
    const int bh = b * H_ + h;
    const float inv_scale = 1.0f / scale_ptr[0];

    const size_t kbase = ((size_t)(b * KVH_ + kvh)) * S_ * D_;
    const size_t vbase = ((size_t)(b * KVH_ + kvh)) * D_ * S_;

    const int q0 = qt * TT;
    float* Pbase = out + OUT_P + ((size_t)bh * S_ + q0) * S_;
    float* Obase = out + ((size_t)bh * S_ + q0) * D_;

    // zero-fill plan (own tile): region cols >= (qt+1)*128, spread over qt+1
    // pass-A iterations in 512B rowlets
    const int zcol0 = (qt + 1) * TT;
    const int rl_total = 128 * (15 - qt);
    const int rl_per = (rl_total + qt) / (qt + 1);

    // stage Q tile: fp32 gmem -> fp16 swizzled smem (inline conversion)
    {
        const float* Qg = Q + ((size_t)bh * S_ + q0) * D_;
#pragma unroll
        for (int it = 0; it < 16; it++) {
            int idx = it * 256 + tid;
            int r = idx >> 5, c4 = (idx & 31) << 2;
            float4 v = *(const float4*)(Qg + (size_t)r * D_ + c4);
            __half2 h01 = __floats2half2_rn(v.x, v.y);
            __half2 h23 = __floats2half2_rn(v.z, v.w);
            *(uint2*)(smc + Q_B + toff(r, c4)) = make_uint2(h2u(h01), h2u(h23));
        }
    }

    // prefetch K(0) -> KB0 and V(0) -> VB0 as ONE group
#pragma unroll
    for (int it = 0; it < 8; it++) {
        int idx = it * 256 + tid;
        int r = idx >> 4, c = (idx & 15) * 8;
        CP_ASYNC16(sb + KB0 + toff(r, c), gK + kbase + (size_t)r * D_ + c);
    }
#pragma unroll
    for (int it = 0; it < 8; it++) {
        int idx = it * 256 + tid;
        int r = idx >> 4, c = (idx & 15) * 8;
        CP_ASYNC16(sb + VB0 + toff(r, c), gVt + vbase + (size_t)r * S_ + c);
    }
    CP_COMMIT();

    float m_run[2], l_run[2];
#pragma unroll
    for (int i = 0; i < 2; i++) { m_run[i] = -3.0e38f; l_run[i] = 0.0f; }

    float acc_o[16][4];
#pragma unroll
    for (int nt = 0; nt < 16; nt++)
#pragma unroll
        for (int k = 0; k < 4; k++) acc_o[nt][k] = 0.0f;

    // ============== pass A: online softmax + O accumulation =============
    for (int kt = 0; kt <= qt; kt++) {
        const int k0 = kt * TT;
        CP_WAIT0();
        __syncthreads();   // tile (kt) visible; all warps past tile kt-1
        const uint32_t KB = (kt & 1) ? KB1 : KB0;
        const uint32_t VB = (kt & 1) ? VB1 : VB0;

        if (kt < qt) {  // prefetch tile kt+1 (overlaps whole tile)
            const uint32_t nKB = (kt & 1) ? KB0 : KB1;
            const uint32_t nVB = (kt & 1) ? VB0 : VB1;
#pragma unroll
            for (int it = 0; it < 8; it++) {
                int idx = it * 256 + tid;
                int r = idx >> 4, c = (idx & 15) * 8;
                CP_ASYNC16(sb + nKB + toff(r, c),
                           gK + kbase + (size_t)(k0 + TT + r) * D_ + c);
            }
#pragma unroll
            for (int it = 0; it < 8; it++) {
                int idx = it * 256 + tid;
                int r = idx >> 4, c = (idx & 15) * 8;
                CP_ASYNC16(sb + nVB + toff(r, c),
                           gVt + vbase + (size_t)r * S_ + k0 + TT + c);
            }
            CP_COMMIT();
        }

        // ---- QK MMA (single combo) ----
        float acc[16][4];
#pragma unroll
        for (int nt = 0; nt < 16; nt++)
#pragma unroll
            for (int k = 0; k < 4; k++) acc[nt][k] = 0.0f;

#pragma unroll
        for (int ks = 0; ks < 8; ks++) {
            uint32_t ah[4];
            {
                int r = wrow + (lane & 15);
                int cc = ks * 16 + (lane >> 4) * 8;
                LDSM_X4(ah[0], ah[1], ah[2], ah[3], sb + Q_B + toff(r, cc));
            }
#pragma unroll
            for (int np = 0; np < 8; np++) {
                uint32_t bb[2][2];
                int r = np * 16 + ((lane >> 4) << 3) + (lane & 7);
                int cc = ks * 16 + ((lane >> 3) & 1) * 8;
                uint32_t o = toff(r, cc);
                LDSM_X4(bb[0][0], bb[0][1], bb[1][0], bb[1][1], sb + KB + o);
#pragma unroll
                for (int t = 0; t < 2; t++)
                    mma16816(acc[2 * np + t], ah, bb[t]);
            }
        }

        // ---- epilogue: warp-local full-row stats, p~ -> fp16 regs ----
        const bool diag = (kt == qt);
        uint32_t php[16][2];
#pragma unroll
        for (int hh = 0; hh < 2; hh++) {
            const int row_l = wrow + (lane >> 2) + hh * 8;
            float rmax = -3.0e38f;
#pragma unroll
            for (int nt = 0; nt < 16; nt++) {
                float v0 = acc[nt][hh * 2]     * inv_scale;
                float v1 = acc[nt][hh * 2 + 1] * inv_scale;
                if (diag) {
                    int colb = nt * 8 + (lane & 3) * 2;
                    if (colb > row_l)     v0 = -3.0e38f;
                    if (colb + 1 > row_l) v1 = -3.0e38f;
                }
                rmax = fmaxf(rmax, fmaxf(v0, v1));
            }
            rmax = fmaxf(rmax, __shfl_xor_sync(0xffffffffu, rmax, 1));
            rmax = fmaxf(rmax, __shfl_xor_sync(0xffffffffu, rmax, 2));
            const float newm = fmaxf(m_run[hh], rmax);
            const float corr = __expf(m_run[hh] - newm);
            float se = 0.0f;
#pragma unroll
            for (int nt = 0; nt < 16; nt++) {
                float v0 = acc[nt][hh * 2]     * inv_scale;
                float v1 = acc[nt][hh * 2 + 1] * inv_scale;
                if (diag) {
                    int colb = nt * 8 + (lane & 3) * 2;
                    if (colb > row_l)     v0 = -3.0e38f;
                    if (colb + 1 > row_l) v1 = -3.0e38f;
                }
                float p0 = __expf(v0 - newm);
                float p1 = __expf(v1 - newm);
                se += p0 + p1;
                acc_o[nt][hh * 2]     *= corr;
                acc_o[nt][hh * 2 + 1] *= corr;
                php[nt][hh] = h2u(__floats2half2_rn(p0, p1));
            }
            se += __shfl_xor_sync(0xffffffffu, se, 1);
            se += __shfl_xor_sync(0xffffffffu, se, 2);
            l_run[hh] = l_run[hh] * corr + se;
            m_run[hh] = newm;
        }

        // ---- PV MMA (1 combo), A from registers ----
#pragma unroll
        for (int ks = 0; ks < 8; ks++) {
            uint32_t aph[4] = {php[2 * ks][0], php[2 * ks][1],
                               php[2 * ks + 1][0], php[2 * ks + 1][1]};
#pragma unroll
            for (int np = 0; np < 8; np++) {
                uint32_t bb[2][2];
                int r = np * 16 + ((lane >> 4) << 3) + (lane & 7);
                int cc = ks * 16 + ((lane >> 3) & 1) * 8;
                uint32_t o = toff(r, cc);
                LDSM_X4(bb[0][0], bb[0][1], bb[1][0], bb[1][1], sb + VB + o);
#pragma unroll
                for (int t = 0; t < 2; t++)
                    mma16816(acc_o[2 * np + t], aph, bb[t]);
            }
        }

        // ---- interleaved zero-fill chunk (own tile's masked region) ----
        if (rl_total > 0) {
            int rl0 = kt * rl_per + wid;
            int rl1 = (kt + 1) * rl_per;
            if (rl1 > rl_total) rl1 = rl_total;
            const float4 z4 = make_float4(0.f, 0.f, 0.f, 0.f);
            for (int rl = rl0; rl < rl1; rl += 8) {
                int ktile = rl >> 7, row = rl & 127;
                STG_CS_F4(Pbase + (size_t)row * S_ + zcol0 + (ktile << 7) + (lane << 2),
                          z4);
            }
        }
    }

    const float linv[2] = {1.0f / l_run[0], 1.0f / l_run[1]};

    __syncthreads();   // all warps done reading pass-A buffers

    // prefetch K(0) for pass B -> KB0
#pragma unroll
    for (int it = 0; it < 8; it++) {
        int idx = it * 256 + tid;
        int r = idx >> 4, c = (idx & 15) * 8;
        CP_ASYNC16(sb + KB0 + toff(r, c), gK + kbase + (size_t)r * D_ + c);
    }
    CP_COMMIT();

    // ---- O epilogue (overlaps pass-B prefetch) ----
#pragma unroll
    for (int hh = 0; hh < 2; hh++) {
        const int row_l = wrow + (lane >> 2) + hh * 8;
        float* orow = Obase + (size_t)row_l * D_ + (lane & 3) * 2;
#pragma unroll
        for (int nt = 0; nt < 16; nt++)
            STG_CS_F2(orow + nt * 8,
                      acc_o[nt][hh * 2] * linv[hh], acc_o[nt][hh * 2 + 1] * linv[hh]);
    }

    // ============== pass B: recompute QK (1 combo), final weights ========
    for (int kt = 0; kt <= qt; kt++) {
        const int k0 = kt * TT;
        CP_WAIT0();
        __syncthreads();
        const uint32_t KB = (kt & 1) ? KB1 : KB0;
        if (kt < qt) {
            const uint32_t nKB = (kt & 1) ? KB0 : KB1;
#pragma unroll
            for (int it = 0; it < 8; it++) {
                int idx = it * 256 + tid;
                int r = idx >> 4, c = (idx & 15) * 8;
                CP_ASYNC16(sb + nKB + toff(r, c),
                           gK + kbase + (size_t)(k0 + TT + r) * D_ + c);
            }
            CP_COMMIT();
        }

        float acc[16][4];
#pragma unroll
        for (int nt = 0; nt < 16; nt++)
#pragma unroll
            for (int k = 0; k < 4; k++) acc[nt][k] = 0.0f;

#pragma unroll
        for (int ks = 0; ks < 8; ks++) {
            uint32_t ah[4];
            {
                int r = wrow + (lane & 15);
                int cc = ks * 16 + (lane >> 4) * 8;
                LDSM_X4(ah[0], ah[1], ah[2], ah[3], sb + Q_B + toff(r, cc));
            }
#pragma unroll
            for (int np = 0; np < 8; np++) {
                uint32_t bb[2][2];
                int r = np * 16 + ((lane >> 4) << 3) + (lane & 7);
                int cc = ks * 16 + ((lane >> 3) & 1) * 8;
                uint32_t o = toff(r, cc);
                LDSM_X4(bb[0][0], bb[0][1], bb[1][0], bb[1][1], sb + KB + o);
#pragma unroll
                for (int t = 0; t < 2; t++)
                    mma16816(acc[2 * np + t], ah, bb[t]);
            }
        }

        // finalize + store (streaming); stats from registers
        const bool diag = (kt == qt);
#pragma unroll
        for (int hh = 0; hh < 2; hh++) {
            const int row_l = wrow + (lane >> 2) + hh * 8;
            const float mfin = m_run[hh];
            const float li = linv[hh];
            float* prow = Pbase + (size_t)row_l * S_ + k0 + (lane & 3) * 2;
#pragma unroll
            for (int nt = 0; nt < 16; nt++) {
                float v0 = acc[nt][hh * 2]     * inv_scale;
                float v1 = acc[nt][hh * 2 + 1] * inv_scale;
                if (diag) {
                    int colb = nt * 8 + (lane & 3) * 2;
                    if (colb > row_l)     v0 = -3.0e38f;
                    if (colb + 1 > row_l) v1 = -3.0e38f;
                }
                STG_CS_F2(prow + nt * 8, __expf(v0 - mfin) * li, __expf(v1 - mfin) * li);
            }
        }
    }
}

extern "C" void kernel_launch(void* const* d_in, const int* in_sizes, int n_in,
                              void* d_out, int out_size)
{
    (void)in_sizes; (void)n_in; (void)out_size;
    const float* Q     = (const float*)d_in[0];
    const float* K     = (const float*)d_in[1];
    const float* V     = (const float*)d_in[2];
    const float* scale = (const float*)d_in[4];
    float* out = (float*)d_out;

    cudaFuncSetAttribute(fused_attn_kernel, cudaFuncAttributeMaxDynamicSharedMemorySize, SMEM_SZ);

    cvtK_copy_kernel<<<4096, 256>>>(K, out);
    cvtV_copy_kernel<<<dim3(16, 4, 16), 256>>>(V, out);

    dim3 grid(16, H_, B_);
    fused_attn_kernel<<<grid, 256, SMEM_SZ>>>(Q, scale, out);
}